// round 1
// baseline (speedup 1.0000x reference)
#include <cuda_runtime.h>
#include <math.h>

#define NN   8192
#define NE   500000
#define NREL 6
#define FEAT 256
#define HIDD 64
#define OUTD 128
#define MROW 4096   // SIZE
#define ITEM 8192

// ---------------- scratch (device globals: allocation-free) ----------------
__device__ int   g_outcnt[NREL][NN];
__device__ int   g_incnt [NREL][NN];
__device__ float g_outinv[NREL][NN];
__device__ float g_ininv [NREL][NN];
__device__ int   g_rowptr[NREL][NN + 1];
__device__ int   g_fill  [NREL][NN];
__device__ int   g_srcs  [NREL][NE];
__device__ float g_xs    [NREL][NN * 128];
__device__ float g_node  [3][NN * 128];     // M, D, T
__device__ float g_x1[4096 * 256];
__device__ float g_x2[4096 * 512];
__device__ float g_x3[4096 * 1024];

// ---------------- CSR build ----------------
__global__ void k_zero_counts() {
    int i = blockIdx.x * blockDim.x + threadIdx.x;
    if (i < NREL * NN) {
        ((int*)g_outcnt)[i] = 0;
        ((int*)g_incnt)[i]  = 0;
    }
}

__global__ void k_count(const int* __restrict__ edges) {
    int i = blockIdx.x * blockDim.x + threadIdx.x;
    if (i >= NREL * NE) return;
    int r = i / NE, e = i - r * NE;
    int src = edges[(size_t)r * 2 * NE + e];
    int dst = edges[(size_t)r * 2 * NE + NE + e];
    atomicAdd(&g_outcnt[r][src], 1);
    atomicAdd(&g_incnt[r][dst], 1);
}

// one block per relation: exclusive scan of incnt -> rowptr/fill, plus deg^-1/2
__global__ void k_scan() {
    int r = blockIdx.x;
    int tid = threadIdx.x;          // 1024 threads
    int base = tid * 8;
    int c[8];
    int s = 0;
#pragma unroll
    for (int i = 0; i < 8; i++) { c[i] = g_incnt[r][base + i]; s += c[i]; }

    int lane = tid & 31, w = tid >> 5;
    int incl = s;
#pragma unroll
    for (int o = 1; o < 32; o <<= 1) {
        int v = __shfl_up_sync(0xffffffffu, incl, o);
        if (lane >= o) incl += v;
    }
    __shared__ int wsum[32];
    if (lane == 31) wsum[w] = incl;
    __syncthreads();
    if (w == 0) {
        int v = wsum[lane];
#pragma unroll
        for (int o = 1; o < 32; o <<= 1) {
            int t = __shfl_up_sync(0xffffffffu, v, o);
            if (lane >= o) v += t;
        }
        wsum[lane] = v;
    }
    __syncthreads();
    int excl = (incl - s) + (w > 0 ? wsum[w - 1] : 0);
    int run = excl;
#pragma unroll
    for (int i = 0; i < 8; i++) {
        g_rowptr[r][base + i] = run;
        g_fill[r][base + i]   = run;
        run += c[i];
        int ic = c[i] > 0 ? c[i] : 1;
        g_ininv[r][base + i] = rsqrtf((float)ic);
        int oc = g_outcnt[r][base + i];
        if (oc < 1) oc = 1;
        g_outinv[r][base + i] = rsqrtf((float)oc);
    }
    if (tid == 1023) g_rowptr[r][NN] = run;
}

__global__ void k_fill(const int* __restrict__ edges) {
    int i = blockIdx.x * blockDim.x + threadIdx.x;
    if (i >= NREL * NE) return;
    int r = i / NE, e = i - r * NE;
    int src = edges[(size_t)r * 2 * NE + e];
    int dst = edges[(size_t)r * 2 * NE + NE + e];
    int pos = atomicAdd(&g_fill[r][dst], 1);
    g_srcs[r][pos] = src;
}

// ---------------- conv GEMM: Xs = (A * scale[row]) @ W  (M=8192) ----------
// BM=64, BN=64, BK=16, 256 threads, 4x4 per thread
__global__ void k_conv_gemm(const float* __restrict__ A,
                            const float* __restrict__ scale,
                            const float* __restrict__ W,
                            float* __restrict__ Xs, int K, int Nh) {
    __shared__ float As[16][64];
    __shared__ float Bs[16][64];
    int tid = threadIdx.x;
    int bx = blockIdx.x, by = blockIdx.y;
    int aRow = tid >> 2, aCol = (tid & 3) * 4;
    int bRow = tid >> 4, bCol = (tid & 15) * 4;
    int tx = tid & 15, ty = tid >> 4;
    float acc[4][4] = {};
    const float* Ap = A + (size_t)(by * 64) * K;
    float scl = scale[by * 64 + aRow];

    for (int k0 = 0; k0 < K; k0 += 16) {
        float4 av = *(const float4*)(Ap + (size_t)aRow * K + k0 + aCol);
        As[aCol + 0][aRow] = av.x * scl;
        As[aCol + 1][aRow] = av.y * scl;
        As[aCol + 2][aRow] = av.z * scl;
        As[aCol + 3][aRow] = av.w * scl;
        float4 bv = *(const float4*)(W + (size_t)(k0 + bRow) * Nh + bx * 64 + bCol);
        *(float4*)&Bs[bRow][bCol] = bv;
        __syncthreads();
#pragma unroll
        for (int kk = 0; kk < 16; kk++) {
            float a[4], b[4];
#pragma unroll
            for (int i = 0; i < 4; i++) a[i] = As[kk][ty * 4 + i];
#pragma unroll
            for (int j = 0; j < 4; j++) b[j] = Bs[kk][tx * 4 + j];
#pragma unroll
            for (int i = 0; i < 4; i++)
#pragma unroll
                for (int j = 0; j < 4; j++) acc[i][j] += a[i] * b[j];
        }
        __syncthreads();
    }
    int row0 = by * 64 + ty * 4, col0 = bx * 64 + tx * 4;
#pragma unroll
    for (int i = 0; i < 4; i++)
#pragma unroll
        for (int j = 0; j < 4; j++)
            Xs[(size_t)(row0 + i) * Nh + col0 + j] = acc[i][j];
}

// ---------------- aggregation: gather over CSR, no atomics ----------------
// target t: newM = out[1]+out[3], newD = out[0]+out[4], newT = out[2]+out[5]
__global__ void k_agg(int hid, const float* __restrict__ bias) {
    int t = blockIdx.y;
    int n = blockIdx.x;
    int h = threadIdx.x;
    const int RA[3] = {1, 0, 2};
    const int RB[3] = {3, 4, 5};
    int ra = RA[t], rb = RB[t];
    float acc = bias[ra * hid + h] + bias[rb * hid + h];
    {
        float s = 0.f;
        int e0 = g_rowptr[ra][n], e1 = g_rowptr[ra][n + 1];
        const float* xs = g_xs[ra];
        for (int e = e0; e < e1; e++) {
            int sidx = g_srcs[ra][e];
            s += xs[(size_t)sidx * hid + h];
        }
        acc += s * g_ininv[ra][n];
    }
    {
        float s = 0.f;
        int e0 = g_rowptr[rb][n], e1 = g_rowptr[rb][n + 1];
        const float* xs = g_xs[rb];
        for (int e = e0; e < e1; e++) {
            int sidx = g_srcs[rb][e];
            s += xs[(size_t)sidx * hid + h];
        }
        acc += s * g_ininv[rb][n];
    }
    g_node[t][(size_t)n * hid + h] = acc;
}

// ---------------- row L1-normalize hM3[0:4096] -> fake_embeding -----------
__global__ void k_l1norm(float* __restrict__ out) {
    int row = blockIdx.x;
    int h = threadIdx.x;  // 128
    float v = g_node[0][(size_t)row * OUTD + h];
    float a = fabsf(v);
#pragma unroll
    for (int o = 16; o > 0; o >>= 1) a += __shfl_xor_sync(0xffffffffu, a, o);
    __shared__ float sh[4];
    if ((h & 31) == 0) sh[h >> 5] = a;
    __syncthreads();
    float tot = sh[0] + sh[1] + sh[2] + sh[3];
    out[(size_t)row * OUTD + h] = v / fmaxf(tot, 1e-12f);
}

// ---------------- MLP GEMM: C = act(A@B + bias + Cin) ----------------------
// BM=128, BN=128, BK=8, 256 threads, 8x8 per thread. ACT: 0 none, 1 relu, 2 sigmoid
template <int ACT>
__global__ void k_gemm(const float* __restrict__ A, const float* __restrict__ B,
                       const float* __restrict__ bias, const float* __restrict__ Cin,
                       float* __restrict__ C, int M, int Nn, int K) {
    __shared__ float As[8][128];
    __shared__ float Bs[8][128];
    int tid = threadIdx.x;
    int bx = blockIdx.x, by = blockIdx.y;
    int aRow = tid >> 1, aCol = (tid & 1) * 4;
    int bRow = tid >> 5, bCol = (tid & 31) * 4;
    int tx = tid & 15, ty = tid >> 4;
    float acc[8][8] = {};
    const float* Ap = A + (size_t)(by * 128) * K;
    const float* Bp = B + (size_t)bx * 128;

    for (int k0 = 0; k0 < K; k0 += 8) {
        float4 av = *(const float4*)(Ap + (size_t)aRow * K + k0 + aCol);
        As[aCol + 0][aRow] = av.x;
        As[aCol + 1][aRow] = av.y;
        As[aCol + 2][aRow] = av.z;
        As[aCol + 3][aRow] = av.w;
        float4 bv = *(const float4*)(Bp + (size_t)(k0 + bRow) * Nn + bCol);
        *(float4*)&Bs[bRow][bCol] = bv;
        __syncthreads();
#pragma unroll
        for (int kk = 0; kk < 8; kk++) {
            float a[8], b[8];
#pragma unroll
            for (int i = 0; i < 8; i++) a[i] = As[kk][ty * 8 + i];
#pragma unroll
            for (int j = 0; j < 8; j++) b[j] = Bs[kk][tx * 8 + j];
#pragma unroll
            for (int i = 0; i < 8; i++)
#pragma unroll
                for (int j = 0; j < 8; j++) acc[i][j] += a[i] * b[j];
        }
        __syncthreads();
    }
    int row0 = by * 128 + ty * 8, col0 = bx * 128 + tx * 8;
#pragma unroll
    for (int i = 0; i < 8; i++) {
#pragma unroll
        for (int j = 0; j < 8; j++) {
            float v = acc[i][j];
            if (Cin)  v += Cin[(size_t)(row0 + i) * Nn + col0 + j];
            if (bias) v += bias[col0 + j];
            if (ACT == 1) v = fmaxf(v, 0.f);
            else if (ACT == 2) v = 1.f / (1.f + expf(-v));
            C[(size_t)(row0 + i) * Nn + col0 + j] = v;
        }
    }
}

// ---------------- orchestration ----------------
extern "C" void kernel_launch(void* const* d_in, const int* in_sizes, int n_in,
                              void* d_out, int out_size) {
    const float* hM  = (const float*)d_in[0];
    const float* hD  = (const float*)d_in[1];
    const float* hT  = (const float*)d_in[2];
    const float* W1  = (const float*)d_in[3];
    const float* b1  = (const float*)d_in[4];
    const float* W2  = (const float*)d_in[5];
    const float* b2  = (const float*)d_in[6];
    const float* W3  = (const float*)d_in[7];
    const float* b3  = (const float*)d_in[8];
    const float* Adj = (const float*)d_in[9];
    const float* f1w = (const float*)d_in[10];
    const float* f1b = (const float*)d_in[11];
    const float* f2w = (const float*)d_in[12];
    const float* f2b = (const float*)d_in[13];
    const float* f3w = (const float*)d_in[14];
    const float* f3b = (const float*)d_in[15];
    const float* f4w = (const float*)d_in[16];
    const float* f4b = (const float*)d_in[17];
    const int* edges = (const int*)d_in[18];

    float *p_xs, *p_node, *p_outinv, *p_x1, *p_x2, *p_x3;
    cudaGetSymbolAddress((void**)&p_xs, g_xs);
    cudaGetSymbolAddress((void**)&p_node, g_node);
    cudaGetSymbolAddress((void**)&p_outinv, g_outinv);
    cudaGetSymbolAddress((void**)&p_x1, g_x1);
    cudaGetSymbolAddress((void**)&p_x2, g_x2);
    cudaGetSymbolAddress((void**)&p_x3, g_x3);

    float* fe   = (float*)d_out;                       // 4096 x 128
    float* outx = (float*)d_out + (size_t)MROW * OUTD; // 4096 x 8192

    // CSR + degrees (edges are identical each call; rebuilt deterministically)
    k_zero_counts<<<(NREL * NN + 255) / 256, 256>>>();
    k_count<<<(NREL * NE + 255) / 256, 256>>>(edges);
    k_scan<<<NREL, 1024>>>();
    k_fill<<<(NREL * NE + 255) / 256, 256>>>(edges);

    const int srcmap[6] = {0, 1, 0, 2, 2, 1};  // M,D,M,T,T,D
    const float* in0[3] = {hM, hD, hT};

    // layer 1: FEAT=256 -> 64
    for (int r = 0; r < 6; r++)
        k_conv_gemm<<<dim3(1, NN / 64), 256>>>(in0[srcmap[r]], p_outinv + r * NN,
                                               W1 + (size_t)r * 256 * 64,
                                               p_xs + (size_t)r * NN * 128, 256, 64);
    k_agg<<<dim3(NN, 3), 64>>>(64, b1);

    // layer 2: 64 -> 64
    for (int r = 0; r < 6; r++)
        k_conv_gemm<<<dim3(1, NN / 64), 256>>>(p_node + (size_t)srcmap[r] * NN * 128,
                                               p_outinv + r * NN,
                                               W2 + (size_t)r * 64 * 64,
                                               p_xs + (size_t)r * NN * 128, 64, 64);
    k_agg<<<dim3(NN, 3), 64>>>(64, b2);

    // layer 3: 64 -> 128
    for (int r = 0; r < 6; r++)
        k_conv_gemm<<<dim3(2, NN / 64), 256>>>(p_node + (size_t)srcmap[r] * NN * 128,
                                               p_outinv + r * NN,
                                               W3 + (size_t)r * 64 * 128,
                                               p_xs + (size_t)r * NN * 128, 64, 128);
    k_agg<<<dim3(NN, 3), 128>>>(128, b3);

    // fake_embeding = L1-normalized hM3[0:4096] -> d_out directly
    k_l1norm<<<MROW, 128>>>(fe);

    // MLP decoder
    // x1 = relu(Adj @ f1w[0:8192] + fe @ f1w[8192:8320] + f1b)
    k_gemm<0><<<dim3(256 / 128, MROW / 128), 256>>>(Adj, f1w, nullptr, nullptr,
                                                    p_x1, MROW, 256, ITEM);
    k_gemm<1><<<dim3(256 / 128, MROW / 128), 256>>>(fe, f1w + (size_t)ITEM * 256, f1b,
                                                    p_x1, p_x1, MROW, 256, 128);
    k_gemm<1><<<dim3(512 / 128, MROW / 128), 256>>>(p_x1, f2w, f2b, nullptr,
                                                    p_x2, MROW, 512, 256);
    k_gemm<1><<<dim3(1024 / 128, MROW / 128), 256>>>(p_x2, f3w, f3b, nullptr,
                                                     p_x3, MROW, 1024, 512);
    k_gemm<2><<<dim3(8192 / 128, MROW / 128), 256>>>(p_x3, f4w, f4b, nullptr,
                                                     outx, MROW, 8192, 1024);
}

// round 3
// speedup vs baseline: 2.4151x; 2.4151x over previous
#include <cuda_runtime.h>
#include <cuda_bf16.h>
#include <stdint.h>
#include <math.h>

#define NN   8192
#define NE   500000
#define NREL 6
#define FEAT 256
#define HIDD 64
#define OUTD 128
#define MROW 4096   // SIZE
#define ITEM 8192

// ---------------- scratch (device globals: allocation-free) ----------------
__device__ int   g_outcnt[NREL][NN];
__device__ int   g_incnt [NREL][NN];
__device__ float g_outinv[NREL][NN];
__device__ float g_ininv [NREL][NN];
__device__ int   g_rowptr[NREL][NN + 1];
__device__ int   g_fill  [NREL][NN];
__device__ int   g_srcs  [NREL][NE];
__device__ float g_xs    [NREL][NN * 128];
__device__ float g_node  [3][NN * 128];     // M, D, T
__device__ float g_x1[4096 * 256];
__device__ float g_x2[4096 * 512];
__device__ float g_x3[4096 * 1024];

// ---------------- CSR build ----------------
__global__ void k_zero_counts() {
    int i = blockIdx.x * blockDim.x + threadIdx.x;
    if (i < NREL * NN) {
        ((int*)g_outcnt)[i] = 0;
        ((int*)g_incnt)[i]  = 0;
    }
}

__global__ void k_count(const int* __restrict__ edges) {
    int i = blockIdx.x * blockDim.x + threadIdx.x;
    if (i >= NREL * NE) return;
    int r = i / NE, e = i - r * NE;
    int src = edges[(size_t)r * 2 * NE + e];
    int dst = edges[(size_t)r * 2 * NE + NE + e];
    atomicAdd(&g_outcnt[r][src], 1);
    atomicAdd(&g_incnt[r][dst], 1);
}

__global__ void k_scan() {
    int r = blockIdx.x;
    int tid = threadIdx.x;          // 1024 threads
    int base = tid * 8;
    int c[8];
    int s = 0;
#pragma unroll
    for (int i = 0; i < 8; i++) { c[i] = g_incnt[r][base + i]; s += c[i]; }

    int lane = tid & 31, w = tid >> 5;
    int incl = s;
#pragma unroll
    for (int o = 1; o < 32; o <<= 1) {
        int v = __shfl_up_sync(0xffffffffu, incl, o);
        if (lane >= o) incl += v;
    }
    __shared__ int wsum[32];
    if (lane == 31) wsum[w] = incl;
    __syncthreads();
    if (w == 0) {
        int v = wsum[lane];
#pragma unroll
        for (int o = 1; o < 32; o <<= 1) {
            int t = __shfl_up_sync(0xffffffffu, v, o);
            if (lane >= o) v += t;
        }
        wsum[lane] = v;
    }
    __syncthreads();
    int excl = (incl - s) + (w > 0 ? wsum[w - 1] : 0);
    int run = excl;
#pragma unroll
    for (int i = 0; i < 8; i++) {
        g_rowptr[r][base + i] = run;
        g_fill[r][base + i]   = run;
        run += c[i];
        int ic = c[i] > 0 ? c[i] : 1;
        g_ininv[r][base + i] = rsqrtf((float)ic);
        int oc = g_outcnt[r][base + i];
        if (oc < 1) oc = 1;
        g_outinv[r][base + i] = rsqrtf((float)oc);
    }
    if (tid == 1023) g_rowptr[r][NN] = run;
}

__global__ void k_fill(const int* __restrict__ edges) {
    int i = blockIdx.x * blockDim.x + threadIdx.x;
    if (i >= NREL * NE) return;
    int r = i / NE, e = i - r * NE;
    int src = edges[(size_t)r * 2 * NE + e];
    int dst = edges[(size_t)r * 2 * NE + NE + e];
    int pos = atomicAdd(&g_fill[r][dst], 1);
    g_srcs[r][pos] = src;
}

// ---------------- conv GEMM batched over relations (gridDim.z = 6) --------
// Xs_r = (A_r * outinv_r[row]) @ W_r.  BM=64, BN=64, BK=16, 256 threads.
__global__ void k_conv_b(const float* __restrict__ A0, const float* __restrict__ A1,
                         const float* __restrict__ A2, const float* __restrict__ Wb,
                         int K, int Nh) {
    const int r = blockIdx.z;
    const int smap[6] = {0, 1, 0, 2, 2, 1};
    int si = smap[r];
    const float* A = (si == 0) ? A0 : (si == 1) ? A1 : A2;
    const float* W = Wb + (size_t)r * K * Nh;
    float* Xs = g_xs[r];
    const float* scale = g_outinv[r];

    __shared__ float As[16][64];
    __shared__ float Bs[16][64];
    int tid = threadIdx.x;
    int bx = blockIdx.x, by = blockIdx.y;
    int aRow = tid >> 2, aCol = (tid & 3) * 4;
    int bRow = tid >> 4, bCol = (tid & 15) * 4;
    int tx = tid & 15, ty = tid >> 4;
    float acc[4][4] = {};
    const float* Ap = A + (size_t)(by * 64) * K;
    float scl = scale[by * 64 + aRow];

    for (int k0 = 0; k0 < K; k0 += 16) {
        float4 av = *(const float4*)(Ap + (size_t)aRow * K + k0 + aCol);
        As[aCol + 0][aRow] = av.x * scl;
        As[aCol + 1][aRow] = av.y * scl;
        As[aCol + 2][aRow] = av.z * scl;
        As[aCol + 3][aRow] = av.w * scl;
        float4 bv = *(const float4*)(W + (size_t)(k0 + bRow) * Nh + bx * 64 + bCol);
        *(float4*)&Bs[bRow][bCol] = bv;
        __syncthreads();
#pragma unroll
        for (int kk = 0; kk < 16; kk++) {
            float a[4], b[4];
#pragma unroll
            for (int i = 0; i < 4; i++) a[i] = As[kk][ty * 4 + i];
#pragma unroll
            for (int j = 0; j < 4; j++) b[j] = Bs[kk][tx * 4 + j];
#pragma unroll
            for (int i = 0; i < 4; i++)
#pragma unroll
                for (int j = 0; j < 4; j++) acc[i][j] += a[i] * b[j];
        }
        __syncthreads();
    }
    int row0 = by * 64 + ty * 4, col0 = bx * 64 + tx * 4;
#pragma unroll
    for (int i = 0; i < 4; i++)
#pragma unroll
        for (int j = 0; j < 4; j++)
            Xs[(size_t)(row0 + i) * Nh + col0 + j] = acc[i][j];
}

// ---------------- aggregation: float4 gather over CSR ----------------------
__device__ __forceinline__ float4 f4add(float4 a, float4 b) {
    a.x += b.x; a.y += b.y; a.z += b.z; a.w += b.w; return a;
}
__device__ __forceinline__ float4 f4fma(float4 a, float s, float4 acc) {
    acc.x += a.x * s; acc.y += a.y * s; acc.z += a.z * s; acc.w += a.w * s; return acc;
}

template <int HID>
__global__ void k_agg_v(const float* __restrict__ bias) {
    const int t = blockIdx.y;
    const int n = blockIdx.x * blockDim.y + threadIdx.y;
    const int lane = threadIdx.x;     // 0..HID/4-1
    const int RA[3] = {1, 0, 2};
    const int RB[3] = {3, 4, 5};
    int rel[2] = {RA[t], RB[t]};
    float4 acc = f4add(reinterpret_cast<const float4*>(bias + rel[0] * HID)[lane],
                       reinterpret_cast<const float4*>(bias + rel[1] * HID)[lane]);
#pragma unroll
    for (int rr = 0; rr < 2; rr++) {
        int r = rel[rr];
        int e0 = g_rowptr[r][n], e1 = g_rowptr[r][n + 1];
        const float* xs = g_xs[r];
        const int* srcs = g_srcs[r];
        float4 s = make_float4(0.f, 0.f, 0.f, 0.f);
        int e = e0;
        for (; e + 1 < e1; e += 2) {
            int s0 = srcs[e], s1 = srcs[e + 1];
            float4 v0 = reinterpret_cast<const float4*>(xs + (size_t)s0 * HID)[lane];
            float4 v1 = reinterpret_cast<const float4*>(xs + (size_t)s1 * HID)[lane];
            s = f4add(s, v0);
            s = f4add(s, v1);
        }
        if (e < e1) {
            int s0 = srcs[e];
            s = f4add(s, reinterpret_cast<const float4*>(xs + (size_t)s0 * HID)[lane]);
        }
        acc = f4fma(s, g_ininv[r][n], acc);
    }
    reinterpret_cast<float4*>(g_node[t] + (size_t)n * HID)[lane] = acc;
}

// ---------------- row L1-normalize hM3[0:4096] -> fake_embeding -----------
__global__ void k_l1norm(float* __restrict__ out) {
    int row = blockIdx.x;
    int h = threadIdx.x;  // 128
    float v = g_node[0][(size_t)row * OUTD + h];
    float a = fabsf(v);
#pragma unroll
    for (int o = 16; o > 0; o >>= 1) a += __shfl_xor_sync(0xffffffffu, a, o);
    __shared__ float sh[4];
    if ((h & 31) == 0) sh[h >> 5] = a;
    __syncthreads();
    float tot = sh[0] + sh[1] + sh[2] + sh[3];
    out[(size_t)row * OUTD + h] = v / fmaxf(tot, 1e-12f);
}

// ---------------- bf16 split helpers ----------------
__device__ __forceinline__ uint32_t pack_bf16(float x, float y) {
    __nv_bfloat162 h = __floats2bfloat162_rn(x, y);
    return *reinterpret_cast<uint32_t*>(&h);
}
__device__ __forceinline__ void split2(float x, float& hi, float& lo) {
    __nv_bfloat16 h = __float2bfloat16(x);
    hi = __bfloat162float(h);
    lo = x - hi;
}
__device__ __forceinline__ void mma_bf16(float* d, const uint32_t* a, const uint32_t* b) {
    asm volatile(
        "mma.sync.aligned.m16n8k16.row.col.f32.bf16.bf16.f32 "
        "{%0,%1,%2,%3}, {%4,%5,%6,%7}, {%8,%9}, {%0,%1,%2,%3};"
        : "+f"(d[0]), "+f"(d[1]), "+f"(d[2]), "+f"(d[3])
        : "r"(a[0]), "r"(a[1]), "r"(a[2]), "r"(a[3]), "r"(b[0]), "r"(b[1]));
}

// ---------------- MLP GEMM via bf16 tensor cores, hi/lo compensated -------
// C = act(A@B [+ Cin] [+ bias]).  BM=BN=128, BK=32, 256 thr (8 warps 4x2),
// warp tile 32x64 (2 m16-tiles x 8 n8-tiles).  3-pass (2-pass if !SPLITA).
// Requires M%128==0, N%128==0, K%32==0.
#define SA 40                      // smem row stride in bf16 elems (bank-safe)
#define ATILE (128 * SA)           // 5120 elems
#define STAGE_ELEMS (4 * ATILE)    // Ah, Al, Bh, Bl
#define MMA_SMEM_BYTES (2 * STAGE_ELEMS * 2)

template <int ACT, bool SPLITA>
__global__ void __launch_bounds__(256, 1)
k_mma(const float* __restrict__ A, const float* __restrict__ B,
      const float* __restrict__ bias, const float* __restrict__ Cin,
      float* __restrict__ C, int M, int N, int K) {
    extern __shared__ __nv_bfloat16 sm[];
    const int tid = threadIdx.x;
    const int lane = tid & 31;
    const int warp = tid >> 5;
    const int wm = warp & 3, wn = warp >> 2;
    const int g = lane >> 2, tig = lane & 3;
    const int bm = blockIdx.y * 128, bn = blockIdx.x * 128;

    const int ar = tid >> 3;            // A ldg row 0..31
    const int ac = (tid & 7) * 4;       // A ldg col
    const int bnt = tid & 127;          // B ldg col
    const int bkt = (tid >> 7) * 16;    // B ldg k base

    float c[2][8][4];
#pragma unroll
    for (int i = 0; i < 2; i++)
#pragma unroll
        for (int j = 0; j < 8; j++)
#pragma unroll
            for (int q = 0; q < 4; q++) c[i][j][q] = 0.f;

    float a_ld[16], b_ld[16];

    auto ldg_tiles = [&](int k0) {
#pragma unroll
        for (int i = 0; i < 4; i++)
            *reinterpret_cast<float4*>(&a_ld[i * 4]) =
                *reinterpret_cast<const float4*>(A + (size_t)(bm + ar + 32 * i) * K + k0 + ac);
#pragma unroll
        for (int j = 0; j < 16; j++)
            b_ld[j] = B[(size_t)(k0 + bkt + j) * N + bn + bnt];
    };

    auto sts_tile = [&](int stage) {
        __nv_bfloat16* base = sm + stage * STAGE_ELEMS;
        __nv_bfloat16* Ah = base;
        __nv_bfloat16* Al = base + ATILE;
        __nv_bfloat16* Bh = base + 2 * ATILE;
        __nv_bfloat16* Bl = base + 3 * ATILE;
#pragma unroll
        for (int i = 0; i < 4; i++) {
            int m = ar + 32 * i;
            float h0, l0, h1, l1, h2, l2, h3, l3;
            split2(a_ld[i * 4 + 0], h0, l0);
            split2(a_ld[i * 4 + 1], h1, l1);
            split2(a_ld[i * 4 + 2], h2, l2);
            split2(a_ld[i * 4 + 3], h3, l3);
            *reinterpret_cast<uint32_t*>(&Ah[m * SA + ac])     = pack_bf16(h0, h1);
            *reinterpret_cast<uint32_t*>(&Ah[m * SA + ac + 2]) = pack_bf16(h2, h3);
            if (SPLITA) {
                *reinterpret_cast<uint32_t*>(&Al[m * SA + ac])     = pack_bf16(l0, l1);
                *reinterpret_cast<uint32_t*>(&Al[m * SA + ac + 2]) = pack_bf16(l2, l3);
            }
        }
#pragma unroll
        for (int j = 0; j < 16; j += 2) {
            float h0, l0, h1, l1;
            split2(b_ld[j], h0, l0);
            split2(b_ld[j + 1], h1, l1);
            *reinterpret_cast<uint32_t*>(&Bh[bnt * SA + bkt + j]) = pack_bf16(h0, h1);
            *reinterpret_cast<uint32_t*>(&Bl[bnt * SA + bkt + j]) = pack_bf16(l0, l1);
        }
    };

    auto mma_stage = [&](int stage) {
        const __nv_bfloat16* base = sm + stage * STAGE_ELEMS;
        const __nv_bfloat16* Ah = base;
        const __nv_bfloat16* Al = base + ATILE;
        const __nv_bfloat16* Bh = base + 2 * ATILE;
        const __nv_bfloat16* Bl = base + 3 * ATILE;
#pragma unroll
        for (int kk = 0; kk < 32; kk += 16) {
            uint32_t ah[2][4], al[2][4], bh[8][2], bl[8][2];
#pragma unroll
            for (int mt = 0; mt < 2; mt++) {
                int mr = wm * 32 + mt * 16 + g;
                ah[mt][0] = *reinterpret_cast<const uint32_t*>(&Ah[(mr)*SA + kk + 2 * tig]);
                ah[mt][1] = *reinterpret_cast<const uint32_t*>(&Ah[(mr + 8) * SA + kk + 2 * tig]);
                ah[mt][2] = *reinterpret_cast<const uint32_t*>(&Ah[(mr)*SA + kk + 2 * tig + 8]);
                ah[mt][3] = *reinterpret_cast<const uint32_t*>(&Ah[(mr + 8) * SA + kk + 2 * tig + 8]);
                if (SPLITA) {
                    al[mt][0] = *reinterpret_cast<const uint32_t*>(&Al[(mr)*SA + kk + 2 * tig]);
                    al[mt][1] = *reinterpret_cast<const uint32_t*>(&Al[(mr + 8) * SA + kk + 2 * tig]);
                    al[mt][2] = *reinterpret_cast<const uint32_t*>(&Al[(mr)*SA + kk + 2 * tig + 8]);
                    al[mt][3] = *reinterpret_cast<const uint32_t*>(&Al[(mr + 8) * SA + kk + 2 * tig + 8]);
                }
            }
#pragma unroll
            for (int nt = 0; nt < 8; nt++) {
                int nr = wn * 64 + nt * 8 + g;
                bh[nt][0] = *reinterpret_cast<const uint32_t*>(&Bh[nr * SA + kk + 2 * tig]);
                bh[nt][1] = *reinterpret_cast<const uint32_t*>(&Bh[nr * SA + kk + 2 * tig + 8]);
                bl[nt][0] = *reinterpret_cast<const uint32_t*>(&Bl[nr * SA + kk + 2 * tig]);
                bl[nt][1] = *reinterpret_cast<const uint32_t*>(&Bl[nr * SA + kk + 2 * tig + 8]);
            }
#pragma unroll
            for (int mt = 0; mt < 2; mt++)
#pragma unroll
                for (int nt = 0; nt < 8; nt++) {
                    mma_bf16(c[mt][nt], ah[mt], bh[nt]);
                    mma_bf16(c[mt][nt], ah[mt], bl[nt]);
                    if (SPLITA) mma_bf16(c[mt][nt], al[mt], bh[nt]);
                }
        }
    };

    const int nsteps = K >> 5;
    ldg_tiles(0);
    sts_tile(0);
    __syncthreads();
    for (int s = 0; s < nsteps; s++) {
        int cur = s & 1;
        if (s + 1 < nsteps) ldg_tiles((s + 1) * 32);
        mma_stage(cur);
        if (s + 1 < nsteps) sts_tile(cur ^ 1);
        __syncthreads();
    }

    // epilogue
#pragma unroll
    for (int mt = 0; mt < 2; mt++) {
#pragma unroll
        for (int nt = 0; nt < 8; nt++) {
            int m0 = bm + wm * 32 + mt * 16 + g;
            int n0 = bn + wn * 64 + nt * 8 + 2 * tig;
            float2 v0 = make_float2(c[mt][nt][0], c[mt][nt][1]);
            float2 v1 = make_float2(c[mt][nt][2], c[mt][nt][3]);
            if (Cin) {
                float2 ci0 = *reinterpret_cast<const float2*>(Cin + (size_t)m0 * N + n0);
                float2 ci1 = *reinterpret_cast<const float2*>(Cin + (size_t)(m0 + 8) * N + n0);
                v0.x += ci0.x; v0.y += ci0.y; v1.x += ci1.x; v1.y += ci1.y;
            }
            if (bias) {
                float bx = bias[n0], by = bias[n0 + 1];
                v0.x += bx; v0.y += by; v1.x += bx; v1.y += by;
            }
            if (ACT == 1) {
                v0.x = fmaxf(v0.x, 0.f); v0.y = fmaxf(v0.y, 0.f);
                v1.x = fmaxf(v1.x, 0.f); v1.y = fmaxf(v1.y, 0.f);
            } else if (ACT == 2) {
                v0.x = 1.f / (1.f + expf(-v0.x)); v0.y = 1.f / (1.f + expf(-v0.y));
                v1.x = 1.f / (1.f + expf(-v1.x)); v1.y = 1.f / (1.f + expf(-v1.y));
            }
            *reinterpret_cast<float2*>(C + (size_t)m0 * N + n0) = v0;
            *reinterpret_cast<float2*>(C + (size_t)(m0 + 8) * N + n0) = v1;
        }
    }
}

// ---------------- orchestration ----------------
extern "C" void kernel_launch(void* const* d_in, const int* in_sizes, int n_in,
                              void* d_out, int out_size) {
    const float* hM  = (const float*)d_in[0];
    const float* hD  = (const float*)d_in[1];
    const float* hT  = (const float*)d_in[2];
    const float* W1  = (const float*)d_in[3];
    const float* b1  = (const float*)d_in[4];
    const float* W2  = (const float*)d_in[5];
    const float* b2  = (const float*)d_in[6];
    const float* W3  = (const float*)d_in[7];
    const float* b3  = (const float*)d_in[8];
    const float* Adj = (const float*)d_in[9];
    const float* f1w = (const float*)d_in[10];
    const float* f1b = (const float*)d_in[11];
    const float* f2w = (const float*)d_in[12];
    const float* f2b = (const float*)d_in[13];
    const float* f3w = (const float*)d_in[14];
    const float* f3b = (const float*)d_in[15];
    const float* f4w = (const float*)d_in[16];
    const float* f4b = (const float*)d_in[17];
    const int* edges = (const int*)d_in[18];

    float *p_node, *p_x1, *p_x2, *p_x3;
    cudaGetSymbolAddress((void**)&p_node, g_node);
    cudaGetSymbolAddress((void**)&p_x1, g_x1);
    cudaGetSymbolAddress((void**)&p_x2, g_x2);
    cudaGetSymbolAddress((void**)&p_x3, g_x3);

    float* fe   = (float*)d_out;                       // 4096 x 128
    float* outx = (float*)d_out + (size_t)MROW * OUTD; // 4096 x 8192

    cudaFuncSetAttribute(k_mma<0, false>, cudaFuncAttributeMaxDynamicSharedMemorySize, MMA_SMEM_BYTES);
    cudaFuncSetAttribute(k_mma<1, true>,  cudaFuncAttributeMaxDynamicSharedMemorySize, MMA_SMEM_BYTES);
    cudaFuncSetAttribute(k_mma<2, true>,  cudaFuncAttributeMaxDynamicSharedMemorySize, MMA_SMEM_BYTES);

    // CSR + degrees
    k_zero_counts<<<(NREL * NN + 255) / 256, 256>>>();
    k_count<<<(NREL * NE + 255) / 256, 256>>>(edges);
    k_scan<<<NREL, 1024>>>();
    k_fill<<<(NREL * NE + 255) / 256, 256>>>(edges);

    // layer 1: FEAT=256 -> 64   (relations batched over gridDim.z)
    k_conv_b<<<dim3(1, NN / 64, 6), 256>>>(hM, hD, hT, W1, 256, 64);
    k_agg_v<64><<<dim3(NN / 8, 3), dim3(16, 8)>>>(b1);

    // layer 2: 64 -> 64
    k_conv_b<<<dim3(1, NN / 64, 6), 256>>>(p_node, p_node + (size_t)NN * 128,
                                           p_node + (size_t)2 * NN * 128, W2, 64, 64);
    k_agg_v<64><<<dim3(NN / 8, 3), dim3(16, 8)>>>(b2);

    // layer 3: 64 -> 128
    k_conv_b<<<dim3(2, NN / 64, 6), 256>>>(p_node, p_node + (size_t)NN * 128,
                                           p_node + (size_t)2 * NN * 128, W3, 64, 128);
    k_agg_v<128><<<dim3(NN / 4, 3), dim3(32, 4)>>>(b3);

    // fake_embeding = L1-normalized hM3[0:4096] -> d_out
    k_l1norm<<<MROW, 128>>>(fe);

    // MLP decoder (bf16 tensor cores, hi/lo compensated)
    // x1 = relu(Adj @ f1w_top + fe @ f1w_bot + f1b)
    k_mma<0, false><<<dim3(2, 32), 256, MMA_SMEM_BYTES>>>(Adj, f1w, nullptr, nullptr,
                                                          p_x1, MROW, 256, ITEM);
    k_mma<1, true><<<dim3(2, 32), 256, MMA_SMEM_BYTES>>>(fe, f1w + (size_t)ITEM * 256, f1b,
                                                         p_x1, p_x1, MROW, 256, 128);
    k_mma<1, true><<<dim3(4, 32), 256, MMA_SMEM_BYTES>>>(p_x1, f2w, f2b, nullptr,
                                                         p_x2, MROW, 512, 256);
    k_mma<1, true><<<dim3(8, 32), 256, MMA_SMEM_BYTES>>>(p_x2, f3w, f3b, nullptr,
                                                         p_x3, MROW, 1024, 512);
    k_mma<2, true><<<dim3(64, 32), 256, MMA_SMEM_BYTES>>>(p_x3, f4w, f4b, nullptr,
                                                          outx, MROW, 8192, 1024);
}

// round 5
// speedup vs baseline: 3.2118x; 1.3299x over previous
#include <cuda_runtime.h>
#include <cuda_bf16.h>
#include <stdint.h>
#include <math.h>

#define NN   8192
#define NE   500000
#define NREL 6
#define FEAT 256
#define HIDD 64
#define OUTD 128
#define MROW 4096   // SIZE
#define ITEM 8192

// ---------------- scratch (device globals: allocation-free) ----------------
__device__ int   g_outcnt[NREL][NN];
__device__ int   g_incnt [NREL][NN];
__device__ float g_outinv[NREL][NN];
__device__ float g_ininv [NREL][NN];
__device__ int   g_rowptr[NREL][NN + 1];
__device__ int   g_fill  [NREL][NN];
__device__ int   g_srcs  [NREL][NE];
__device__ float g_xs    [NREL][NN * 128];
__device__ float g_node  [3][NN * 128];     // M, D, T

// pre-transposed bf16 hi/lo weights: Bt[n][k] per matrix, offsets below
#define O1A 0                            // f1w top   [256][8192]
#define O1B 2097152                      // f1w bot   [256][128]
#define O2  2129920                      // f2w^T     [512][256]
#define O3  2260992                      // f3w^T     [1024][512]
#define O4  2785280                      // f4w^T     [8192][1024]
#define BT_TOTAL 11173888
__device__ __nv_bfloat16 g_bth[BT_TOTAL];
__device__ __nv_bfloat16 g_btl[BT_TOTAL];

// bf16 activations (hi/lo) + fp32 partial for f1
__device__ __nv_bfloat16 g_adjh[(size_t)MROW * ITEM];
__device__ __nv_bfloat16 g_feh[MROW * OUTD], g_fel[MROW * OUTD];
__device__ float         g_x1[MROW * 256];
__device__ __nv_bfloat16 g_x1h[MROW * 256],  g_x1l[MROW * 256];
__device__ __nv_bfloat16 g_x2h[MROW * 512],  g_x2l[MROW * 512];
__device__ __nv_bfloat16 g_x3h[MROW * 1024], g_x3l[MROW * 1024];

// ---------------- CSR build ----------------
__global__ void k_zero_counts() {
    int i = blockIdx.x * blockDim.x + threadIdx.x;
    if (i < NREL * NN) {
        ((int*)g_outcnt)[i] = 0;
        ((int*)g_incnt)[i]  = 0;
    }
}

__global__ void k_count(const int* __restrict__ edges) {
    int i = blockIdx.x * blockDim.x + threadIdx.x;
    if (i >= NREL * NE) return;
    int r = i / NE, e = i - r * NE;
    int src = edges[(size_t)r * 2 * NE + e];
    int dst = edges[(size_t)r * 2 * NE + NE + e];
    atomicAdd(&g_outcnt[r][src], 1);
    atomicAdd(&g_incnt[r][dst], 1);
}

__global__ void k_scan() {
    int r = blockIdx.x;
    int tid = threadIdx.x;          // 1024 threads
    int base = tid * 8;
    int c[8];
    int s = 0;
#pragma unroll
    for (int i = 0; i < 8; i++) { c[i] = g_incnt[r][base + i]; s += c[i]; }

    int lane = tid & 31, w = tid >> 5;
    int incl = s;
#pragma unroll
    for (int o = 1; o < 32; o <<= 1) {
        int v = __shfl_up_sync(0xffffffffu, incl, o);
        if (lane >= o) incl += v;
    }
    __shared__ int wsum[32];
    if (lane == 31) wsum[w] = incl;
    __syncthreads();
    if (w == 0) {
        int v = wsum[lane];
#pragma unroll
        for (int o = 1; o < 32; o <<= 1) {
            int t = __shfl_up_sync(0xffffffffu, v, o);
            if (lane >= o) v += t;
        }
        wsum[lane] = v;
    }
    __syncthreads();
    int excl = (incl - s) + (w > 0 ? wsum[w - 1] : 0);
    int run = excl;
#pragma unroll
    for (int i = 0; i < 8; i++) {
        g_rowptr[r][base + i] = run;
        g_fill[r][base + i]   = run;
        run += c[i];
        int ic = c[i] > 0 ? c[i] : 1;
        g_ininv[r][base + i] = rsqrtf((float)ic);
        int oc = g_outcnt[r][base + i];
        if (oc < 1) oc = 1;
        g_outinv[r][base + i] = rsqrtf((float)oc);
    }
    if (tid == 1023) g_rowptr[r][NN] = run;
}

__global__ void k_fill(const int* __restrict__ edges) {
    int i = blockIdx.x * blockDim.x + threadIdx.x;
    if (i >= NREL * NE) return;
    int r = i / NE, e = i - r * NE;
    int src = edges[(size_t)r * 2 * NE + e];
    int dst = edges[(size_t)r * 2 * NE + NE + e];
    int pos = atomicAdd(&g_fill[r][dst], 1);
    g_srcs[r][pos] = src;
}

// ---------------- conv GEMM batched over relations (gridDim.z = 6) --------
__global__ void k_conv_b(const float* __restrict__ A0, const float* __restrict__ A1,
                         const float* __restrict__ A2, const float* __restrict__ Wb,
                         int K, int Nh) {
    const int r = blockIdx.z;
    const int smap[6] = {0, 1, 0, 2, 2, 1};
    int si = smap[r];
    const float* A = (si == 0) ? A0 : (si == 1) ? A1 : A2;
    const float* W = Wb + (size_t)r * K * Nh;
    float* Xs = g_xs[r];
    const float* scale = g_outinv[r];

    __shared__ float As[16][64];
    __shared__ float Bs[16][64];
    int tid = threadIdx.x;
    int bx = blockIdx.x, by = blockIdx.y;
    int aRow = tid >> 2, aCol = (tid & 3) * 4;
    int bRow = tid >> 4, bCol = (tid & 15) * 4;
    int tx = tid & 15, ty = tid >> 4;
    float acc[4][4] = {};
    const float* Ap = A + (size_t)(by * 64) * K;
    float scl = scale[by * 64 + aRow];

    for (int k0 = 0; k0 < K; k0 += 16) {
        float4 av = *(const float4*)(Ap + (size_t)aRow * K + k0 + aCol);
        As[aCol + 0][aRow] = av.x * scl;
        As[aCol + 1][aRow] = av.y * scl;
        As[aCol + 2][aRow] = av.z * scl;
        As[aCol + 3][aRow] = av.w * scl;
        float4 bv = *(const float4*)(W + (size_t)(k0 + bRow) * Nh + bx * 64 + bCol);
        *(float4*)&Bs[bRow][bCol] = bv;
        __syncthreads();
#pragma unroll
        for (int kk = 0; kk < 16; kk++) {
            float a[4], b[4];
#pragma unroll
            for (int i = 0; i < 4; i++) a[i] = As[kk][ty * 4 + i];
#pragma unroll
            for (int j = 0; j < 4; j++) b[j] = Bs[kk][tx * 4 + j];
#pragma unroll
            for (int i = 0; i < 4; i++)
#pragma unroll
                for (int j = 0; j < 4; j++) acc[i][j] += a[i] * b[j];
        }
        __syncthreads();
    }
    int row0 = by * 64 + ty * 4, col0 = bx * 64 + tx * 4;
#pragma unroll
    for (int i = 0; i < 4; i++)
#pragma unroll
        for (int j = 0; j < 4; j++)
            Xs[(size_t)(row0 + i) * Nh + col0 + j] = acc[i][j];
}

// ---------------- aggregation: float4 gather over CSR ----------------------
__device__ __forceinline__ float4 f4add(float4 a, float4 b) {
    a.x += b.x; a.y += b.y; a.z += b.z; a.w += b.w; return a;
}
__device__ __forceinline__ float4 f4fma(float4 a, float s, float4 acc) {
    acc.x += a.x * s; acc.y += a.y * s; acc.z += a.z * s; acc.w += a.w * s; return acc;
}

template <int HID>
__global__ void k_agg_v(const float* __restrict__ bias) {
    const int t = blockIdx.y;
    const int n = blockIdx.x * blockDim.y + threadIdx.y;
    const int lane = threadIdx.x;     // 0..HID/4-1
    const int RA[3] = {1, 0, 2};
    const int RB[3] = {3, 4, 5};
    int rel[2] = {RA[t], RB[t]};
    float4 acc = f4add(reinterpret_cast<const float4*>(bias + rel[0] * HID)[lane],
                       reinterpret_cast<const float4*>(bias + rel[1] * HID)[lane]);
#pragma unroll
    for (int rr = 0; rr < 2; rr++) {
        int r = rel[rr];
        int e0 = g_rowptr[r][n], e1 = g_rowptr[r][n + 1];
        const float* xs = g_xs[r];
        const int* srcs = g_srcs[r];
        float4 s = make_float4(0.f, 0.f, 0.f, 0.f);
        int e = e0;
        for (; e + 1 < e1; e += 2) {
            int s0 = srcs[e], s1 = srcs[e + 1];
            float4 v0 = reinterpret_cast<const float4*>(xs + (size_t)s0 * HID)[lane];
            float4 v1 = reinterpret_cast<const float4*>(xs + (size_t)s1 * HID)[lane];
            s = f4add(s, v0);
            s = f4add(s, v1);
        }
        if (e < e1) {
            int s0 = srcs[e];
            s = f4add(s, reinterpret_cast<const float4*>(xs + (size_t)s0 * HID)[lane]);
        }
        acc = f4fma(s, g_ininv[r][n], acc);
    }
    reinterpret_cast<float4*>(g_node[t] + (size_t)n * HID)[lane] = acc;
}

// ---------------- bf16 helpers ----------------
__device__ __forceinline__ uint32_t pack_bf16(float x, float y) {
    __nv_bfloat162 h = __floats2bfloat162_rn(x, y);
    return *reinterpret_cast<uint32_t*>(&h);
}
__device__ __forceinline__ void split2(float x, float& hi, float& lo) {
    __nv_bfloat16 h = __float2bfloat16(x);
    hi = __bfloat162float(h);
    lo = x - hi;
}

// ---------------- row L1-normalize hM3[0:4096] -> fe (f32 + bf16 hi/lo) ----
__global__ void k_l1norm(float* __restrict__ out,
                         __nv_bfloat16* __restrict__ feh,
                         __nv_bfloat16* __restrict__ fel) {
    int row = blockIdx.x;
    int h = threadIdx.x;  // 128
    float v = g_node[0][(size_t)row * OUTD + h];
    float a = fabsf(v);
#pragma unroll
    for (int o = 16; o > 0; o >>= 1) a += __shfl_xor_sync(0xffffffffu, a, o);
    __shared__ float sh[4];
    if ((h & 31) == 0) sh[h >> 5] = a;
    __syncthreads();
    float tot = sh[0] + sh[1] + sh[2] + sh[3];
    float r = v / fmaxf(tot, 1e-12f);
    out[(size_t)row * OUTD + h] = r;
    float hi, lo;
    split2(r, hi, lo);
    feh[(size_t)row * OUTD + h] = __float2bfloat16(hi);
    fel[(size_t)row * OUTD + h] = __float2bfloat16(lo);
}

// ---------------- Adj fp32 -> bf16 (exact: values are 0/1) -----------------
__global__ void k_cvt(const float4* __restrict__ src, __nv_bfloat16* __restrict__ dst) {
    size_t i = (size_t)blockIdx.x * blockDim.x + threadIdx.x;
    float4 v = src[i];
    uint2 p = make_uint2(pack_bf16(v.x, v.y), pack_bf16(v.z, v.w));
    *reinterpret_cast<uint2*>(dst + 4 * i) = p;
}

// ---------------- weight transpose + hi/lo split: B[K][N] -> Bt[N][K] -----
__global__ void k_tsp(const float* __restrict__ B, __nv_bfloat16* __restrict__ th,
                      __nv_bfloat16* __restrict__ tl, int K, int N) {
    __shared__ float s[32][33];
    int n0 = blockIdx.x * 32, k0 = blockIdx.y * 32;
    int tx = threadIdx.x, ty = threadIdx.y;
#pragma unroll
    for (int i = 0; i < 32; i += 8)
        s[ty + i][tx] = B[(size_t)(k0 + ty + i) * N + n0 + tx];
    __syncthreads();
#pragma unroll
    for (int i = 0; i < 32; i += 8) {
        int n = n0 + ty + i, k = k0 + tx;
        float v = s[tx][ty + i];
        float h, l;
        split2(v, h, l);
        th[(size_t)n * K + k] = __float2bfloat16(h);
        tl[(size_t)n * K + k] = __float2bfloat16(l);
    }
}

// ---------------- mma.sync + ldmatrix + cp.async plumbing ------------------
__device__ __forceinline__ uint32_t s2u(const void* p) {
    uint32_t a;
    asm("{ .reg .u64 t; cvta.to.shared.u64 t, %1; cvt.u32.u64 %0, t; }" : "=r"(a) : "l"(p));
    return a;
}
__device__ __forceinline__ void mma_bf16(float* d, const uint32_t* a, const uint32_t* b) {
    asm volatile(
        "mma.sync.aligned.m16n8k16.row.col.f32.bf16.bf16.f32 "
        "{%0,%1,%2,%3}, {%4,%5,%6,%7}, {%8,%9}, {%0,%1,%2,%3};"
        : "+f"(d[0]), "+f"(d[1]), "+f"(d[2]), "+f"(d[3])
        : "r"(a[0]), "r"(a[1]), "r"(a[2]), "r"(a[3]), "r"(b[0]), "r"(b[1]));
}
__device__ __forceinline__ void ldsm4(uint32_t* r, uint32_t addr) {
    asm volatile("ldmatrix.sync.aligned.m8n8.x4.shared.b16 {%0,%1,%2,%3}, [%4];"
                 : "=r"(r[0]), "=r"(r[1]), "=r"(r[2]), "=r"(r[3]) : "r"(addr));
}
__device__ __forceinline__ void cpa16(uint32_t s, const void* g) {
    asm volatile("cp.async.cg.shared.global [%0], [%1], 16;" :: "r"(s), "l"(g));
}
#define CP_COMMIT() asm volatile("cp.async.commit_group;" ::: "memory")
#define CP_WAIT2()  asm volatile("cp.async.wait_group 2;" ::: "memory")

// ---------------- MLP GEMM: bf16 hi/lo pre-split operands ------------------
// C = act(Ah/Al @ (Bh/Bl)^T [+Cin] [+bias]); A [M][K] row-major bf16,
// B [N][K] row-major bf16 (i.e. col-major k x n). BM=BN=128, BK=64,
// 256 threads (8 warps 4m x 2n, warp tile 32x64), 3-stage cp.async pipeline.
// OUT: 0 = fp32 to Cf; 1 = bf16 hi/lo split to Oh/Ol (for next layer).
#define TC_STAGE 65536u                // Ah,Al,Bh,Bl tiles 16KB each
#define TC_SMEM  (3 * TC_STAGE)

template <int PASSES, int ACT, int OUT, bool HC>
__global__ void __launch_bounds__(256, 1)
k_tc(const __nv_bfloat16* __restrict__ Ah_, const __nv_bfloat16* __restrict__ Al_,
     const __nv_bfloat16* __restrict__ Bh_, const __nv_bfloat16* __restrict__ Bl_,
     const float* __restrict__ bias, const float* __restrict__ Cin,
     float* __restrict__ Cf, __nv_bfloat16* __restrict__ Oh,
     __nv_bfloat16* __restrict__ Ol, int N, int K) {
    extern __shared__ char smc[];
    const uint32_t sb = s2u(smc);
    const int tid = threadIdx.x, lane = tid & 31, warp = tid >> 5;
    const int wm = warp & 3, wn = warp >> 2;
    const int g = lane >> 2, tig = lane & 3;
    const int bm = blockIdx.y * 128, bn = blockIdx.x * 128;

    float c[2][8][4];
#pragma unroll
    for (int i = 0; i < 2; i++)
#pragma unroll
        for (int j = 0; j < 8; j++)
#pragma unroll
            for (int q = 0; q < 4; q++) c[i][j][q] = 0.f;

    auto load_stage = [&](int s) {
        const uint32_t st = sb + (uint32_t)(s % 3) * TC_STAGE;
        const int k0 = s * 64;
#pragma unroll
        for (int j = 0; j < 4; j++) {
            int cidx = tid + 256 * j;
            int row = cidx >> 3, kc = cidx & 7;
            uint32_t off = (uint32_t)(row * 128 + kc * 16);
            off ^= (off >> 3) & 0x70;
            size_t ga = (size_t)(bm + row) * K + k0 + kc * 8;
            size_t gb = (size_t)(bn + row) * K + k0 + kc * 8;
            cpa16(st + off, Ah_ + ga);
            if (PASSES == 3) cpa16(st + 16384 + off, Al_ + ga);
            cpa16(st + 32768 + off, Bh_ + gb);
            cpa16(st + 49152 + off, Bl_ + gb);
        }
    };

    const int nst = K >> 6;
#pragma unroll
    for (int i = 0; i < 3; i++) {
        if (i < nst) load_stage(i);
        CP_COMMIT();
    }

    for (int s = 0; s < nst; s++) {
        CP_WAIT2();
        __syncthreads();
        const uint32_t st = sb + (uint32_t)(s % 3) * TC_STAGE;
#pragma unroll
        for (int kk = 0; kk < 64; kk += 16) {
            uint32_t ah[2][4], al[2][4], bh[8][2], bl[8][2];
#pragma unroll
            for (int mt = 0; mt < 2; mt++) {
                int row = wm * 32 + mt * 16 + (lane & 15);
                uint32_t off = (uint32_t)(row * 128) + (uint32_t)(kk * 2) + (uint32_t)(lane & 16);
                off ^= (off >> 3) & 0x70;
                ldsm4(ah[mt], st + off);
                if (PASSES == 3) ldsm4(al[mt], st + 16384 + off);
            }
#pragma unroll
            for (int bt = 0; bt < 4; bt++) {
                int row = wn * 64 + bt * 16 + ((lane >> 4) << 3) + (lane & 7);
                uint32_t off = (uint32_t)(row * 128) + (uint32_t)(kk * 2) + (uint32_t)((lane & 8) << 1);
                off ^= (off >> 3) & 0x70;
                uint32_t r[4];
                ldsm4(r, st + 32768 + off);
                bh[2 * bt][0] = r[0]; bh[2 * bt][1] = r[1];
                bh[2 * bt + 1][0] = r[2]; bh[2 * bt + 1][1] = r[3];
                ldsm4(r, st + 49152 + off);
                bl[2 * bt][0] = r[0]; bl[2 * bt][1] = r[1];
                bl[2 * bt + 1][0] = r[2]; bl[2 * bt + 1][1] = r[3];
            }
#pragma unroll
            for (int mt = 0; mt < 2; mt++)
#pragma unroll
                for (int nt = 0; nt < 8; nt++) {
                    mma_bf16(c[mt][nt], ah[mt], bh[nt]);
                    mma_bf16(c[mt][nt], ah[mt], bl[nt]);
                    if (PASSES == 3) mma_bf16(c[mt][nt], al[mt], bh[nt]);
                }
        }
        __syncthreads();
        if (s + 3 < nst) load_stage(s + 3);
        CP_COMMIT();
    }

    // epilogue
#pragma unroll
    for (int mt = 0; mt < 2; mt++) {
#pragma unroll
        for (int nt = 0; nt < 8; nt++) {
            int m0 = bm + wm * 32 + mt * 16 + g;
            int n0 = bn + wn * 64 + nt * 8 + 2 * tig;
            float2 v0 = make_float2(c[mt][nt][0], c[mt][nt][1]);
            float2 v1 = make_float2(c[mt][nt][2], c[mt][nt][3]);
            if (HC) {
                float2 ci0 = *reinterpret_cast<const float2*>(Cin + (size_t)m0 * N + n0);
                float2 ci1 = *reinterpret_cast<const float2*>(Cin + (size_t)(m0 + 8) * N + n0);
                v0.x += ci0.x; v0.y += ci0.y; v1.x += ci1.x; v1.y += ci1.y;
            }
            if (bias) {
                float bx = bias[n0], by = bias[n0 + 1];
                v0.x += bx; v0.y += by; v1.x += bx; v1.y += by;
            }
            if (ACT == 1) {
                v0.x = fmaxf(v0.x, 0.f); v0.y = fmaxf(v0.y, 0.f);
                v1.x = fmaxf(v1.x, 0.f); v1.y = fmaxf(v1.y, 0.f);
            } else if (ACT == 2) {
                v0.x = 1.f / (1.f + expf(-v0.x)); v0.y = 1.f / (1.f + expf(-v0.y));
                v1.x = 1.f / (1.f + expf(-v1.x)); v1.y = 1.f / (1.f + expf(-v1.y));
            }
            if (OUT == 0) {
                *reinterpret_cast<float2*>(Cf + (size_t)m0 * N + n0) = v0;
                *reinterpret_cast<float2*>(Cf + (size_t)(m0 + 8) * N + n0) = v1;
            } else {
                float h0, l0, h1, l1;
                split2(v0.x, h0, l0); split2(v0.y, h1, l1);
                *reinterpret_cast<uint32_t*>(Oh + (size_t)m0 * N + n0) = pack_bf16(h0, h1);
                *reinterpret_cast<uint32_t*>(Ol + (size_t)m0 * N + n0) = pack_bf16(l0, l1);
                split2(v1.x, h0, l0); split2(v1.y, h1, l1);
                *reinterpret_cast<uint32_t*>(Oh + (size_t)(m0 + 8) * N + n0) = pack_bf16(h0, h1);
                *reinterpret_cast<uint32_t*>(Ol + (size_t)(m0 + 8) * N + n0) = pack_bf16(l0, l1);
            }
        }
    }
}

// ---------------- orchestration ----------------
extern "C" void kernel_launch(void* const* d_in, const int* in_sizes, int n_in,
                              void* d_out, int out_size) {
    const float* hM  = (const float*)d_in[0];
    const float* hD  = (const float*)d_in[1];
    const float* hT  = (const float*)d_in[2];
    const float* W1  = (const float*)d_in[3];
    const float* b1  = (const float*)d_in[4];
    const float* W2  = (const float*)d_in[5];
    const float* b2  = (const float*)d_in[6];
    const float* W3  = (const float*)d_in[7];
    const float* b3  = (const float*)d_in[8];
    const float* Adj = (const float*)d_in[9];
    const float* f1w = (const float*)d_in[10];
    const float* f1b = (const float*)d_in[11];
    const float* f2w = (const float*)d_in[12];
    const float* f2b = (const float*)d_in[13];
    const float* f3w = (const float*)d_in[14];
    const float* f3b = (const float*)d_in[15];
    const float* f4w = (const float*)d_in[16];
    const float* f4b = (const float*)d_in[17];
    const int* edges = (const int*)d_in[18];

    float *p_node, *p_x1;
    __nv_bfloat16 *p_bth, *p_btl, *p_adjh, *p_feh, *p_fel;
    __nv_bfloat16 *p_x1h, *p_x1l, *p_x2h, *p_x2l, *p_x3h, *p_x3l;
    cudaGetSymbolAddress((void**)&p_node, g_node);
    cudaGetSymbolAddress((void**)&p_x1, g_x1);
    cudaGetSymbolAddress((void**)&p_bth, g_bth);
    cudaGetSymbolAddress((void**)&p_btl, g_btl);
    cudaGetSymbolAddress((void**)&p_adjh, g_adjh);
    cudaGetSymbolAddress((void**)&p_feh, g_feh);
    cudaGetSymbolAddress((void**)&p_fel, g_fel);
    cudaGetSymbolAddress((void**)&p_x1h, g_x1h);
    cudaGetSymbolAddress((void**)&p_x1l, g_x1l);
    cudaGetSymbolAddress((void**)&p_x2h, g_x2h);
    cudaGetSymbolAddress((void**)&p_x2l, g_x2l);
    cudaGetSymbolAddress((void**)&p_x3h, g_x3h);
    cudaGetSymbolAddress((void**)&p_x3l, g_x3l);

    float* fe   = (float*)d_out;                       // 4096 x 128
    float* outx = (float*)d_out + (size_t)MROW * OUTD; // 4096 x 8192

    cudaFuncSetAttribute(k_tc<2, 0, 0, false>, cudaFuncAttributeMaxDynamicSharedMemorySize, TC_SMEM);
    cudaFuncSetAttribute(k_tc<3, 1, 1, true >, cudaFuncAttributeMaxDynamicSharedMemorySize, TC_SMEM);
    cudaFuncSetAttribute(k_tc<3, 1, 1, false>, cudaFuncAttributeMaxDynamicSharedMemorySize, TC_SMEM);
    cudaFuncSetAttribute(k_tc<3, 2, 0, false>, cudaFuncAttributeMaxDynamicSharedMemorySize, TC_SMEM);

    // operand prep (independent of GNN stages)
    k_cvt<<<(MROW * ITEM / 4) / 256, 256>>>((const float4*)Adj, p_adjh);
    k_tsp<<<dim3(256 / 32, 8192 / 32), dim3(32, 8)>>>(f1w, p_bth + O1A, p_btl + O1A, 8192, 256);
    k_tsp<<<dim3(256 / 32, 128 / 32),  dim3(32, 8)>>>(f1w + (size_t)ITEM * 256, p_bth + O1B, p_btl + O1B, 128, 256);
    k_tsp<<<dim3(512 / 32, 256 / 32),  dim3(32, 8)>>>(f2w, p_bth + O2, p_btl + O2, 256, 512);
    k_tsp<<<dim3(1024 / 32, 512 / 32), dim3(32, 8)>>>(f3w, p_bth + O3, p_btl + O3, 512, 1024);
    k_tsp<<<dim3(8192 / 32, 1024 / 32), dim3(32, 8)>>>(f4w, p_bth + O4, p_btl + O4, 1024, 8192);

    // CSR + degrees
    k_zero_counts<<<(NREL * NN + 255) / 256, 256>>>();
    k_count<<<(NREL * NE + 255) / 256, 256>>>(edges);
    k_scan<<<NREL, 1024>>>();
    k_fill<<<(NREL * NE + 255) / 256, 256>>>(edges);

    // layer 1: FEAT=256 -> 64
    k_conv_b<<<dim3(1, NN / 64, 6), 256>>>(hM, hD, hT, W1, 256, 64);
    k_agg_v<64><<<dim3(NN / 8, 3), dim3(16, 8)>>>(b1);

    // layer 2: 64 -> 64
    k_conv_b<<<dim3(1, NN / 64, 6), 256>>>(p_node, p_node + (size_t)NN * 128,
                                           p_node + (size_t)2 * NN * 128, W2, 64, 64);
    k_agg_v<64><<<dim3(NN / 8, 3), dim3(16, 8)>>>(b2);

    // layer 3: 64 -> 128
    k_conv_b<<<dim3(2, NN / 64, 6), 256>>>(p_node, p_node + (size_t)NN * 128,
                                           p_node + (size_t)2 * NN * 128, W3, 64, 128);
    k_agg_v<128><<<dim3(NN / 4, 3), dim3(32, 4)>>>(b3);

    // fake_embeding = L1-normalized hM3[0:4096] -> d_out (+ bf16 hi/lo)
    k_l1norm<<<MROW, 128>>>(fe, p_feh, p_fel);

    // MLP decoder
    // x1_partial = Adj @ f1w_top   (Adj exact in bf16 -> 2-pass)
    k_tc<2, 0, 0, false><<<dim3(2, 32), 256, TC_SMEM>>>(
        p_adjh, p_adjh, p_bth + O1A, p_btl + O1A, nullptr, nullptr,
        p_x1, nullptr, nullptr, 256, 8192);
    // x1 = relu(fe @ f1w_bot + x1_partial + f1b) -> split bf16
    k_tc<3, 1, 1, true><<<dim3(2, 32), 256, TC_SMEM>>>(
        p_feh, p_fel, p_bth + O1B, p_btl + O1B, f1b, p_x1,
        nullptr, p_x1h, p_x1l, 256, 128);
    // x2 = relu(x1 @ f2w + f2b) -> split
    k_tc<3, 1, 1, false><<<dim3(4, 32), 256, TC_SMEM>>>(
        p_x1h, p_x1l, p_bth + O2, p_btl + O2, f2b, nullptr,
        nullptr, p_x2h, p_x2l, 512, 256);
    // x3 = relu(x2 @ f3w + f3b) -> split
    k_tc<3, 1, 1, false><<<dim3(8, 32), 256, TC_SMEM>>>(
        p_x2h, p_x2l, p_bth + O3, p_btl + O3, f3b, nullptr,
        nullptr, p_x3h, p_x3l, 1024, 512);
    // out = sigmoid(x3 @ f4w + f4b) -> fp32
    k_tc<3, 2, 0, false><<<dim3(64, 32), 256, TC_SMEM>>>(
        p_x3h, p_x3l, p_bth + O4, p_btl + O4, f4b, nullptr,
        outx, nullptr, nullptr, 8192, 1024);
}

// round 6
// speedup vs baseline: 3.3618x; 1.0467x over previous
#include <cuda_runtime.h>
#include <cuda_bf16.h>
#include <stdint.h>
#include <math.h>

#define NN   8192
#define NE   500000
#define NREL 6
#define FEAT 256
#define HIDD 64
#define OUTD 128
#define MROW 4096   // SIZE
#define ITEM 8192

// ---------------- scratch (device globals: allocation-free) ----------------
__device__ int   g_outcnt[NREL][NN];
__device__ int   g_incnt [NREL][NN];
__device__ float g_outinv[NREL][NN];
__device__ float g_ininv [NREL][NN];
__device__ int   g_rowptr[NREL][NN + 1];
__device__ int   g_fill  [NREL][NN];
__device__ int   g_srcs  [NREL][NE];
__device__ float g_xs    [NREL][NN * 128];
__device__ float g_agg   [NREL][NN * 64];   // layer-3 pre-aggregated inputs
__device__ float g_node  [3][NN * 128];     // M, D, T

// pre-transposed bf16 hi/lo weights: Bt[n][k] per matrix, offsets below
#define O1A 0                            // f1w top   [256][8192]
#define O1B 2097152                      // f1w bot   [256][128]
#define O2  2129920                      // f2w^T     [512][256]
#define O3  2260992                      // f3w^T     [1024][512]
#define O4  2785280                      // f4w^T     [8192][1024]
#define BT_TOTAL 11173888
__device__ __nv_bfloat16 g_bth[BT_TOTAL];
__device__ __nv_bfloat16 g_btl[BT_TOTAL];

// bf16 activations (hi/lo) + fp32 partial for f1
__device__ __nv_bfloat16 g_adjh[(size_t)MROW * ITEM];
__device__ __nv_bfloat16 g_feh[MROW * OUTD], g_fel[MROW * OUTD];
__device__ float         g_x1[MROW * 256];
__device__ __nv_bfloat16 g_x1h[MROW * 256],  g_x1l[MROW * 256];
__device__ __nv_bfloat16 g_x2h[MROW * 512],  g_x2l[MROW * 512];
__device__ __nv_bfloat16 g_x3h[MROW * 1024], g_x3l[MROW * 1024];

// ---------------- CSR build ----------------
__global__ void k_zero_counts() {
    int i = blockIdx.x * blockDim.x + threadIdx.x;
    if (i < NREL * NN) {
        ((int*)g_outcnt)[i] = 0;
        ((int*)g_incnt)[i]  = 0;
    }
}

// 4 edges per thread, int4 loads (NE % 4 == 0, offsets 2*NE*r % 4 == 0)
__global__ void k_count(const int* __restrict__ edges) {
    int i = (blockIdx.x * blockDim.x + threadIdx.x) * 4;
    if (i >= NREL * NE) return;
    int r = i / NE, e = i - r * NE;
    int4 src = *reinterpret_cast<const int4*>(edges + (size_t)r * 2 * NE + e);
    int4 dst = *reinterpret_cast<const int4*>(edges + (size_t)r * 2 * NE + NE + e);
    atomicAdd(&g_outcnt[r][src.x], 1);
    atomicAdd(&g_outcnt[r][src.y], 1);
    atomicAdd(&g_outcnt[r][src.z], 1);
    atomicAdd(&g_outcnt[r][src.w], 1);
    atomicAdd(&g_incnt[r][dst.x], 1);
    atomicAdd(&g_incnt[r][dst.y], 1);
    atomicAdd(&g_incnt[r][dst.z], 1);
    atomicAdd(&g_incnt[r][dst.w], 1);
}

__global__ void k_scan() {
    int r = blockIdx.x;
    int tid = threadIdx.x;          // 1024 threads
    int base = tid * 8;
    int c[8];
    int s = 0;
#pragma unroll
    for (int i = 0; i < 8; i++) { c[i] = g_incnt[r][base + i]; s += c[i]; }

    int lane = tid & 31, w = tid >> 5;
    int incl = s;
#pragma unroll
    for (int o = 1; o < 32; o <<= 1) {
        int v = __shfl_up_sync(0xffffffffu, incl, o);
        if (lane >= o) incl += v;
    }
    __shared__ int wsum[32];
    if (lane == 31) wsum[w] = incl;
    __syncthreads();
    if (w == 0) {
        int v = wsum[lane];
#pragma unroll
        for (int o = 1; o < 32; o <<= 1) {
            int t = __shfl_up_sync(0xffffffffu, v, o);
            if (lane >= o) v += t;
        }
        wsum[lane] = v;
    }
    __syncthreads();
    int excl = (incl - s) + (w > 0 ? wsum[w - 1] : 0);
    int run = excl;
#pragma unroll
    for (int i = 0; i < 8; i++) {
        g_rowptr[r][base + i] = run;
        g_fill[r][base + i]   = run;
        run += c[i];
        int ic = c[i] > 0 ? c[i] : 1;
        g_ininv[r][base + i] = rsqrtf((float)ic);
        int oc = g_outcnt[r][base + i];
        if (oc < 1) oc = 1;
        g_outinv[r][base + i] = rsqrtf((float)oc);
    }
    if (tid == 1023) g_rowptr[r][NN] = run;
}

__global__ void k_fill(const int* __restrict__ edges) {
    int i = (blockIdx.x * blockDim.x + threadIdx.x) * 4;
    if (i >= NREL * NE) return;
    int r = i / NE, e = i - r * NE;
    int4 src = *reinterpret_cast<const int4*>(edges + (size_t)r * 2 * NE + e);
    int4 dst = *reinterpret_cast<const int4*>(edges + (size_t)r * 2 * NE + NE + e);
    g_srcs[r][atomicAdd(&g_fill[r][dst.x], 1)] = src.x;
    g_srcs[r][atomicAdd(&g_fill[r][dst.y], 1)] = src.y;
    g_srcs[r][atomicAdd(&g_fill[r][dst.z], 1)] = src.z;
    g_srcs[r][atomicAdd(&g_fill[r][dst.w], 1)] = src.w;
}

// ---------------- conv GEMM batched over relations (gridDim.z = 6) --------
// Xs_r = (A_r * scale_r[row]) @ W_r. If A1==nullptr, A = A0 + r*NN*K (per-rel).
__global__ void k_conv_b(const float* __restrict__ A0, const float* __restrict__ A1,
                         const float* __restrict__ A2, const float* __restrict__ Wb,
                         const float* __restrict__ scaleb, int K, int Nh) {
    const int r = blockIdx.z;
    const int smap[6] = {0, 1, 0, 2, 2, 1};
    const float* A;
    if (A1 == nullptr) {
        A = A0 + (size_t)r * NN * K;
    } else {
        int si = smap[r];
        A = (si == 0) ? A0 : (si == 1) ? A1 : A2;
    }
    const float* W = Wb + (size_t)r * K * Nh;
    float* Xs = g_xs[r];
    const float* scale = scaleb + r * NN;

    __shared__ float As[16][64];
    __shared__ float Bs[16][64];
    int tid = threadIdx.x;
    int bx = blockIdx.x, by = blockIdx.y;
    int aRow = tid >> 2, aCol = (tid & 3) * 4;
    int bRow = tid >> 4, bCol = (tid & 15) * 4;
    int tx = tid & 15, ty = tid >> 4;
    float acc[4][4] = {};
    const float* Ap = A + (size_t)(by * 64) * K;
    float scl = scale[by * 64 + aRow];

    for (int k0 = 0; k0 < K; k0 += 16) {
        float4 av = *(const float4*)(Ap + (size_t)aRow * K + k0 + aCol);
        As[aCol + 0][aRow] = av.x * scl;
        As[aCol + 1][aRow] = av.y * scl;
        As[aCol + 2][aRow] = av.z * scl;
        As[aCol + 3][aRow] = av.w * scl;
        float4 bv = *(const float4*)(W + (size_t)(k0 + bRow) * Nh + bx * 64 + bCol);
        *(float4*)&Bs[bRow][bCol] = bv;
        __syncthreads();
#pragma unroll
        for (int kk = 0; kk < 16; kk++) {
            float a[4], b[4];
#pragma unroll
            for (int i = 0; i < 4; i++) a[i] = As[kk][ty * 4 + i];
#pragma unroll
            for (int j = 0; j < 4; j++) b[j] = Bs[kk][tx * 4 + j];
#pragma unroll
            for (int i = 0; i < 4; i++)
#pragma unroll
                for (int j = 0; j < 4; j++) acc[i][j] += a[i] * b[j];
        }
        __syncthreads();
    }
    int row0 = by * 64 + ty * 4, col0 = bx * 64 + tx * 4;
#pragma unroll
    for (int i = 0; i < 4; i++)
#pragma unroll
        for (int j = 0; j < 4; j++)
            Xs[(size_t)(row0 + i) * Nh + col0 + j] = acc[i][j];
}

// ---------------- aggregation helpers ----------------
__device__ __forceinline__ float4 f4add(float4 a, float4 b) {
    a.x += b.x; a.y += b.y; a.z += b.z; a.w += b.w; return a;
}
__device__ __forceinline__ float4 f4fma(float4 a, float s, float4 acc) {
    acc.x += a.x * s; acc.y += a.y * s; acc.z += a.z * s; acc.w += a.w * s; return acc;
}

// post-GEMM agg (layers 1,2): newnode[t] = (Σ xs)·ind + biases, HID=64
__global__ void k_agg_v(const float* __restrict__ bias) {
    const int t = blockIdx.y;
    const int n = blockIdx.x * blockDim.y + threadIdx.y;
    const int lane = threadIdx.x;     // 0..15
    const int RA[3] = {1, 0, 2};
    const int RB[3] = {3, 4, 5};
    int rel[2] = {RA[t], RB[t]};
    float4 acc = f4add(reinterpret_cast<const float4*>(bias + rel[0] * 64)[lane],
                       reinterpret_cast<const float4*>(bias + rel[1] * 64)[lane]);
#pragma unroll
    for (int rr = 0; rr < 2; rr++) {
        int r = rel[rr];
        int e0 = g_rowptr[r][n], e1 = g_rowptr[r][n + 1];
        const float* xs = g_xs[r];
        const int* srcs = g_srcs[r];
        float4 s = make_float4(0.f, 0.f, 0.f, 0.f);
        int e = e0;
        for (; e + 3 < e1; e += 4) {
            int s0 = srcs[e], s1 = srcs[e + 1], s2 = srcs[e + 2], s3 = srcs[e + 3];
            float4 v0 = reinterpret_cast<const float4*>(xs + (size_t)s0 * 64)[lane];
            float4 v1 = reinterpret_cast<const float4*>(xs + (size_t)s1 * 64)[lane];
            float4 v2 = reinterpret_cast<const float4*>(xs + (size_t)s2 * 64)[lane];
            float4 v3 = reinterpret_cast<const float4*>(xs + (size_t)s3 * 64)[lane];
            s = f4add(s, f4add(f4add(v0, v1), f4add(v2, v3)));
        }
        for (; e < e1; e++) {
            int s0 = srcs[e];
            s = f4add(s, reinterpret_cast<const float4*>(xs + (size_t)s0 * 64)[lane]);
        }
        acc = f4fma(s, g_ininv[r][n], acc);
    }
    reinterpret_cast<float4*>(g_node[t] + (size_t)n * 64)[lane] = acc;
}

// pre-GEMM agg (layer 3): g_agg[r][n] = Σ_{src} node[smap[r]][src]·outinv_r[src]
__global__ void k_aggpre() {
    const int r = blockIdx.y;
    const int n = blockIdx.x * blockDim.y + threadIdx.y;
    const int lane = threadIdx.x;     // 0..15
    const int smap[6] = {0, 1, 0, 2, 2, 1};
    const float* x = g_node[smap[r]];
    const float* oi = g_outinv[r];
    const int* srcs = g_srcs[r];
    int e0 = g_rowptr[r][n], e1 = g_rowptr[r][n + 1];
    float4 acc = make_float4(0.f, 0.f, 0.f, 0.f);
    int e = e0;
    for (; e + 3 < e1; e += 4) {
        int s0 = srcs[e], s1 = srcs[e + 1], s2 = srcs[e + 2], s3 = srcs[e + 3];
        float4 v0 = reinterpret_cast<const float4*>(x + (size_t)s0 * 64)[lane];
        float4 v1 = reinterpret_cast<const float4*>(x + (size_t)s1 * 64)[lane];
        float4 v2 = reinterpret_cast<const float4*>(x + (size_t)s2 * 64)[lane];
        float4 v3 = reinterpret_cast<const float4*>(x + (size_t)s3 * 64)[lane];
        acc = f4fma(v0, oi[s0], acc);
        acc = f4fma(v1, oi[s1], acc);
        acc = f4fma(v2, oi[s2], acc);
        acc = f4fma(v3, oi[s3], acc);
    }
    for (; e < e1; e++) {
        int s0 = srcs[e];
        float4 v0 = reinterpret_cast<const float4*>(x + (size_t)s0 * 64)[lane];
        acc = f4fma(v0, oi[s0], acc);
    }
    reinterpret_cast<float4*>(g_agg[r] + (size_t)n * 64)[lane] = acc;
}

// layer-3 combine: node[t] = xs[ra] + xs[rb] + b[ra] + b[rb]  (stride 128)
__global__ void k_addb(const float* __restrict__ bias) {
    const int t = blockIdx.y;
    const int RA[3] = {1, 0, 2};
    const int RB[3] = {3, 4, 5};
    int ra = RA[t], rb = RB[t];
    int i = blockIdx.x * blockDim.x + threadIdx.x;   // over NN*128/4
    int h = (i & 31);                                 // float4 col index
    float4 a = reinterpret_cast<const float4*>(g_xs[ra])[i];
    float4 b = reinterpret_cast<const float4*>(g_xs[rb])[i];
    float4 ba = reinterpret_cast<const float4*>(bias + ra * 128)[h];
    float4 bb = reinterpret_cast<const float4*>(bias + rb * 128)[h];
    float4 o;
    o.x = a.x + b.x + ba.x + bb.x;
    o.y = a.y + b.y + ba.y + bb.y;
    o.z = a.z + b.z + ba.z + bb.z;
    o.w = a.w + b.w + ba.w + bb.w;
    reinterpret_cast<float4*>(g_node[t])[i] = o;
}

// ---------------- bf16 helpers ----------------
__device__ __forceinline__ uint32_t pack_bf16(float x, float y) {
    __nv_bfloat162 h = __floats2bfloat162_rn(x, y);
    return *reinterpret_cast<uint32_t*>(&h);
}
__device__ __forceinline__ void split2(float x, float& hi, float& lo) {
    __nv_bfloat16 h = __float2bfloat16(x);
    hi = __bfloat162float(h);
    lo = x - hi;
}

// ---------------- row L1-normalize hM3[0:4096] -> fe (f32 + bf16 hi/lo) ----
__global__ void k_l1norm(float* __restrict__ out,
                         __nv_bfloat16* __restrict__ feh,
                         __nv_bfloat16* __restrict__ fel) {
    int row = blockIdx.x;
    int h = threadIdx.x;  // 128
    float v = g_node[0][(size_t)row * OUTD + h];
    float a = fabsf(v);
#pragma unroll
    for (int o = 16; o > 0; o >>= 1) a += __shfl_xor_sync(0xffffffffu, a, o);
    __shared__ float sh[4];
    if ((h & 31) == 0) sh[h >> 5] = a;
    __syncthreads();
    float tot = sh[0] + sh[1] + sh[2] + sh[3];
    float r = v / fmaxf(tot, 1e-12f);
    out[(size_t)row * OUTD + h] = r;
    float hi, lo;
    split2(r, hi, lo);
    feh[(size_t)row * OUTD + h] = __float2bfloat16(hi);
    fel[(size_t)row * OUTD + h] = __float2bfloat16(lo);
}

// ---------------- Adj fp32 -> bf16 (exact: values are 0/1) -----------------
__global__ void k_cvt(const float4* __restrict__ src, __nv_bfloat16* __restrict__ dst) {
    size_t i = (size_t)blockIdx.x * blockDim.x + threadIdx.x;
    float4 v = src[i];
    uint2 p = make_uint2(pack_bf16(v.x, v.y), pack_bf16(v.z, v.w));
    *reinterpret_cast<uint2*>(dst + 4 * i) = p;
}

// ---------------- weight transpose + hi/lo split: B[K][N] -> Bt[N][K] -----
__global__ void k_tsp(const float* __restrict__ B, __nv_bfloat16* __restrict__ th,
                      __nv_bfloat16* __restrict__ tl, int K, int N) {
    __shared__ float s[32][33];
    int n0 = blockIdx.x * 32, k0 = blockIdx.y * 32;
    int tx = threadIdx.x, ty = threadIdx.y;
#pragma unroll
    for (int i = 0; i < 32; i += 8)
        s[ty + i][tx] = B[(size_t)(k0 + ty + i) * N + n0 + tx];
    __syncthreads();
#pragma unroll
    for (int i = 0; i < 32; i += 8) {
        int n = n0 + ty + i, k = k0 + tx;
        float v = s[tx][ty + i];
        float h, l;
        split2(v, h, l);
        th[(size_t)n * K + k] = __float2bfloat16(h);
        tl[(size_t)n * K + k] = __float2bfloat16(l);
    }
}

// ---------------- mma.sync + ldmatrix + cp.async plumbing ------------------
__device__ __forceinline__ uint32_t s2u(const void* p) {
    uint32_t a;
    asm("{ .reg .u64 t; cvta.to.shared.u64 t, %1; cvt.u32.u64 %0, t; }" : "=r"(a) : "l"(p));
    return a;
}
__device__ __forceinline__ void mma_bf16(float* d, const uint32_t* a, const uint32_t* b) {
    asm volatile(
        "mma.sync.aligned.m16n8k16.row.col.f32.bf16.bf16.f32 "
        "{%0,%1,%2,%3}, {%4,%5,%6,%7}, {%8,%9}, {%0,%1,%2,%3};"
        : "+f"(d[0]), "+f"(d[1]), "+f"(d[2]), "+f"(d[3])
        : "r"(a[0]), "r"(a[1]), "r"(a[2]), "r"(a[3]), "r"(b[0]), "r"(b[1]));
}
__device__ __forceinline__ void ldsm4(uint32_t* r, uint32_t addr) {
    asm volatile("ldmatrix.sync.aligned.m8n8.x4.shared.b16 {%0,%1,%2,%3}, [%4];"
                 : "=r"(r[0]), "=r"(r[1]), "=r"(r[2]), "=r"(r[3]) : "r"(addr));
}
__device__ __forceinline__ void cpa16(uint32_t s, const void* g) {
    asm volatile("cp.async.cg.shared.global [%0], [%1], 16;" :: "r"(s), "l"(g));
}
#define CP_COMMIT() asm volatile("cp.async.commit_group;" ::: "memory")
#define CP_WAIT2()  asm volatile("cp.async.wait_group 2;" ::: "memory")

// ---------------- MLP GEMM: bf16 hi/lo pre-split operands ------------------
#define TC_STAGE 65536u                // Ah,Al,Bh,Bl tiles 16KB each
#define TC_SMEM  (3 * TC_STAGE)

template <int PASSES, int ACT, int OUT, bool HC>
__global__ void __launch_bounds__(256, 1)
k_tc(const __nv_bfloat16* __restrict__ Ah_, const __nv_bfloat16* __restrict__ Al_,
     const __nv_bfloat16* __restrict__ Bh_, const __nv_bfloat16* __restrict__ Bl_,
     const float* __restrict__ bias, const float* __restrict__ Cin,
     float* __restrict__ Cf, __nv_bfloat16* __restrict__ Oh,
     __nv_bfloat16* __restrict__ Ol, int N, int K) {
    extern __shared__ char smc[];
    const uint32_t sb = s2u(smc);
    const int tid = threadIdx.x, lane = tid & 31, warp = tid >> 5;
    const int wm = warp & 3, wn = warp >> 2;
    const int g = lane >> 2, tig = lane & 3;
    const int bm = blockIdx.y * 128, bn = blockIdx.x * 128;

    float c[2][8][4];
#pragma unroll
    for (int i = 0; i < 2; i++)
#pragma unroll
        for (int j = 0; j < 8; j++)
#pragma unroll
            for (int q = 0; q < 4; q++) c[i][j][q] = 0.f;

    auto load_stage = [&](int s) {
        const uint32_t st = sb + (uint32_t)(s % 3) * TC_STAGE;
        const int k0 = s * 64;
#pragma unroll
        for (int j = 0; j < 4; j++) {
            int cidx = tid + 256 * j;
            int row = cidx >> 3, kc = cidx & 7;
            uint32_t off = (uint32_t)(row * 128 + kc * 16);
            off ^= (off >> 3) & 0x70;
            size_t ga = (size_t)(bm + row) * K + k0 + kc * 8;
            size_t gb = (size_t)(bn + row) * K + k0 + kc * 8;
            cpa16(st + off, Ah_ + ga);
            if (PASSES == 3) cpa16(st + 16384 + off, Al_ + ga);
            cpa16(st + 32768 + off, Bh_ + gb);
            cpa16(st + 49152 + off, Bl_ + gb);
        }
    };

    const int nst = K >> 6;
#pragma unroll
    for (int i = 0; i < 3; i++) {
        if (i < nst) load_stage(i);
        CP_COMMIT();
    }

    for (int s = 0; s < nst; s++) {
        CP_WAIT2();
        __syncthreads();
        const uint32_t st = sb + (uint32_t)(s % 3) * TC_STAGE;
#pragma unroll
        for (int kk = 0; kk < 64; kk += 16) {
            uint32_t ah[2][4], al[2][4], bh[8][2], bl[8][2];
#pragma unroll
            for (int mt = 0; mt < 2; mt++) {
                int row = wm * 32 + mt * 16 + (lane & 15);
                uint32_t off = (uint32_t)(row * 128) + (uint32_t)(kk * 2) + (uint32_t)(lane & 16);
                off ^= (off >> 3) & 0x70;
                ldsm4(ah[mt], st + off);
                if (PASSES == 3) ldsm4(al[mt], st + 16384 + off);
            }
#pragma unroll
            for (int bt = 0; bt < 4; bt++) {
                int row = wn * 64 + bt * 16 + ((lane >> 4) << 3) + (lane & 7);
                uint32_t off = (uint32_t)(row * 128) + (uint32_t)(kk * 2) + (uint32_t)((lane & 8) << 1);
                off ^= (off >> 3) & 0x70;
                uint32_t r[4];
                ldsm4(r, st + 32768 + off);
                bh[2 * bt][0] = r[0]; bh[2 * bt][1] = r[1];
                bh[2 * bt + 1][0] = r[2]; bh[2 * bt + 1][1] = r[3];
                ldsm4(r, st + 49152 + off);
                bl[2 * bt][0] = r[0]; bl[2 * bt][1] = r[1];
                bl[2 * bt + 1][0] = r[2]; bl[2 * bt + 1][1] = r[3];
            }
#pragma unroll
            for (int mt = 0; mt < 2; mt++)
#pragma unroll
                for (int nt = 0; nt < 8; nt++) {
                    mma_bf16(c[mt][nt], ah[mt], bh[nt]);
                    mma_bf16(c[mt][nt], ah[mt], bl[nt]);
                    if (PASSES == 3) mma_bf16(c[mt][nt], al[mt], bh[nt]);
                }
        }
        __syncthreads();
        if (s + 3 < nst) load_stage(s + 3);
        CP_COMMIT();
    }

    // epilogue
#pragma unroll
    for (int mt = 0; mt < 2; mt++) {
#pragma unroll
        for (int nt = 0; nt < 8; nt++) {
            int m0 = bm + wm * 32 + mt * 16 + g;
            int n0 = bn + wn * 64 + nt * 8 + 2 * tig;
            float2 v0 = make_float2(c[mt][nt][0], c[mt][nt][1]);
            float2 v1 = make_float2(c[mt][nt][2], c[mt][nt][3]);
            if (HC) {
                float2 ci0 = *reinterpret_cast<const float2*>(Cin + (size_t)m0 * N + n0);
                float2 ci1 = *reinterpret_cast<const float2*>(Cin + (size_t)(m0 + 8) * N + n0);
                v0.x += ci0.x; v0.y += ci0.y; v1.x += ci1.x; v1.y += ci1.y;
            }
            if (bias) {
                float bx = bias[n0], by = bias[n0 + 1];
                v0.x += bx; v0.y += by; v1.x += bx; v1.y += by;
            }
            if (ACT == 1) {
                v0.x = fmaxf(v0.x, 0.f); v0.y = fmaxf(v0.y, 0.f);
                v1.x = fmaxf(v1.x, 0.f); v1.y = fmaxf(v1.y, 0.f);
            } else if (ACT == 2) {
                v0.x = 1.f / (1.f + expf(-v0.x)); v0.y = 1.f / (1.f + expf(-v0.y));
                v1.x = 1.f / (1.f + expf(-v1.x)); v1.y = 1.f / (1.f + expf(-v1.y));
            }
            if (OUT == 0) {
                *reinterpret_cast<float2*>(Cf + (size_t)m0 * N + n0) = v0;
                *reinterpret_cast<float2*>(Cf + (size_t)(m0 + 8) * N + n0) = v1;
            } else {
                float h0, l0, h1, l1;
                split2(v0.x, h0, l0); split2(v0.y, h1, l1);
                *reinterpret_cast<uint32_t*>(Oh + (size_t)m0 * N + n0) = pack_bf16(h0, h1);
                *reinterpret_cast<uint32_t*>(Ol + (size_t)m0 * N + n0) = pack_bf16(l0, l1);
                split2(v1.x, h0, l0); split2(v1.y, h1, l1);
                *reinterpret_cast<uint32_t*>(Oh + (size_t)(m0 + 8) * N + n0) = pack_bf16(h0, h1);
                *reinterpret_cast<uint32_t*>(Ol + (size_t)(m0 + 8) * N + n0) = pack_bf16(l0, l1);
            }
        }
    }
}

// ---------------- orchestration ----------------
extern "C" void kernel_launch(void* const* d_in, const int* in_sizes, int n_in,
                              void* d_out, int out_size) {
    const float* hM  = (const float*)d_in[0];
    const float* hD  = (const float*)d_in[1];
    const float* hT  = (const float*)d_in[2];
    const float* W1  = (const float*)d_in[3];
    const float* b1  = (const float*)d_in[4];
    const float* W2  = (const float*)d_in[5];
    const float* b2  = (const float*)d_in[6];
    const float* W3  = (const float*)d_in[7];
    const float* b3  = (const float*)d_in[8];
    const float* Adj = (const float*)d_in[9];
    const float* f1w = (const float*)d_in[10];
    const float* f1b = (const float*)d_in[11];
    const float* f2w = (const float*)d_in[12];
    const float* f2b = (const float*)d_in[13];
    const float* f3w = (const float*)d_in[14];
    const float* f3b = (const float*)d_in[15];
    const float* f4w = (const float*)d_in[16];
    const float* f4b = (const float*)d_in[17];
    const int* edges = (const int*)d_in[18];

    float *p_node, *p_x1, *p_agg, *p_outinv, *p_ininv;
    __nv_bfloat16 *p_bth, *p_btl, *p_adjh, *p_feh, *p_fel;
    __nv_bfloat16 *p_x1h, *p_x1l, *p_x2h, *p_x2l, *p_x3h, *p_x3l;
    cudaGetSymbolAddress((void**)&p_node, g_node);
    cudaGetSymbolAddress((void**)&p_x1, g_x1);
    cudaGetSymbolAddress((void**)&p_agg, g_agg);
    cudaGetSymbolAddress((void**)&p_outinv, g_outinv);
    cudaGetSymbolAddress((void**)&p_ininv, g_ininv);
    cudaGetSymbolAddress((void**)&p_bth, g_bth);
    cudaGetSymbolAddress((void**)&p_btl, g_btl);
    cudaGetSymbolAddress((void**)&p_adjh, g_adjh);
    cudaGetSymbolAddress((void**)&p_feh, g_feh);
    cudaGetSymbolAddress((void**)&p_fel, g_fel);
    cudaGetSymbolAddress((void**)&p_x1h, g_x1h);
    cudaGetSymbolAddress((void**)&p_x1l, g_x1l);
    cudaGetSymbolAddress((void**)&p_x2h, g_x2h);
    cudaGetSymbolAddress((void**)&p_x2l, g_x2l);
    cudaGetSymbolAddress((void**)&p_x3h, g_x3h);
    cudaGetSymbolAddress((void**)&p_x3l, g_x3l);

    float* fe   = (float*)d_out;                       // 4096 x 128
    float* outx = (float*)d_out + (size_t)MROW * OUTD; // 4096 x 8192

    cudaFuncSetAttribute(k_tc<2, 0, 0, false>, cudaFuncAttributeMaxDynamicSharedMemorySize, TC_SMEM);
    cudaFuncSetAttribute(k_tc<3, 1, 1, true >, cudaFuncAttributeMaxDynamicSharedMemorySize, TC_SMEM);
    cudaFuncSetAttribute(k_tc<3, 1, 1, false>, cudaFuncAttributeMaxDynamicSharedMemorySize, TC_SMEM);
    cudaFuncSetAttribute(k_tc<3, 2, 0, false>, cudaFuncAttributeMaxDynamicSharedMemorySize, TC_SMEM);

    // operand prep (independent of GNN stages)
    k_cvt<<<(MROW * ITEM / 4) / 256, 256>>>((const float4*)Adj, p_adjh);
    k_tsp<<<dim3(256 / 32, 8192 / 32), dim3(32, 8)>>>(f1w, p_bth + O1A, p_btl + O1A, 8192, 256);
    k_tsp<<<dim3(256 / 32, 128 / 32),  dim3(32, 8)>>>(f1w + (size_t)ITEM * 256, p_bth + O1B, p_btl + O1B, 128, 256);
    k_tsp<<<dim3(512 / 32, 256 / 32),  dim3(32, 8)>>>(f2w, p_bth + O2, p_btl + O2, 256, 512);
    k_tsp<<<dim3(1024 / 32, 512 / 32), dim3(32, 8)>>>(f3w, p_bth + O3, p_btl + O3, 512, 1024);
    k_tsp<<<dim3(8192 / 32, 1024 / 32), dim3(32, 8)>>>(f4w, p_bth + O4, p_btl + O4, 1024, 8192);

    // CSR + degrees
    k_zero_counts<<<(NREL * NN + 255) / 256, 256>>>();
    k_count<<<(NREL * NE / 4 + 255) / 256, 256>>>(edges);
    k_scan<<<NREL, 1024>>>();
    k_fill<<<(NREL * NE / 4 + 255) / 256, 256>>>(edges);

    // layer 1: FEAT=256 -> 64, then gather at 64
    k_conv_b<<<dim3(1, NN / 64, 6), 256>>>(hM, hD, hT, W1, p_outinv, 256, 64);
    k_agg_v<<<dim3(NN / 8, 3), dim3(16, 8)>>>(b1);

    // layer 2: 64 -> 64, then gather at 64
    k_conv_b<<<dim3(1, NN / 64, 6), 256>>>(p_node, p_node + (size_t)NN * 128,
                                           p_node + (size_t)2 * NN * 128, W2, p_outinv, 64, 64);
    k_agg_v<<<dim3(NN / 8, 3), dim3(16, 8)>>>(b2);

    // layer 3: pre-aggregate at 64, then GEMM 64->128 (ind-scale in GEMM), combine
    k_aggpre<<<dim3(NN / 8, 6), dim3(16, 8)>>>();
    k_conv_b<<<dim3(2, NN / 64, 6), 256>>>(p_agg, nullptr, nullptr, W3, p_ininv, 64, 128);
    k_addb<<<dim3(NN * 128 / 4 / 256, 3), 256>>>(b3);

    // fake_embeding = L1-normalized hM3[0:4096] -> d_out (+ bf16 hi/lo)
    k_l1norm<<<MROW, 128>>>(fe, p_feh, p_fel);

    // MLP decoder
    k_tc<2, 0, 0, false><<<dim3(2, 32), 256, TC_SMEM>>>(
        p_adjh, p_adjh, p_bth + O1A, p_btl + O1A, nullptr, nullptr,
        p_x1, nullptr, nullptr, 256, 8192);
    k_tc<3, 1, 1, true><<<dim3(2, 32), 256, TC_SMEM>>>(
        p_feh, p_fel, p_bth + O1B, p_btl + O1B, f1b, p_x1,
        nullptr, p_x1h, p_x1l, 256, 128);
    k_tc<3, 1, 1, false><<<dim3(4, 32), 256, TC_SMEM>>>(
        p_x1h, p_x1l, p_bth + O2, p_btl + O2, f2b, nullptr,
        nullptr, p_x2h, p_x2l, 512, 256);
    k_tc<3, 1, 1, false><<<dim3(8, 32), 256, TC_SMEM>>>(
        p_x2h, p_x2l, p_bth + O3, p_btl + O3, f3b, nullptr,
        nullptr, p_x3h, p_x3l, 1024, 512);
    k_tc<3, 2, 0, false><<<dim3(64, 32), 256, TC_SMEM>>>(
        p_x3h, p_x3l, p_bth + O4, p_btl + O4, f4b, nullptr,
        outx, nullptr, nullptr, 8192, 1024);
}

// round 7
// speedup vs baseline: 3.7895x; 1.1272x over previous
#include <cuda_runtime.h>
#include <cuda_fp16.h>
#include <stdint.h>
#include <math.h>

#define NN   8192
#define NE   500000
#define NREL 6
#define FEAT 256
#define HIDD 64
#define OUTD 128
#define MROW 4096   // SIZE
#define ITEM 8192
#define KCAT 8320   // ITEM + OUTD

// ---------------- scratch (device globals: allocation-free) ----------------
__device__ int   g_outcnt[NREL][NN];
__device__ int   g_incnt [NREL][NN];
__device__ float g_outinv[NREL][NN];
__device__ float g_ininv [NREL][NN];
__device__ int   g_rowptr[NREL][NN + 1];
__device__ int   g_fill  [NREL][NN];
__device__ int   g_srcs  [NREL][NE];
__device__ float g_xs    [NREL][NN * 128];
__device__ float g_agg   [NREL][NN * 64];   // layer-3 pre-aggregated inputs
__device__ float g_node  [3][NN * 128];     // M, D, T

// pre-transposed fp16 hi/lo weights: Bt[n][k] per matrix, offsets below
#define O1  0                            // f1w^T     [256][8320]
#define O2  2129920                      // f2w^T     [512][256]
#define O3  2260992                      // f3w^T     [1024][512]
#define O4  2785280                      // f4w^T     [8192][1024]
#define BT_TOTAL 11173888
__device__ __half g_bth[BT_TOTAL];
__device__ __half g_btl[BT_TOTAL];

// fp16 activations: concatenated [Adj | fe] + layer outputs
__device__ __half g_adjcat[(size_t)MROW * KCAT];
__device__ __half g_x1h[MROW * 256];
__device__ __half g_x2h[MROW * 512];
__device__ __half g_x3h[MROW * 1024];

// ---------------- CSR build ----------------
__global__ void k_zero_counts() {
    int i = blockIdx.x * blockDim.x + threadIdx.x;
    if (i < NREL * NN) {
        ((int*)g_outcnt)[i] = 0;
        ((int*)g_incnt)[i]  = 0;
    }
}

__global__ void k_count(const int* __restrict__ edges) {
    int i = (blockIdx.x * blockDim.x + threadIdx.x) * 4;
    if (i >= NREL * NE) return;
    int r = i / NE, e = i - r * NE;
    int4 src = *reinterpret_cast<const int4*>(edges + (size_t)r * 2 * NE + e);
    int4 dst = *reinterpret_cast<const int4*>(edges + (size_t)r * 2 * NE + NE + e);
    atomicAdd(&g_outcnt[r][src.x], 1);
    atomicAdd(&g_outcnt[r][src.y], 1);
    atomicAdd(&g_outcnt[r][src.z], 1);
    atomicAdd(&g_outcnt[r][src.w], 1);
    atomicAdd(&g_incnt[r][dst.x], 1);
    atomicAdd(&g_incnt[r][dst.y], 1);
    atomicAdd(&g_incnt[r][dst.z], 1);
    atomicAdd(&g_incnt[r][dst.w], 1);
}

__global__ void k_scan() {
    int r = blockIdx.x;
    int tid = threadIdx.x;          // 1024 threads
    int base = tid * 8;
    int c[8];
    int s = 0;
#pragma unroll
    for (int i = 0; i < 8; i++) { c[i] = g_incnt[r][base + i]; s += c[i]; }

    int lane = tid & 31, w = tid >> 5;
    int incl = s;
#pragma unroll
    for (int o = 1; o < 32; o <<= 1) {
        int v = __shfl_up_sync(0xffffffffu, incl, o);
        if (lane >= o) incl += v;
    }
    __shared__ int wsum[32];
    if (lane == 31) wsum[w] = incl;
    __syncthreads();
    if (w == 0) {
        int v = wsum[lane];
#pragma unroll
        for (int o = 1; o < 32; o <<= 1) {
            int t = __shfl_up_sync(0xffffffffu, v, o);
            if (lane >= o) v += t;
        }
        wsum[lane] = v;
    }
    __syncthreads();
    int excl = (incl - s) + (w > 0 ? wsum[w - 1] : 0);
    int run = excl;
#pragma unroll
    for (int i = 0; i < 8; i++) {
        g_rowptr[r][base + i] = run;
        g_fill[r][base + i]   = run;
        run += c[i];
        int ic = c[i] > 0 ? c[i] : 1;
        g_ininv[r][base + i] = rsqrtf((float)ic);
        int oc = g_outcnt[r][base + i];
        if (oc < 1) oc = 1;
        g_outinv[r][base + i] = rsqrtf((float)oc);
    }
    if (tid == 1023) g_rowptr[r][NN] = run;
}

__global__ void k_fill(const int* __restrict__ edges) {
    int i = (blockIdx.x * blockDim.x + threadIdx.x) * 4;
    if (i >= NREL * NE) return;
    int r = i / NE, e = i - r * NE;
    int4 src = *reinterpret_cast<const int4*>(edges + (size_t)r * 2 * NE + e);
    int4 dst = *reinterpret_cast<const int4*>(edges + (size_t)r * 2 * NE + NE + e);
    g_srcs[r][atomicAdd(&g_fill[r][dst.x], 1)] = src.x;
    g_srcs[r][atomicAdd(&g_fill[r][dst.y], 1)] = src.y;
    g_srcs[r][atomicAdd(&g_fill[r][dst.z], 1)] = src.z;
    g_srcs[r][atomicAdd(&g_fill[r][dst.w], 1)] = src.w;
}

// ---------------- conv GEMM batched over relations (gridDim.z = 6) --------
__global__ void k_conv_b(const float* __restrict__ A0, const float* __restrict__ A1,
                         const float* __restrict__ A2, const float* __restrict__ Wb,
                         const float* __restrict__ scaleb, int K, int Nh) {
    const int r = blockIdx.z;
    const int smap[6] = {0, 1, 0, 2, 2, 1};
    const float* A;
    if (A1 == nullptr) {
        A = A0 + (size_t)r * NN * K;
    } else {
        int si = smap[r];
        A = (si == 0) ? A0 : (si == 1) ? A1 : A2;
    }
    const float* W = Wb + (size_t)r * K * Nh;
    float* Xs = g_xs[r];
    const float* scale = scaleb + r * NN;

    __shared__ float As[16][64];
    __shared__ float Bs[16][64];
    int tid = threadIdx.x;
    int bx = blockIdx.x, by = blockIdx.y;
    int aRow = tid >> 2, aCol = (tid & 3) * 4;
    int bRow = tid >> 4, bCol = (tid & 15) * 4;
    int tx = tid & 15, ty = tid >> 4;
    float acc[4][4] = {};
    const float* Ap = A + (size_t)(by * 64) * K;
    float scl = scale[by * 64 + aRow];

    for (int k0 = 0; k0 < K; k0 += 16) {
        float4 av = *(const float4*)(Ap + (size_t)aRow * K + k0 + aCol);
        As[aCol + 0][aRow] = av.x * scl;
        As[aCol + 1][aRow] = av.y * scl;
        As[aCol + 2][aRow] = av.z * scl;
        As[aCol + 3][aRow] = av.w * scl;
        float4 bv = *(const float4*)(W + (size_t)(k0 + bRow) * Nh + bx * 64 + bCol);
        *(float4*)&Bs[bRow][bCol] = bv;
        __syncthreads();
#pragma unroll
        for (int kk = 0; kk < 16; kk++) {
            float a[4], b[4];
#pragma unroll
            for (int i = 0; i < 4; i++) a[i] = As[kk][ty * 4 + i];
#pragma unroll
            for (int j = 0; j < 4; j++) b[j] = Bs[kk][tx * 4 + j];
#pragma unroll
            for (int i = 0; i < 4; i++)
#pragma unroll
                for (int j = 0; j < 4; j++) acc[i][j] += a[i] * b[j];
        }
        __syncthreads();
    }
    int row0 = by * 64 + ty * 4, col0 = bx * 64 + tx * 4;
#pragma unroll
    for (int i = 0; i < 4; i++)
#pragma unroll
        for (int j = 0; j < 4; j++)
            Xs[(size_t)(row0 + i) * Nh + col0 + j] = acc[i][j];
}

// ---------------- aggregation helpers ----------------
__device__ __forceinline__ float4 f4add(float4 a, float4 b) {
    a.x += b.x; a.y += b.y; a.z += b.z; a.w += b.w; return a;
}
__device__ __forceinline__ float4 f4fma(float4 a, float s, float4 acc) {
    acc.x += a.x * s; acc.y += a.y * s; acc.z += a.z * s; acc.w += a.w * s; return acc;
}

// post-GEMM agg (layers 1,2): newnode[t] = (Σ xs)·ind + biases, HID=64
__global__ void k_agg_v(const float* __restrict__ bias) {
    const int t = blockIdx.y;
    const int n = blockIdx.x * blockDim.y + threadIdx.y;
    const int lane = threadIdx.x;     // 0..15
    const int RA[3] = {1, 0, 2};
    const int RB[3] = {3, 4, 5};
    int rel[2] = {RA[t], RB[t]};
    float4 acc = f4add(reinterpret_cast<const float4*>(bias + rel[0] * 64)[lane],
                       reinterpret_cast<const float4*>(bias + rel[1] * 64)[lane]);
#pragma unroll
    for (int rr = 0; rr < 2; rr++) {
        int r = rel[rr];
        int e0 = g_rowptr[r][n], e1 = g_rowptr[r][n + 1];
        const float* xs = g_xs[r];
        const int* srcs = g_srcs[r];
        float4 s = make_float4(0.f, 0.f, 0.f, 0.f);
        int e = e0;
        for (; e + 7 < e1; e += 8) {
            float4 v0 = reinterpret_cast<const float4*>(xs + (size_t)srcs[e] * 64)[lane];
            float4 v1 = reinterpret_cast<const float4*>(xs + (size_t)srcs[e + 1] * 64)[lane];
            float4 v2 = reinterpret_cast<const float4*>(xs + (size_t)srcs[e + 2] * 64)[lane];
            float4 v3 = reinterpret_cast<const float4*>(xs + (size_t)srcs[e + 3] * 64)[lane];
            float4 v4 = reinterpret_cast<const float4*>(xs + (size_t)srcs[e + 4] * 64)[lane];
            float4 v5 = reinterpret_cast<const float4*>(xs + (size_t)srcs[e + 5] * 64)[lane];
            float4 v6 = reinterpret_cast<const float4*>(xs + (size_t)srcs[e + 6] * 64)[lane];
            float4 v7 = reinterpret_cast<const float4*>(xs + (size_t)srcs[e + 7] * 64)[lane];
            s = f4add(s, f4add(f4add(f4add(v0, v1), f4add(v2, v3)),
                               f4add(f4add(v4, v5), f4add(v6, v7))));
        }
        for (; e < e1; e++)
            s = f4add(s, reinterpret_cast<const float4*>(xs + (size_t)srcs[e] * 64)[lane]);
        acc = f4fma(s, g_ininv[r][n], acc);
    }
    reinterpret_cast<float4*>(g_node[t] + (size_t)n * 64)[lane] = acc;
}

// pre-GEMM agg (layer 3): g_agg[r][n] = Σ_{src} node[smap[r]][src]·outinv_r[src]
__global__ void k_aggpre() {
    const int r = blockIdx.y;
    const int n = blockIdx.x * blockDim.y + threadIdx.y;
    const int lane = threadIdx.x;     // 0..15
    const int smap[6] = {0, 1, 0, 2, 2, 1};
    const float* x = g_node[smap[r]];
    const float* oi = g_outinv[r];
    const int* srcs = g_srcs[r];
    int e0 = g_rowptr[r][n], e1 = g_rowptr[r][n + 1];
    float4 acc = make_float4(0.f, 0.f, 0.f, 0.f);
    int e = e0;
    for (; e + 3 < e1; e += 4) {
        int s0 = srcs[e], s1 = srcs[e + 1], s2 = srcs[e + 2], s3 = srcs[e + 3];
        float4 v0 = reinterpret_cast<const float4*>(x + (size_t)s0 * 64)[lane];
        float4 v1 = reinterpret_cast<const float4*>(x + (size_t)s1 * 64)[lane];
        float4 v2 = reinterpret_cast<const float4*>(x + (size_t)s2 * 64)[lane];
        float4 v3 = reinterpret_cast<const float4*>(x + (size_t)s3 * 64)[lane];
        acc = f4fma(v0, oi[s0], acc);
        acc = f4fma(v1, oi[s1], acc);
        acc = f4fma(v2, oi[s2], acc);
        acc = f4fma(v3, oi[s3], acc);
    }
    for (; e < e1; e++) {
        int s0 = srcs[e];
        float4 v0 = reinterpret_cast<const float4*>(x + (size_t)s0 * 64)[lane];
        acc = f4fma(v0, oi[s0], acc);
    }
    reinterpret_cast<float4*>(g_agg[r] + (size_t)n * 64)[lane] = acc;
}

// layer-3 combine: node[t] = xs[ra] + xs[rb] + b[ra] + b[rb]  (stride 128)
__global__ void k_addb(const float* __restrict__ bias) {
    const int t = blockIdx.y;
    const int RA[3] = {1, 0, 2};
    const int RB[3] = {3, 4, 5};
    int ra = RA[t], rb = RB[t];
    int i = blockIdx.x * blockDim.x + threadIdx.x;   // over NN*128/4
    int h = (i & 31);                                 // float4 col index
    float4 a = reinterpret_cast<const float4*>(g_xs[ra])[i];
    float4 b = reinterpret_cast<const float4*>(g_xs[rb])[i];
    float4 ba = reinterpret_cast<const float4*>(bias + ra * 128)[h];
    float4 bb = reinterpret_cast<const float4*>(bias + rb * 128)[h];
    float4 o;
    o.x = a.x + b.x + ba.x + bb.x;
    o.y = a.y + b.y + ba.y + bb.y;
    o.z = a.z + b.z + ba.z + bb.z;
    o.w = a.w + b.w + ba.w + bb.w;
    reinterpret_cast<float4*>(g_node[t])[i] = o;
}

// ---------------- fp16 helpers ----------------
__device__ __forceinline__ uint32_t pack_h2(float x, float y) {
    __half2 h = __floats2half2_rn(x, y);
    return *reinterpret_cast<uint32_t*>(&h);
}
__device__ __forceinline__ void split2h(float x, __half& hi, __half& lo) {
    hi = __float2half_rn(x);
    lo = __float2half_rn(x - __half2float(hi));
}

// ---------------- row L1-normalize hM3[0:4096] -> fe (f32) + adjcat fp16 ---
__global__ void k_l1norm(float* __restrict__ out, __half* __restrict__ adjcat) {
    int row = blockIdx.x;
    int h = threadIdx.x;  // 128
    float v = g_node[0][(size_t)row * OUTD + h];
    float a = fabsf(v);
#pragma unroll
    for (int o = 16; o > 0; o >>= 1) a += __shfl_xor_sync(0xffffffffu, a, o);
    __shared__ float sh[4];
    if ((h & 31) == 0) sh[h >> 5] = a;
    __syncthreads();
    float tot = sh[0] + sh[1] + sh[2] + sh[3];
    float r = v / fmaxf(tot, 1e-12f);
    out[(size_t)row * OUTD + h] = r;
    adjcat[(size_t)row * KCAT + ITEM + h] = __float2half_rn(r);
}

// ---------------- Adj fp32 -> fp16 into adjcat (stride KCAT) ---------------
__global__ void k_cvt(const float4* __restrict__ src, __half* __restrict__ dst) {
    size_t i = (size_t)blockIdx.x * blockDim.x + threadIdx.x;  // float4 index
    float4 v = src[i];
    size_t row = i >> 11;          // 2048 float4 per 8192-col row
    int col = (int)(i & 2047) * 4;
    uint2 p = make_uint2(pack_h2(v.x, v.y), pack_h2(v.z, v.w));
    *reinterpret_cast<uint2*>(dst + row * KCAT + col) = p;
}

// ---------------- weight transpose + fp16 hi/lo split: B[K][N] -> Bt[N][K] -
__global__ void k_tsp(const float* __restrict__ B, __half* __restrict__ th,
                      __half* __restrict__ tl, int K, int N) {
    __shared__ float s[32][33];
    int n0 = blockIdx.x * 32, k0 = blockIdx.y * 32;
    int tx = threadIdx.x, ty = threadIdx.y;
#pragma unroll
    for (int i = 0; i < 32; i += 8)
        s[ty + i][tx] = B[(size_t)(k0 + ty + i) * N + n0 + tx];
    __syncthreads();
#pragma unroll
    for (int i = 0; i < 32; i += 8) {
        int n = n0 + ty + i, k = k0 + tx;
        __half h, l;
        split2h(s[tx][ty + i], h, l);
        th[(size_t)n * K + k] = h;
        tl[(size_t)n * K + k] = l;
    }
}

// ---------------- mma.sync + ldmatrix + cp.async plumbing ------------------
__device__ __forceinline__ uint32_t s2u(const void* p) {
    uint32_t a;
    asm("{ .reg .u64 t; cvta.to.shared.u64 t, %1; cvt.u32.u64 %0, t; }" : "=r"(a) : "l"(p));
    return a;
}
__device__ __forceinline__ void mma_f16(float* d, const uint32_t* a, const uint32_t* b) {
    asm volatile(
        "mma.sync.aligned.m16n8k16.row.col.f32.f16.f16.f32 "
        "{%0,%1,%2,%3}, {%4,%5,%6,%7}, {%8,%9}, {%0,%1,%2,%3};"
        : "+f"(d[0]), "+f"(d[1]), "+f"(d[2]), "+f"(d[3])
        : "r"(a[0]), "r"(a[1]), "r"(a[2]), "r"(a[3]), "r"(b[0]), "r"(b[1]));
}
__device__ __forceinline__ void ldsm4(uint32_t* r, uint32_t addr) {
    asm volatile("ldmatrix.sync.aligned.m8n8.x4.shared.b16 {%0,%1,%2,%3}, [%4];"
                 : "=r"(r[0]), "=r"(r[1]), "=r"(r[2]), "=r"(r[3]) : "r"(addr));
}
__device__ __forceinline__ void cpa16(uint32_t s, const void* g) {
    asm volatile("cp.async.cg.shared.global [%0], [%1], 16;" :: "r"(s), "l"(g));
}
#define CP_COMMIT() asm volatile("cp.async.commit_group;" ::: "memory")
#define CP_WAIT2()  asm volatile("cp.async.wait_group 2;" ::: "memory")

// ---------------- MLP GEMM: A fp16, B fp16 hi/lo (2-pass) ------------------
// C = act(A @ (Bh+Bl)^T + bias); A [M][K] fp16 row-major, B [N][K] fp16.
// BM=BN=128, BK=64, 256 threads (8 warps 4m x 2n), 3-stage cp.async.
// OUT: 0 = fp32 to Cf; 1 = fp16 to Oh.
#define TC_STAGE 49152u                // A 16KB, Bh 16KB, Bl 16KB
#define TC_SMEM  (3 * TC_STAGE)

template <int ACT, int OUT>
__global__ void __launch_bounds__(256, 1)
k_tc(const __half* __restrict__ A_, const __half* __restrict__ Bh_,
     const __half* __restrict__ Bl_, const float* __restrict__ bias,
     float* __restrict__ Cf, __half* __restrict__ Oh, int N, int K) {
    extern __shared__ char smc[];
    const uint32_t sb = s2u(smc);
    const int tid = threadIdx.x, lane = tid & 31, warp = tid >> 5;
    const int wm = warp & 3, wn = warp >> 2;
    const int g = lane >> 2, tig = lane & 3;
    const int bm = blockIdx.y * 128, bn = blockIdx.x * 128;

    float c[2][8][4];
#pragma unroll
    for (int i = 0; i < 2; i++)
#pragma unroll
        for (int j = 0; j < 8; j++)
#pragma unroll
            for (int q = 0; q < 4; q++) c[i][j][q] = 0.f;

    auto load_stage = [&](int s) {
        const uint32_t st = sb + (uint32_t)(s % 3) * TC_STAGE;
        const int k0 = s * 64;
#pragma unroll
        for (int j = 0; j < 4; j++) {
            int cidx = tid + 256 * j;
            int row = cidx >> 3, kc = cidx & 7;
            uint32_t off = (uint32_t)(row * 128 + kc * 16);
            off ^= (off >> 3) & 0x70;
            size_t ga = (size_t)(bm + row) * K + k0 + kc * 8;
            size_t gb = (size_t)(bn + row) * K + k0 + kc * 8;
            cpa16(st + off, A_ + ga);
            cpa16(st + 16384 + off, Bh_ + gb);
            cpa16(st + 32768 + off, Bl_ + gb);
        }
    };

    const int nst = K >> 6;
#pragma unroll
    for (int i = 0; i < 3; i++) {
        if (i < nst) load_stage(i);
        CP_COMMIT();
    }

    for (int s = 0; s < nst; s++) {
        CP_WAIT2();
        __syncthreads();
        const uint32_t st = sb + (uint32_t)(s % 3) * TC_STAGE;
#pragma unroll
        for (int kk = 0; kk < 64; kk += 16) {
            uint32_t ah[2][4], bh[8][2], bl[8][2];
#pragma unroll
            for (int mt = 0; mt < 2; mt++) {
                int row = wm * 32 + mt * 16 + (lane & 15);
                uint32_t off = (uint32_t)(row * 128) + (uint32_t)(kk * 2) + (uint32_t)(lane & 16);
                off ^= (off >> 3) & 0x70;
                ldsm4(ah[mt], st + off);
            }
#pragma unroll
            for (int bt = 0; bt < 4; bt++) {
                int row = wn * 64 + bt * 16 + ((lane >> 4) << 3) + (lane & 7);
                uint32_t off = (uint32_t)(row * 128) + (uint32_t)(kk * 2) + (uint32_t)((lane & 8) << 1);
                off ^= (off >> 3) & 0x70;
                uint32_t r[4];
                ldsm4(r, st + 16384 + off);
                bh[2 * bt][0] = r[0]; bh[2 * bt][1] = r[1];
                bh[2 * bt + 1][0] = r[2]; bh[2 * bt + 1][1] = r[3];
                ldsm4(r, st + 32768 + off);
                bl[2 * bt][0] = r[0]; bl[2 * bt][1] = r[1];
                bl[2 * bt + 1][0] = r[2]; bl[2 * bt + 1][1] = r[3];
            }
#pragma unroll
            for (int mt = 0; mt < 2; mt++)
#pragma unroll
                for (int nt = 0; nt < 8; nt++) {
                    mma_f16(c[mt][nt], ah[mt], bh[nt]);
                    mma_f16(c[mt][nt], ah[mt], bl[nt]);
                }
        }
        __syncthreads();
        if (s + 3 < nst) load_stage(s + 3);
        CP_COMMIT();
    }

    // epilogue
#pragma unroll
    for (int mt = 0; mt < 2; mt++) {
#pragma unroll
        for (int nt = 0; nt < 8; nt++) {
            int m0 = bm + wm * 32 + mt * 16 + g;
            int n0 = bn + wn * 64 + nt * 8 + 2 * tig;
            float2 v0 = make_float2(c[mt][nt][0], c[mt][nt][1]);
            float2 v1 = make_float2(c[mt][nt][2], c[mt][nt][3]);
            if (bias) {
                float bx = bias[n0], by = bias[n0 + 1];
                v0.x += bx; v0.y += by; v1.x += bx; v1.y += by;
            }
            if (ACT == 1) {
                v0.x = fmaxf(v0.x, 0.f); v0.y = fmaxf(v0.y, 0.f);
                v1.x = fmaxf(v1.x, 0.f); v1.y = fmaxf(v1.y, 0.f);
            } else if (ACT == 2) {
                v0.x = 1.f / (1.f + expf(-v0.x)); v0.y = 1.f / (1.f + expf(-v0.y));
                v1.x = 1.f / (1.f + expf(-v1.x)); v1.y = 1.f / (1.f + expf(-v1.y));
            }
            if (OUT == 0) {
                *reinterpret_cast<float2*>(Cf + (size_t)m0 * N + n0) = v0;
                *reinterpret_cast<float2*>(Cf + (size_t)(m0 + 8) * N + n0) = v1;
            } else {
                *reinterpret_cast<uint32_t*>(Oh + (size_t)m0 * N + n0) = pack_h2(v0.x, v0.y);
                *reinterpret_cast<uint32_t*>(Oh + (size_t)(m0 + 8) * N + n0) = pack_h2(v1.x, v1.y);
            }
        }
    }
}

// ---------------- orchestration ----------------
extern "C" void kernel_launch(void* const* d_in, const int* in_sizes, int n_in,
                              void* d_out, int out_size) {
    const float* hM  = (const float*)d_in[0];
    const float* hD  = (const float*)d_in[1];
    const float* hT  = (const float*)d_in[2];
    const float* W1  = (const float*)d_in[3];
    const float* b1  = (const float*)d_in[4];
    const float* W2  = (const float*)d_in[5];
    const float* b2  = (const float*)d_in[6];
    const float* W3  = (const float*)d_in[7];
    const float* b3  = (const float*)d_in[8];
    const float* Adj = (const float*)d_in[9];
    const float* f1w = (const float*)d_in[10];
    const float* f1b = (const float*)d_in[11];
    const float* f2w = (const float*)d_in[12];
    const float* f2b = (const float*)d_in[13];
    const float* f3w = (const float*)d_in[14];
    const float* f3b = (const float*)d_in[15];
    const float* f4w = (const float*)d_in[16];
    const float* f4b = (const float*)d_in[17];
    const int* edges = (const int*)d_in[18];

    float *p_node, *p_agg, *p_outinv, *p_ininv;
    __half *p_bth, *p_btl, *p_adjcat, *p_x1h, *p_x2h, *p_x3h;
    cudaGetSymbolAddress((void**)&p_node, g_node);
    cudaGetSymbolAddress((void**)&p_agg, g_agg);
    cudaGetSymbolAddress((void**)&p_outinv, g_outinv);
    cudaGetSymbolAddress((void**)&p_ininv, g_ininv);
    cudaGetSymbolAddress((void**)&p_bth, g_bth);
    cudaGetSymbolAddress((void**)&p_btl, g_btl);
    cudaGetSymbolAddress((void**)&p_adjcat, g_adjcat);
    cudaGetSymbolAddress((void**)&p_x1h, g_x1h);
    cudaGetSymbolAddress((void**)&p_x2h, g_x2h);
    cudaGetSymbolAddress((void**)&p_x3h, g_x3h);

    float* fe   = (float*)d_out;                       // 4096 x 128
    float* outx = (float*)d_out + (size_t)MROW * OUTD; // 4096 x 8192

    cudaFuncSetAttribute(k_tc<1, 1>, cudaFuncAttributeMaxDynamicSharedMemorySize, TC_SMEM);
    cudaFuncSetAttribute(k_tc<2, 0>, cudaFuncAttributeMaxDynamicSharedMemorySize, TC_SMEM);

    // operand prep (independent of GNN stages)
    k_cvt<<<(MROW * ITEM / 4) / 256, 256>>>((const float4*)Adj, p_adjcat);
    k_tsp<<<dim3(256 / 32, KCAT / 32), dim3(32, 8)>>>(f1w, p_bth + O1, p_btl + O1, KCAT, 256);
    k_tsp<<<dim3(512 / 32, 256 / 32),  dim3(32, 8)>>>(f2w, p_bth + O2, p_btl + O2, 256, 512);
    k_tsp<<<dim3(1024 / 32, 512 / 32), dim3(32, 8)>>>(f3w, p_bth + O3, p_btl + O3, 512, 1024);
    k_tsp<<<dim3(8192 / 32, 1024 / 32), dim3(32, 8)>>>(f4w, p_bth + O4, p_btl + O4, 1024, 8192);

    // CSR + degrees
    k_zero_counts<<<(NREL * NN + 255) / 256, 256>>>();
    k_count<<<(NREL * NE / 4 + 255) / 256, 256>>>(edges);
    k_scan<<<NREL, 1024>>>();
    k_fill<<<(NREL * NE / 4 + 255) / 256, 256>>>(edges);

    // layer 1: FEAT=256 -> 64, then gather at 64
    k_conv_b<<<dim3(1, NN / 64, 6), 256>>>(hM, hD, hT, W1, p_outinv, 256, 64);
    k_agg_v<<<dim3(NN / 16, 3), dim3(16, 16)>>>(b1);

    // layer 2: 64 -> 64, then gather at 64
    k_conv_b<<<dim3(1, NN / 64, 6), 256>>>(p_node, p_node + (size_t)NN * 128,
                                           p_node + (size_t)2 * NN * 128, W2, p_outinv, 64, 64);
    k_agg_v<<<dim3(NN / 16, 3), dim3(16, 16)>>>(b2);

    // layer 3: pre-aggregate at 64, then GEMM 64->128 (ind-scale in GEMM), combine
    k_aggpre<<<dim3(NN / 16, 6), dim3(16, 16)>>>();
    k_conv_b<<<dim3(2, NN / 64, 6), 256>>>(p_agg, nullptr, nullptr, W3, p_ininv, 64, 128);
    k_addb<<<dim3(NN * 128 / 4 / 256, 3), 256>>>(b3);

    // fake_embeding = L1-normalized hM3[0:4096] -> d_out (+ fp16 into adjcat)
    k_l1norm<<<MROW, 128>>>(fe, p_adjcat);

    // MLP decoder (fp16 A, fp16 hi/lo B, 2-pass)
    // x1 = relu([Adj|fe] @ f1w + f1b)
    k_tc<1, 1><<<dim3(2, 32), 256, TC_SMEM>>>(
        p_adjcat, p_bth + O1, p_btl + O1, f1b, nullptr, p_x1h, 256, KCAT);
    k_tc<1, 1><<<dim3(4, 32), 256, TC_SMEM>>>(
        p_x1h, p_bth + O2, p_btl + O2, f2b, nullptr, p_x2h, 512, 256);
    k_tc<1, 1><<<dim3(8, 32), 256, TC_SMEM>>>(
        p_x2h, p_bth + O3, p_btl + O3, f3b, nullptr, p_x3h, 1024, 512);
    k_tc<2, 0><<<dim3(64, 32), 256, TC_SMEM>>>(
        p_x3h, p_bth + O4, p_btl + O4, f4b, outx, nullptr, 8192, 1024);
}

// round 8
// speedup vs baseline: 4.7859x; 1.2630x over previous
#include <cuda_runtime.h>
#include <cuda_fp16.h>
#include <stdint.h>
#include <math.h>

#define NN   8192
#define NE   500000
#define NREL 6
#define FEAT 256
#define HIDD 64
#define OUTD 128
#define MROW 4096   // SIZE
#define ITEM 8192
#define KCAT 8320   // ITEM + OUTD
#define CB   8      // count blocks per relation

// ---------------- scratch (device globals: allocation-free) ----------------
__device__ int   g_outcnt[NREL][NN];
__device__ int   g_incnt [NREL][NN];
__device__ float g_outinv[NREL][NN];
__device__ float g_ininv [NREL][NN];
__device__ int   g_rowptr[NREL][NN + 1];
__device__ int   g_fill  [NREL][NN];
__device__ int   g_srcs  [NREL][NE];
__device__ float g_xs    [NREL][NN * 128];
__device__ float g_agg   [NREL][NN * 64];   // layer-3 pre-aggregated inputs
__device__ float g_node  [3][NN * 128];     // M, D, T

// pre-transposed fp16 weights: Bt[n][k] per matrix, offsets below
#define O1  0                            // f1w^T     [256][8320]
#define O2  2129920                      // f2w^T     [512][256]
#define O3  2260992                      // f3w^T     [1024][512]
#define O4  2785280                      // f4w^T     [8192][1024]
#define BT_TOTAL 11173888
__device__ __half g_bth[BT_TOTAL];

// fp16 activations: concatenated [Adj | fe] + layer outputs
__device__ __half g_adjcat[(size_t)MROW * KCAT];
__device__ __half g_x1h[MROW * 256];
__device__ __half g_x2h[MROW * 512];
__device__ __half g_x3h[MROW * 1024];

// ---------------- CSR build ----------------
__global__ void k_zero_counts() {
    int i = blockIdx.x * blockDim.x + threadIdx.x;
    if (i < NREL * NN) {
        ((int*)g_outcnt)[i] = 0;
        ((int*)g_incnt)[i]  = 0;
    }
}

// smem-privatized degree histogram: 8 blocks per relation, 64KB smem each
__global__ void k_count(const int* __restrict__ edges) {
    extern __shared__ int smcnt[];            // [2*NN]
    const int r = blockIdx.y, b = blockIdx.x;
    int* so = smcnt;
    int* si = smcnt + NN;
    for (int i = threadIdx.x; i < 2 * NN; i += blockDim.x) smcnt[i] = 0;
    __syncthreads();
    const int per = NE / CB;                  // 62500, %4==0
    const int e0 = b * per;
    const int* es = edges + (size_t)r * 2 * NE;
    for (int e = e0 + threadIdx.x * 4; e < e0 + per; e += blockDim.x * 4) {
        int4 s = *reinterpret_cast<const int4*>(es + e);
        int4 d = *reinterpret_cast<const int4*>(es + NE + e);
        atomicAdd(&so[s.x], 1); atomicAdd(&so[s.y], 1);
        atomicAdd(&so[s.z], 1); atomicAdd(&so[s.w], 1);
        atomicAdd(&si[d.x], 1); atomicAdd(&si[d.y], 1);
        atomicAdd(&si[d.z], 1); atomicAdd(&si[d.w], 1);
    }
    __syncthreads();
    for (int i = threadIdx.x; i < NN; i += blockDim.x) {
        int v = so[i];
        if (v) atomicAdd(&g_outcnt[r][i], v);
        v = si[i];
        if (v) atomicAdd(&g_incnt[r][i], v);
    }
}

__global__ void k_scan() {
    int r = blockIdx.x;
    int tid = threadIdx.x;          // 1024 threads
    int base = tid * 8;
    int c[8];
    int s = 0;
#pragma unroll
    for (int i = 0; i < 8; i++) { c[i] = g_incnt[r][base + i]; s += c[i]; }

    int lane = tid & 31, w = tid >> 5;
    int incl = s;
#pragma unroll
    for (int o = 1; o < 32; o <<= 1) {
        int v = __shfl_up_sync(0xffffffffu, incl, o);
        if (lane >= o) incl += v;
    }
    __shared__ int wsum[32];
    if (lane == 31) wsum[w] = incl;
    __syncthreads();
    if (w == 0) {
        int v = wsum[lane];
#pragma unroll
        for (int o = 1; o < 32; o <<= 1) {
            int t = __shfl_up_sync(0xffffffffu, v, o);
            if (lane >= o) v += t;
        }
        wsum[lane] = v;
    }
    __syncthreads();
    int excl = (incl - s) + (w > 0 ? wsum[w - 1] : 0);
    int run = excl;
#pragma unroll
    for (int i = 0; i < 8; i++) {
        g_rowptr[r][base + i] = run;
        g_fill[r][base + i]   = run;
        run += c[i];
        int ic = c[i] > 0 ? c[i] : 1;
        g_ininv[r][base + i] = rsqrtf((float)ic);
        int oc = g_outcnt[r][base + i];
        if (oc < 1) oc = 1;
        g_outinv[r][base + i] = rsqrtf((float)oc);
    }
    if (tid == 1023) g_rowptr[r][NN] = run;
}

__global__ void k_fill(const int* __restrict__ edges) {
    int i = (blockIdx.x * blockDim.x + threadIdx.x) * 4;
    if (i >= NREL * NE) return;
    int r = i / NE, e = i - r * NE;
    int4 src = *reinterpret_cast<const int4*>(edges + (size_t)r * 2 * NE + e);
    int4 dst = *reinterpret_cast<const int4*>(edges + (size_t)r * 2 * NE + NE + e);
    g_srcs[r][atomicAdd(&g_fill[r][dst.x], 1)] = src.x;
    g_srcs[r][atomicAdd(&g_fill[r][dst.y], 1)] = src.y;
    g_srcs[r][atomicAdd(&g_fill[r][dst.z], 1)] = src.z;
    g_srcs[r][atomicAdd(&g_fill[r][dst.w], 1)] = src.w;
}

// ---------------- conv GEMM batched over relations (gridDim.z = 6) --------
__global__ void k_conv_b(const float* __restrict__ A0, const float* __restrict__ A1,
                         const float* __restrict__ A2, const float* __restrict__ Wb,
                         const float* __restrict__ scaleb, int K, int Nh) {
    const int r = blockIdx.z;
    const int smap[6] = {0, 1, 0, 2, 2, 1};
    const float* A;
    if (A1 == nullptr) {
        A = A0 + (size_t)r * NN * K;
    } else {
        int si = smap[r];
        A = (si == 0) ? A0 : (si == 1) ? A1 : A2;
    }
    const float* W = Wb + (size_t)r * K * Nh;
    float* Xs = g_xs[r];
    const float* scale = scaleb + r * NN;

    __shared__ float As[16][64];
    __shared__ float Bs[16][64];
    int tid = threadIdx.x;
    int bx = blockIdx.x, by = blockIdx.y;
    int aRow = tid >> 2, aCol = (tid & 3) * 4;
    int bRow = tid >> 4, bCol = (tid & 15) * 4;
    int tx = tid & 15, ty = tid >> 4;
    float acc[4][4] = {};
    const float* Ap = A + (size_t)(by * 64) * K;
    float scl = scale[by * 64 + aRow];

    for (int k0 = 0; k0 < K; k0 += 16) {
        float4 av = *(const float4*)(Ap + (size_t)aRow * K + k0 + aCol);
        As[aCol + 0][aRow] = av.x * scl;
        As[aCol + 1][aRow] = av.y * scl;
        As[aCol + 2][aRow] = av.z * scl;
        As[aCol + 3][aRow] = av.w * scl;
        float4 bv = *(const float4*)(W + (size_t)(k0 + bRow) * Nh + bx * 64 + bCol);
        *(float4*)&Bs[bRow][bCol] = bv;
        __syncthreads();
#pragma unroll
        for (int kk = 0; kk < 16; kk++) {
            float a[4], b[4];
#pragma unroll
            for (int i = 0; i < 4; i++) a[i] = As[kk][ty * 4 + i];
#pragma unroll
            for (int j = 0; j < 4; j++) b[j] = Bs[kk][tx * 4 + j];
#pragma unroll
            for (int i = 0; i < 4; i++)
#pragma unroll
                for (int j = 0; j < 4; j++) acc[i][j] += a[i] * b[j];
        }
        __syncthreads();
    }
    int row0 = by * 64 + ty * 4, col0 = bx * 64 + tx * 4;
#pragma unroll
    for (int i = 0; i < 4; i++)
#pragma unroll
        for (int j = 0; j < 4; j++)
            Xs[(size_t)(row0 + i) * Nh + col0 + j] = acc[i][j];
}

// ---------------- aggregation helpers ----------------
__device__ __forceinline__ float4 f4add(float4 a, float4 b) {
    a.x += b.x; a.y += b.y; a.z += b.z; a.w += b.w; return a;
}
__device__ __forceinline__ float4 f4fma(float4 a, float s, float4 acc) {
    acc.x += a.x * s; acc.y += a.y * s; acc.z += a.z * s; acc.w += a.w * s; return acc;
}

// post-GEMM agg (layers 1,2): newnode[t] = (Σ xs)·ind + biases, HID=64
__global__ void k_agg_v(const float* __restrict__ bias) {
    const int t = blockIdx.y;
    const int n = blockIdx.x * blockDim.y + threadIdx.y;
    const int lane = threadIdx.x;     // 0..15
    const int RA[3] = {1, 0, 2};
    const int RB[3] = {3, 4, 5};
    int rel[2] = {RA[t], RB[t]};
    float4 acc = f4add(reinterpret_cast<const float4*>(bias + rel[0] * 64)[lane],
                       reinterpret_cast<const float4*>(bias + rel[1] * 64)[lane]);
#pragma unroll
    for (int rr = 0; rr < 2; rr++) {
        int r = rel[rr];
        int e0 = g_rowptr[r][n], e1 = g_rowptr[r][n + 1];
        const float* xs = g_xs[r];
        const int* srcs = g_srcs[r];
        float4 s = make_float4(0.f, 0.f, 0.f, 0.f);
        int e = e0;
        for (; e + 7 < e1; e += 8) {
            float4 v0 = reinterpret_cast<const float4*>(xs + (size_t)srcs[e] * 64)[lane];
            float4 v1 = reinterpret_cast<const float4*>(xs + (size_t)srcs[e + 1] * 64)[lane];
            float4 v2 = reinterpret_cast<const float4*>(xs + (size_t)srcs[e + 2] * 64)[lane];
            float4 v3 = reinterpret_cast<const float4*>(xs + (size_t)srcs[e + 3] * 64)[lane];
            float4 v4 = reinterpret_cast<const float4*>(xs + (size_t)srcs[e + 4] * 64)[lane];
            float4 v5 = reinterpret_cast<const float4*>(xs + (size_t)srcs[e + 5] * 64)[lane];
            float4 v6 = reinterpret_cast<const float4*>(xs + (size_t)srcs[e + 6] * 64)[lane];
            float4 v7 = reinterpret_cast<const float4*>(xs + (size_t)srcs[e + 7] * 64)[lane];
            s = f4add(s, f4add(f4add(f4add(v0, v1), f4add(v2, v3)),
                               f4add(f4add(v4, v5), f4add(v6, v7))));
        }
        for (; e < e1; e++)
            s = f4add(s, reinterpret_cast<const float4*>(xs + (size_t)srcs[e] * 64)[lane]);
        acc = f4fma(s, g_ininv[r][n], acc);
    }
    reinterpret_cast<float4*>(g_node[t] + (size_t)n * 64)[lane] = acc;
}

// pre-GEMM agg (layer 3): g_agg[r][n] = Σ_{src} node[smap[r]][src]·outinv_r[src]
__global__ void k_aggpre() {
    const int r = blockIdx.y;
    const int n = blockIdx.x * blockDim.y + threadIdx.y;
    const int lane = threadIdx.x;     // 0..15
    const int smap[6] = {0, 1, 0, 2, 2, 1};
    const float* x = g_node[smap[r]];
    const float* oi = g_outinv[r];
    const int* srcs = g_srcs[r];
    int e0 = g_rowptr[r][n], e1 = g_rowptr[r][n + 1];
    float4 acc = make_float4(0.f, 0.f, 0.f, 0.f);
    int e = e0;
    for (; e + 3 < e1; e += 4) {
        int s0 = srcs[e], s1 = srcs[e + 1], s2 = srcs[e + 2], s3 = srcs[e + 3];
        float4 v0 = reinterpret_cast<const float4*>(x + (size_t)s0 * 64)[lane];
        float4 v1 = reinterpret_cast<const float4*>(x + (size_t)s1 * 64)[lane];
        float4 v2 = reinterpret_cast<const float4*>(x + (size_t)s2 * 64)[lane];
        float4 v3 = reinterpret_cast<const float4*>(x + (size_t)s3 * 64)[lane];
        acc = f4fma(v0, oi[s0], acc);
        acc = f4fma(v1, oi[s1], acc);
        acc = f4fma(v2, oi[s2], acc);
        acc = f4fma(v3, oi[s3], acc);
    }
    for (; e < e1; e++) {
        int s0 = srcs[e];
        float4 v0 = reinterpret_cast<const float4*>(x + (size_t)s0 * 64)[lane];
        acc = f4fma(v0, oi[s0], acc);
    }
    reinterpret_cast<float4*>(g_agg[r] + (size_t)n * 64)[lane] = acc;
}

// layer-3 combine: node[t] = xs[ra] + xs[rb] + b[ra] + b[rb]  (stride 128)
__global__ void k_addb(const float* __restrict__ bias) {
    const int t = blockIdx.y;
    const int RA[3] = {1, 0, 2};
    const int RB[3] = {3, 4, 5};
    int ra = RA[t], rb = RB[t];
    int i = blockIdx.x * blockDim.x + threadIdx.x;   // over NN*128/4
    int h = (i & 31);                                 // float4 col index
    float4 a = reinterpret_cast<const float4*>(g_xs[ra])[i];
    float4 b = reinterpret_cast<const float4*>(g_xs[rb])[i];
    float4 ba = reinterpret_cast<const float4*>(bias + ra * 128)[h];
    float4 bb = reinterpret_cast<const float4*>(bias + rb * 128)[h];
    float4 o;
    o.x = a.x + b.x + ba.x + bb.x;
    o.y = a.y + b.y + ba.y + bb.y;
    o.z = a.z + b.z + ba.z + bb.z;
    o.w = a.w + b.w + ba.w + bb.w;
    reinterpret_cast<float4*>(g_node[t])[i] = o;
}

// ---------------- fp16 helpers ----------------
__device__ __forceinline__ uint32_t pack_h2(float x, float y) {
    __half2 h = __floats2half2_rn(x, y);
    return *reinterpret_cast<uint32_t*>(&h);
}

// ---------------- row L1-normalize hM3[0:4096] -> fe (f32) + adjcat fp16 ---
__global__ void k_l1norm(float* __restrict__ out, __half* __restrict__ adjcat) {
    int row = blockIdx.x;
    int h = threadIdx.x;  // 128
    float v = g_node[0][(size_t)row * OUTD + h];
    float a = fabsf(v);
#pragma unroll
    for (int o = 16; o > 0; o >>= 1) a += __shfl_xor_sync(0xffffffffu, a, o);
    __shared__ float sh[4];
    if ((h & 31) == 0) sh[h >> 5] = a;
    __syncthreads();
    float tot = sh[0] + sh[1] + sh[2] + sh[3];
    float r = v / fmaxf(tot, 1e-12f);
    out[(size_t)row * OUTD + h] = r;
    adjcat[(size_t)row * KCAT + ITEM + h] = __float2half_rn(r);
}

// ---------------- Adj fp32 -> fp16 into adjcat (stride KCAT) ---------------
__global__ void k_cvt(const float4* __restrict__ src, __half* __restrict__ dst) {
    size_t i = (size_t)blockIdx.x * blockDim.x + threadIdx.x;  // float4 index
    float4 v = src[i];
    size_t row = i >> 11;          // 2048 float4 per 8192-col row
    int col = (int)(i & 2047) * 4;
    uint2 p = make_uint2(pack_h2(v.x, v.y), pack_h2(v.z, v.w));
    *reinterpret_cast<uint2*>(dst + row * KCAT + col) = p;
}

// ---------------- weight transpose fp16: B[K][N] -> Bt[N][K] ---------------
__global__ void k_tsp(const float* __restrict__ B, __half* __restrict__ th,
                      int K, int N) {
    __shared__ float s[32][33];
    int n0 = blockIdx.x * 32, k0 = blockIdx.y * 32;
    int tx = threadIdx.x, ty = threadIdx.y;
#pragma unroll
    for (int i = 0; i < 32; i += 8)
        s[ty + i][tx] = B[(size_t)(k0 + ty + i) * N + n0 + tx];
    __syncthreads();
#pragma unroll
    for (int i = 0; i < 32; i += 8) {
        int n = n0 + ty + i, k = k0 + tx;
        th[(size_t)n * K + k] = __float2half_rn(s[tx][ty + i]);
    }
}

// ---------------- mma.sync + ldmatrix + cp.async plumbing ------------------
__device__ __forceinline__ uint32_t s2u(const void* p) {
    uint32_t a;
    asm("{ .reg .u64 t; cvta.to.shared.u64 t, %1; cvt.u32.u64 %0, t; }" : "=r"(a) : "l"(p));
    return a;
}
__device__ __forceinline__ void mma_f16(float* d, const uint32_t* a, const uint32_t* b) {
    asm volatile(
        "mma.sync.aligned.m16n8k16.row.col.f32.f16.f16.f32 "
        "{%0,%1,%2,%3}, {%4,%5,%6,%7}, {%8,%9}, {%0,%1,%2,%3};"
        : "+f"(d[0]), "+f"(d[1]), "+f"(d[2]), "+f"(d[3])
        : "r"(a[0]), "r"(a[1]), "r"(a[2]), "r"(a[3]), "r"(b[0]), "r"(b[1]));
}
__device__ __forceinline__ void ldsm4(uint32_t* r, uint32_t addr) {
    asm volatile("ldmatrix.sync.aligned.m8n8.x4.shared.b16 {%0,%1,%2,%3}, [%4];"
                 : "=r"(r[0]), "=r"(r[1]), "=r"(r[2]), "=r"(r[3]) : "r"(addr));
}
__device__ __forceinline__ void cpa16(uint32_t s, const void* g) {
    asm volatile("cp.async.cg.shared.global [%0], [%1], 16;" :: "r"(s), "l"(g));
}
#define CP_COMMIT() asm volatile("cp.async.commit_group;" ::: "memory")
#define CP_WAIT2()  asm volatile("cp.async.wait_group 2;" ::: "memory")

// ---------------- MLP GEMM: fp16 single-pass -------------------------------
// C = act(A @ B^T + bias); A [M][K] fp16 row-major, B [N][K] fp16.
// BM=BN=128, BK=64, 256 threads (8 warps 4m x 2n), 3-stage cp.async.
// OUT: 0 = fp32 to Cf; 1 = fp16 to Oh.
#define TC_STAGE 32768u                // A 16KB, B 16KB
#define TC_SMEM  (3 * TC_STAGE)

template <int ACT, int OUT>
__global__ void __launch_bounds__(256, 1)
k_tc(const __half* __restrict__ A_, const __half* __restrict__ Bh_,
     const float* __restrict__ bias,
     float* __restrict__ Cf, __half* __restrict__ Oh, int N, int K) {
    extern __shared__ char smc[];
    const uint32_t sb = s2u(smc);
    const int tid = threadIdx.x, lane = tid & 31, warp = tid >> 5;
    const int wm = warp & 3, wn = warp >> 2;
    const int g = lane >> 2, tig = lane & 3;
    const int bm = blockIdx.y * 128, bn = blockIdx.x * 128;

    float c[2][8][4];
#pragma unroll
    for (int i = 0; i < 2; i++)
#pragma unroll
        for (int j = 0; j < 8; j++)
#pragma unroll
            for (int q = 0; q < 4; q++) c[i][j][q] = 0.f;

    auto load_stage = [&](int s) {
        const uint32_t st = sb + (uint32_t)(s % 3) * TC_STAGE;
        const int k0 = s * 64;
#pragma unroll
        for (int j = 0; j < 4; j++) {
            int cidx = tid + 256 * j;
            int row = cidx >> 3, kc = cidx & 7;
            uint32_t off = (uint32_t)(row * 128 + kc * 16);
            off ^= (off >> 3) & 0x70;
            size_t ga = (size_t)(bm + row) * K + k0 + kc * 8;
            size_t gb = (size_t)(bn + row) * K + k0 + kc * 8;
            cpa16(st + off, A_ + ga);
            cpa16(st + 16384 + off, Bh_ + gb);
        }
    };

    const int nst = K >> 6;
#pragma unroll
    for (int i = 0; i < 3; i++) {
        if (i < nst) load_stage(i);
        CP_COMMIT();
    }

    for (int s = 0; s < nst; s++) {
        CP_WAIT2();
        __syncthreads();
        const uint32_t st = sb + (uint32_t)(s % 3) * TC_STAGE;
#pragma unroll
        for (int kk = 0; kk < 64; kk += 16) {
            uint32_t ah[2][4], bh[8][2];
#pragma unroll
            for (int mt = 0; mt < 2; mt++) {
                int row = wm * 32 + mt * 16 + (lane & 15);
                uint32_t off = (uint32_t)(row * 128) + (uint32_t)(kk * 2) + (uint32_t)(lane & 16);
                off ^= (off >> 3) & 0x70;
                ldsm4(ah[mt], st + off);
            }
#pragma unroll
            for (int bt = 0; bt < 4; bt++) {
                int row = wn * 64 + bt * 16 + ((lane >> 4) << 3) + (lane & 7);
                uint32_t off = (uint32_t)(row * 128) + (uint32_t)(kk * 2) + (uint32_t)((lane & 8) << 1);
                off ^= (off >> 3) & 0x70;
                uint32_t r[4];
                ldsm4(r, st + 16384 + off);
                bh[2 * bt][0] = r[0]; bh[2 * bt][1] = r[1];
                bh[2 * bt + 1][0] = r[2]; bh[2 * bt + 1][1] = r[3];
            }
#pragma unroll
            for (int mt = 0; mt < 2; mt++)
#pragma unroll
                for (int nt = 0; nt < 8; nt++)
                    mma_f16(c[mt][nt], ah[mt], bh[nt]);
        }
        __syncthreads();
        if (s + 3 < nst) load_stage(s + 3);
        CP_COMMIT();
    }

    // epilogue
#pragma unroll
    for (int mt = 0; mt < 2; mt++) {
#pragma unroll
        for (int nt = 0; nt < 8; nt++) {
            int m0 = bm + wm * 32 + mt * 16 + g;
            int n0 = bn + wn * 64 + nt * 8 + 2 * tig;
            float2 v0 = make_float2(c[mt][nt][0], c[mt][nt][1]);
            float2 v1 = make_float2(c[mt][nt][2], c[mt][nt][3]);
            if (bias) {
                float bx = bias[n0], by = bias[n0 + 1];
                v0.x += bx; v0.y += by; v1.x += bx; v1.y += by;
            }
            if (ACT == 1) {
                v0.x = fmaxf(v0.x, 0.f); v0.y = fmaxf(v0.y, 0.f);
                v1.x = fmaxf(v1.x, 0.f); v1.y = fmaxf(v1.y, 0.f);
            } else if (ACT == 2) {
                v0.x = 1.f / (1.f + expf(-v0.x)); v0.y = 1.f / (1.f + expf(-v0.y));
                v1.x = 1.f / (1.f + expf(-v1.x)); v1.y = 1.f / (1.f + expf(-v1.y));
            }
            if (OUT == 0) {
                *reinterpret_cast<float2*>(Cf + (size_t)m0 * N + n0) = v0;
                *reinterpret_cast<float2*>(Cf + (size_t)(m0 + 8) * N + n0) = v1;
            } else {
                *reinterpret_cast<uint32_t*>(Oh + (size_t)m0 * N + n0) = pack_h2(v0.x, v0.y);
                *reinterpret_cast<uint32_t*>(Oh + (size_t)(m0 + 8) * N + n0) = pack_h2(v1.x, v1.y);
            }
        }
    }
}

// ---------------- orchestration ----------------
extern "C" void kernel_launch(void* const* d_in, const int* in_sizes, int n_in,
                              void* d_out, int out_size) {
    const float* hM  = (const float*)d_in[0];
    const float* hD  = (const float*)d_in[1];
    const float* hT  = (const float*)d_in[2];
    const float* W1  = (const float*)d_in[3];
    const float* b1  = (const float*)d_in[4];
    const float* W2  = (const float*)d_in[5];
    const float* b2  = (const float*)d_in[6];
    const float* W3  = (const float*)d_in[7];
    const float* b3  = (const float*)d_in[8];
    const float* Adj = (const float*)d_in[9];
    const float* f1w = (const float*)d_in[10];
    const float* f1b = (const float*)d_in[11];
    const float* f2w = (const float*)d_in[12];
    const float* f2b = (const float*)d_in[13];
    const float* f3w = (const float*)d_in[14];
    const float* f3b = (const float*)d_in[15];
    const float* f4w = (const float*)d_in[16];
    const float* f4b = (const float*)d_in[17];
    const int* edges = (const int*)d_in[18];

    float *p_node, *p_agg, *p_outinv, *p_ininv;
    __half *p_bth, *p_adjcat, *p_x1h, *p_x2h, *p_x3h;
    cudaGetSymbolAddress((void**)&p_node, g_node);
    cudaGetSymbolAddress((void**)&p_agg, g_agg);
    cudaGetSymbolAddress((void**)&p_outinv, g_outinv);
    cudaGetSymbolAddress((void**)&p_ininv, g_ininv);
    cudaGetSymbolAddress((void**)&p_bth, g_bth);
    cudaGetSymbolAddress((void**)&p_adjcat, g_adjcat);
    cudaGetSymbolAddress((void**)&p_x1h, g_x1h);
    cudaGetSymbolAddress((void**)&p_x2h, g_x2h);
    cudaGetSymbolAddress((void**)&p_x3h, g_x3h);

    float* fe   = (float*)d_out;                       // 4096 x 128
    float* outx = (float*)d_out + (size_t)MROW * OUTD; // 4096 x 8192

    cudaFuncSetAttribute(k_tc<1, 1>, cudaFuncAttributeMaxDynamicSharedMemorySize, TC_SMEM);
    cudaFuncSetAttribute(k_tc<2, 0>, cudaFuncAttributeMaxDynamicSharedMemorySize, TC_SMEM);
    cudaFuncSetAttribute(k_count, cudaFuncAttributeMaxDynamicSharedMemorySize, 2 * NN * 4);

    // operand prep (independent of GNN stages)
    k_cvt<<<(MROW * ITEM / 4) / 256, 256>>>((const float4*)Adj, p_adjcat);
    k_tsp<<<dim3(256 / 32, KCAT / 32), dim3(32, 8)>>>(f1w, p_bth + O1, KCAT, 256);
    k_tsp<<<dim3(512 / 32, 256 / 32),  dim3(32, 8)>>>(f2w, p_bth + O2, 256, 512);
    k_tsp<<<dim3(1024 / 32, 512 / 32), dim3(32, 8)>>>(f3w, p_bth + O3, 512, 1024);
    k_tsp<<<dim3(8192 / 32, 1024 / 32), dim3(32, 8)>>>(f4w, p_bth + O4, 1024, 8192);

    // CSR + degrees
    k_zero_counts<<<(NREL * NN + 255) / 256, 256>>>();
    k_count<<<dim3(CB, NREL), 512, 2 * NN * 4>>>(edges);
    k_scan<<<NREL, 1024>>>();
    k_fill<<<(NREL * NE / 4 + 255) / 256, 256>>>(edges);

    // layer 1: FEAT=256 -> 64, then gather at 64
    k_conv_b<<<dim3(1, NN / 64, 6), 256>>>(hM, hD, hT, W1, p_outinv, 256, 64);
    k_agg_v<<<dim3(NN / 16, 3), dim3(16, 16)>>>(b1);

    // layer 2: 64 -> 64, then gather at 64
    k_conv_b<<<dim3(1, NN / 64, 6), 256>>>(p_node, p_node + (size_t)NN * 128,
                                           p_node + (size_t)2 * NN * 128, W2, p_outinv, 64, 64);
    k_agg_v<<<dim3(NN / 16, 3), dim3(16, 16)>>>(b2);

    // layer 3: pre-aggregate at 64, then GEMM 64->128 (ind-scale in GEMM), combine
    k_aggpre<<<dim3(NN / 16, 6), dim3(16, 16)>>>();
    k_conv_b<<<dim3(2, NN / 64, 6), 256>>>(p_agg, nullptr, nullptr, W3, p_ininv, 64, 128);
    k_addb<<<dim3(NN * 128 / 4 / 256, 3), 256>>>(b3);

    // fake_embeding = L1-normalized hM3[0:4096] -> d_out (+ fp16 into adjcat)
    k_l1norm<<<MROW, 128>>>(fe, p_adjcat);

    // MLP decoder (fp16 single-pass)
    k_tc<1, 1><<<dim3(2, 32), 256, TC_SMEM>>>(
        p_adjcat, p_bth + O1, f1b, nullptr, p_x1h, 256, KCAT);
    k_tc<1, 1><<<dim3(4, 32), 256, TC_SMEM>>>(
        p_x1h, p_bth + O2, f2b, nullptr, p_x2h, 512, 256);
    k_tc<1, 1><<<dim3(8, 32), 256, TC_SMEM>>>(
        p_x2h, p_bth + O3, f3b, nullptr, p_x3h, 1024, 512);
    k_tc<2, 0><<<dim3(64, 32), 256, TC_SMEM>>>(
        p_x3h, p_bth + O4, f4b, outx, nullptr, 8192, 1024);
}

// round 9
// speedup vs baseline: 5.0318x; 1.0514x over previous
#include <cuda_runtime.h>
#include <cuda_fp16.h>
#include <stdint.h>
#include <math.h>

#define NN   8192
#define NE   500000
#define NREL 6
#define FEAT 256
#define HIDD 64
#define OUTD 128
#define MROW 4096   // SIZE
#define ITEM 8192
#define KCAT 8320   // ITEM + OUTD
#define CB   8      // count blocks per relation

// ---------------- scratch (device globals: allocation-free) ----------------
__device__ int   g_outcnt[NREL][NN];
__device__ int   g_incnt [NREL][NN];
__device__ float g_outinv[NREL][NN];
__device__ float g_ininv [NREL][NN];
__device__ int   g_rowptr[NREL][NN + 1];
__device__ int   g_fill  [NREL][NN];
__device__ int   g_srcs  [NREL][NE];
__device__ __half g_xsh [NREL][NN * 64];    // layers 1-2 conv outputs (gathered)
__device__ float g_xs32 [NREL][NN * 128];   // layer-3 conv outputs (fp32)
__device__ float g_agg  [NREL][NN * 64];    // layer-3 pre-aggregated inputs
__device__ float g_node [3][NN * 128];      // trunk state fp32
__device__ __half g_nodeh[3][NN * 64];      // fp16 shadow for layer-3 gather

// pre-transposed fp16 weights: Bt[n][k] per matrix, offsets below
#define O1  0                            // f1w^T     [256][8320]
#define O2  2129920                      // f2w^T     [512][256]
#define O3  2260992                      // f3w^T     [1024][512]
#define O4  2785280                      // f4w^T     [8192][1024]
#define BT_TOTAL 11173888
__device__ __half g_bth[BT_TOTAL];

// fp16 activations: concatenated [Adj | fe] + layer outputs
__device__ __half g_adjcat[(size_t)MROW * KCAT];
__device__ __half g_x1h[MROW * 256];
__device__ __half g_x2h[MROW * 512];
__device__ __half g_x3h[MROW * 1024];

// ---------------- fp16 helpers ----------------
__device__ __forceinline__ uint32_t pack_h2(float x, float y) {
    __half2 h = __floats2half2_rn(x, y);
    return *reinterpret_cast<uint32_t*>(&h);
}
__device__ __forceinline__ float4 h4tof4(uint2 u) {
    float2 a = __half22float2(*reinterpret_cast<__half2*>(&u.x));
    float2 b = __half22float2(*reinterpret_cast<__half2*>(&u.y));
    return make_float4(a.x, a.y, b.x, b.y);
}
__device__ __forceinline__ void store4(float* p, float a, float b, float c, float d) {
    *reinterpret_cast<float4*>(p) = make_float4(a, b, c, d);
}
__device__ __forceinline__ void store4(__half* p, float a, float b, float c, float d) {
    *reinterpret_cast<uint2*>(p) = make_uint2(pack_h2(a, b), pack_h2(c, d));
}

// ---------------- CSR build ----------------
__global__ void k_zero_counts() {
    int i = blockIdx.x * blockDim.x + threadIdx.x;
    if (i < NREL * NN) {
        ((int*)g_outcnt)[i] = 0;
        ((int*)g_incnt)[i]  = 0;
    }
}

// smem-privatized degree histogram: 8 blocks per relation, 64KB smem each
__global__ void k_count(const int* __restrict__ edges) {
    extern __shared__ int smcnt[];            // [2*NN]
    const int r = blockIdx.y, b = blockIdx.x;
    int* so = smcnt;
    int* si = smcnt + NN;
    for (int i = threadIdx.x; i < 2 * NN; i += blockDim.x) smcnt[i] = 0;
    __syncthreads();
    const int per = NE / CB;
    const int e0 = b * per;
    const int* es = edges + (size_t)r * 2 * NE;
    for (int e = e0 + threadIdx.x * 4; e < e0 + per; e += blockDim.x * 4) {
        int4 s = *reinterpret_cast<const int4*>(es + e);
        int4 d = *reinterpret_cast<const int4*>(es + NE + e);
        atomicAdd(&so[s.x], 1); atomicAdd(&so[s.y], 1);
        atomicAdd(&so[s.z], 1); atomicAdd(&so[s.w], 1);
        atomicAdd(&si[d.x], 1); atomicAdd(&si[d.y], 1);
        atomicAdd(&si[d.z], 1); atomicAdd(&si[d.w], 1);
    }
    __syncthreads();
    for (int i = threadIdx.x; i < NN; i += blockDim.x) {
        int v = so[i];
        if (v) atomicAdd(&g_outcnt[r][i], v);
        v = si[i];
        if (v) atomicAdd(&g_incnt[r][i], v);
    }
}

__global__ void k_scan() {
    int r = blockIdx.x;
    int tid = threadIdx.x;          // 1024 threads
    int base = tid * 8;
    int c[8];
    int s = 0;
#pragma unroll
    for (int i = 0; i < 8; i++) { c[i] = g_incnt[r][base + i]; s += c[i]; }

    int lane = tid & 31, w = tid >> 5;
    int incl = s;
#pragma unroll
    for (int o = 1; o < 32; o <<= 1) {
        int v = __shfl_up_sync(0xffffffffu, incl, o);
        if (lane >= o) incl += v;
    }
    __shared__ int wsum[32];
    if (lane == 31) wsum[w] = incl;
    __syncthreads();
    if (w == 0) {
        int v = wsum[lane];
#pragma unroll
        for (int o = 1; o < 32; o <<= 1) {
            int t = __shfl_up_sync(0xffffffffu, v, o);
            if (lane >= o) v += t;
        }
        wsum[lane] = v;
    }
    __syncthreads();
    int excl = (incl - s) + (w > 0 ? wsum[w - 1] : 0);
    int run = excl;
#pragma unroll
    for (int i = 0; i < 8; i++) {
        g_rowptr[r][base + i] = run;
        g_fill[r][base + i]   = run;
        run += c[i];
        int ic = c[i] > 0 ? c[i] : 1;
        g_ininv[r][base + i] = rsqrtf((float)ic);
        int oc = g_outcnt[r][base + i];
        if (oc < 1) oc = 1;
        g_outinv[r][base + i] = rsqrtf((float)oc);
    }
    if (tid == 1023) g_rowptr[r][NN] = run;
}

__global__ void k_fill(const int* __restrict__ edges) {
    int i = (blockIdx.x * blockDim.x + threadIdx.x) * 4;
    if (i >= NREL * NE) return;
    int r = i / NE, e = i - r * NE;
    int4 src = *reinterpret_cast<const int4*>(edges + (size_t)r * 2 * NE + e);
    int4 dst = *reinterpret_cast<const int4*>(edges + (size_t)r * 2 * NE + NE + e);
    g_srcs[r][atomicAdd(&g_fill[r][dst.x], 1)] = src.x;
    g_srcs[r][atomicAdd(&g_fill[r][dst.y], 1)] = src.y;
    g_srcs[r][atomicAdd(&g_fill[r][dst.z], 1)] = src.z;
    g_srcs[r][atomicAdd(&g_fill[r][dst.w], 1)] = src.w;
}

// ---------------- conv GEMM batched over relations (gridDim.z = 6) --------
// out type T in {float, __half}; out stride per relation given by xstride.
template <typename T>
__global__ void k_conv_b(const float* __restrict__ A0, const float* __restrict__ A1,
                         const float* __restrict__ A2, const float* __restrict__ Wb,
                         const float* __restrict__ scaleb, int K, int Nh,
                         T* __restrict__ xsbase, size_t xstride) {
    const int r = blockIdx.z;
    const int smap[6] = {0, 1, 0, 2, 2, 1};
    const float* A;
    if (A1 == nullptr) {
        A = A0 + (size_t)r * NN * K;
    } else {
        int si = smap[r];
        A = (si == 0) ? A0 : (si == 1) ? A1 : A2;
    }
    const float* W = Wb + (size_t)r * K * Nh;
    T* Xs = xsbase + (size_t)r * xstride;
    const float* scale = scaleb + r * NN;

    __shared__ float As[16][64];
    __shared__ float Bs[16][64];
    int tid = threadIdx.x;
    int bx = blockIdx.x, by = blockIdx.y;
    int aRow = tid >> 2, aCol = (tid & 3) * 4;
    int bRow = tid >> 4, bCol = (tid & 15) * 4;
    int tx = tid & 15, ty = tid >> 4;
    float acc[4][4] = {};
    const float* Ap = A + (size_t)(by * 64) * K;
    float scl = scale[by * 64 + aRow];

    for (int k0 = 0; k0 < K; k0 += 16) {
        float4 av = *(const float4*)(Ap + (size_t)aRow * K + k0 + aCol);
        As[aCol + 0][aRow] = av.x * scl;
        As[aCol + 1][aRow] = av.y * scl;
        As[aCol + 2][aRow] = av.z * scl;
        As[aCol + 3][aRow] = av.w * scl;
        float4 bv = *(const float4*)(W + (size_t)(k0 + bRow) * Nh + bx * 64 + bCol);
        *(float4*)&Bs[bRow][bCol] = bv;
        __syncthreads();
#pragma unroll
        for (int kk = 0; kk < 16; kk++) {
            float a[4], b[4];
#pragma unroll
            for (int i = 0; i < 4; i++) a[i] = As[kk][ty * 4 + i];
#pragma unroll
            for (int j = 0; j < 4; j++) b[j] = Bs[kk][tx * 4 + j];
#pragma unroll
            for (int i = 0; i < 4; i++)
#pragma unroll
                for (int j = 0; j < 4; j++) acc[i][j] += a[i] * b[j];
        }
        __syncthreads();
    }
    int row0 = by * 64 + ty * 4, col0 = bx * 64 + tx * 4;
#pragma unroll
    for (int i = 0; i < 4; i++)
        store4(Xs + (size_t)(row0 + i) * Nh + col0,
               acc[i][0], acc[i][1], acc[i][2], acc[i][3]);
}

// ---------------- aggregation helpers ----------------
__device__ __forceinline__ float4 f4add(float4 a, float4 b) {
    a.x += b.x; a.y += b.y; a.z += b.z; a.w += b.w; return a;
}
__device__ __forceinline__ float4 f4fma(float4 a, float s, float4 acc) {
    acc.x += a.x * s; acc.y += a.y * s; acc.z += a.z * s; acc.w += a.w * s; return acc;
}

// post-GEMM agg (layers 1,2): gathers fp16 xs; writes fp32 node + fp16 shadow
__global__ void k_agg_v(const float* __restrict__ bias) {
    const int t = blockIdx.y;
    const int n = blockIdx.x * blockDim.y + threadIdx.y;
    const int lane = threadIdx.x;     // 0..15
    const int RA[3] = {1, 0, 2};
    const int RB[3] = {3, 4, 5};
    int rel[2] = {RA[t], RB[t]};
    float4 acc = f4add(reinterpret_cast<const float4*>(bias + rel[0] * 64)[lane],
                       reinterpret_cast<const float4*>(bias + rel[1] * 64)[lane]);
#pragma unroll
    for (int rr = 0; rr < 2; rr++) {
        int r = rel[rr];
        int e0 = g_rowptr[r][n], e1 = g_rowptr[r][n + 1];
        const __half* xs = g_xsh[r];
        const int* srcs = g_srcs[r];
        float4 s = make_float4(0.f, 0.f, 0.f, 0.f);
        int e = e0;
        for (; e + 7 < e1; e += 8) {
            uint2 u0 = reinterpret_cast<const uint2*>(xs + (size_t)srcs[e] * 64)[lane];
            uint2 u1 = reinterpret_cast<const uint2*>(xs + (size_t)srcs[e + 1] * 64)[lane];
            uint2 u2 = reinterpret_cast<const uint2*>(xs + (size_t)srcs[e + 2] * 64)[lane];
            uint2 u3 = reinterpret_cast<const uint2*>(xs + (size_t)srcs[e + 3] * 64)[lane];
            uint2 u4 = reinterpret_cast<const uint2*>(xs + (size_t)srcs[e + 4] * 64)[lane];
            uint2 u5 = reinterpret_cast<const uint2*>(xs + (size_t)srcs[e + 5] * 64)[lane];
            uint2 u6 = reinterpret_cast<const uint2*>(xs + (size_t)srcs[e + 6] * 64)[lane];
            uint2 u7 = reinterpret_cast<const uint2*>(xs + (size_t)srcs[e + 7] * 64)[lane];
            s = f4add(s, f4add(f4add(h4tof4(u0), h4tof4(u1)),
                               f4add(h4tof4(u2), h4tof4(u3))));
            s = f4add(s, f4add(f4add(h4tof4(u4), h4tof4(u5)),
                               f4add(h4tof4(u6), h4tof4(u7))));
        }
        for (; e < e1; e++) {
            uint2 u = reinterpret_cast<const uint2*>(xs + (size_t)srcs[e] * 64)[lane];
            s = f4add(s, h4tof4(u));
        }
        acc = f4fma(s, g_ininv[r][n], acc);
    }
    reinterpret_cast<float4*>(g_node[t] + (size_t)n * 64)[lane] = acc;
    reinterpret_cast<uint2*>(g_nodeh[t] + (size_t)n * 64)[lane] =
        make_uint2(pack_h2(acc.x, acc.y), pack_h2(acc.z, acc.w));
}

// pre-GEMM agg (layer 3): gathers fp16 node shadow, scaled by outinv[src]
__global__ void k_aggpre() {
    const int r = blockIdx.y;
    const int n = blockIdx.x * blockDim.y + threadIdx.y;
    const int lane = threadIdx.x;     // 0..15
    const int smap[6] = {0, 1, 0, 2, 2, 1};
    const __half* x = g_nodeh[smap[r]];
    const float* oi = g_outinv[r];
    const int* srcs = g_srcs[r];
    int e0 = g_rowptr[r][n], e1 = g_rowptr[r][n + 1];
    float4 acc = make_float4(0.f, 0.f, 0.f, 0.f);
    int e = e0;
    for (; e + 3 < e1; e += 4) {
        int s0 = srcs[e], s1 = srcs[e + 1], s2 = srcs[e + 2], s3 = srcs[e + 3];
        uint2 u0 = reinterpret_cast<const uint2*>(x + (size_t)s0 * 64)[lane];
        uint2 u1 = reinterpret_cast<const uint2*>(x + (size_t)s1 * 64)[lane];
        uint2 u2 = reinterpret_cast<const uint2*>(x + (size_t)s2 * 64)[lane];
        uint2 u3 = reinterpret_cast<const uint2*>(x + (size_t)s3 * 64)[lane];
        acc = f4fma(h4tof4(u0), oi[s0], acc);
        acc = f4fma(h4tof4(u1), oi[s1], acc);
        acc = f4fma(h4tof4(u2), oi[s2], acc);
        acc = f4fma(h4tof4(u3), oi[s3], acc);
    }
    for (; e < e1; e++) {
        int s0 = srcs[e];
        uint2 u0 = reinterpret_cast<const uint2*>(x + (size_t)s0 * 64)[lane];
        acc = f4fma(h4tof4(u0), oi[s0], acc);
    }
    reinterpret_cast<float4*>(g_agg[r] + (size_t)n * 64)[lane] = acc;
}

// layer-3 combine: node[t] = xs32[ra] + xs32[rb] + b[ra] + b[rb]  (stride 128)
__global__ void k_addb(const float* __restrict__ bias) {
    const int t = blockIdx.y;
    const int RA[3] = {1, 0, 2};
    const int RB[3] = {3, 4, 5};
    int ra = RA[t], rb = RB[t];
    int i = blockIdx.x * blockDim.x + threadIdx.x;   // over NN*128/4
    int h = (i & 31);                                 // float4 col index
    float4 a = reinterpret_cast<const float4*>(g_xs32[ra])[i];
    float4 b = reinterpret_cast<const float4*>(g_xs32[rb])[i];
    float4 ba = reinterpret_cast<const float4*>(bias + ra * 128)[h];
    float4 bb = reinterpret_cast<const float4*>(bias + rb * 128)[h];
    float4 o;
    o.x = a.x + b.x + ba.x + bb.x;
    o.y = a.y + b.y + ba.y + bb.y;
    o.z = a.z + b.z + ba.z + bb.z;
    o.w = a.w + b.w + ba.w + bb.w;
    reinterpret_cast<float4*>(g_node[t])[i] = o;
}

// ---------------- row L1-normalize hM3[0:4096] -> fe (f32) + adjcat fp16 ---
__global__ void k_l1norm(float* __restrict__ out, __half* __restrict__ adjcat) {
    int row = blockIdx.x;
    int h = threadIdx.x;  // 128
    float v = g_node[0][(size_t)row * OUTD + h];
    float a = fabsf(v);
#pragma unroll
    for (int o = 16; o > 0; o >>= 1) a += __shfl_xor_sync(0xffffffffu, a, o);
    __shared__ float sh[4];
    if ((h & 31) == 0) sh[h >> 5] = a;
    __syncthreads();
    float tot = sh[0] + sh[1] + sh[2] + sh[3];
    float r = v / fmaxf(tot, 1e-12f);
    out[(size_t)row * OUTD + h] = r;
    adjcat[(size_t)row * KCAT + ITEM + h] = __float2half_rn(r);
}

// ---------------- Adj fp32 -> fp16 into adjcat (stride KCAT) ---------------
__global__ void k_cvt(const float4* __restrict__ src, __half* __restrict__ dst) {
    size_t i = (size_t)blockIdx.x * blockDim.x + threadIdx.x;  // float4 index
    float4 v = src[i];
    size_t row = i >> 11;          // 2048 float4 per 8192-col row
    int col = (int)(i & 2047) * 4;
    uint2 p = make_uint2(pack_h2(v.x, v.y), pack_h2(v.z, v.w));
    *reinterpret_cast<uint2*>(dst + row * KCAT + col) = p;
}

// ---------------- weight transpose fp16: B[K][N] -> Bt[N][K] ---------------
__global__ void k_tsp(const float* __restrict__ B, __half* __restrict__ th,
                      int K, int N) {
    __shared__ float s[32][33];
    int n0 = blockIdx.x * 32, k0 = blockIdx.y * 32;
    int tx = threadIdx.x, ty = threadIdx.y;
#pragma unroll
    for (int i = 0; i < 32; i += 8)
        s[ty + i][tx] = B[(size_t)(k0 + ty + i) * N + n0 + tx];
    __syncthreads();
#pragma unroll
    for (int i = 0; i < 32; i += 8) {
        int n = n0 + ty + i, k = k0 + tx;
        th[(size_t)n * K + k] = __float2half_rn(s[tx][ty + i]);
    }
}

// ---------------- mma.sync + ldmatrix + cp.async plumbing ------------------
__device__ __forceinline__ uint32_t s2u(const void* p) {
    uint32_t a;
    asm("{ .reg .u64 t; cvta.to.shared.u64 t, %1; cvt.u32.u64 %0, t; }" : "=r"(a) : "l"(p));
    return a;
}
__device__ __forceinline__ void mma_f16(float* d, const uint32_t* a, const uint32_t* b) {
    asm volatile(
        "mma.sync.aligned.m16n8k16.row.col.f32.f16.f16.f32 "
        "{%0,%1,%2,%3}, {%4,%5,%6,%7}, {%8,%9}, {%0,%1,%2,%3};"
        : "+f"(d[0]), "+f"(d[1]), "+f"(d[2]), "+f"(d[3])
        : "r"(a[0]), "r"(a[1]), "r"(a[2]), "r"(a[3]), "r"(b[0]), "r"(b[1]));
}
__device__ __forceinline__ void ldsm4(uint32_t* r, uint32_t addr) {
    asm volatile("ldmatrix.sync.aligned.m8n8.x4.shared.b16 {%0,%1,%2,%3}, [%4];"
                 : "=r"(r[0]), "=r"(r[1]), "=r"(r[2]), "=r"(r[3]) : "r"(addr));
}
__device__ __forceinline__ void cpa16(uint32_t s, const void* g) {
    asm volatile("cp.async.cg.shared.global [%0], [%1], 16;" :: "r"(s), "l"(g));
}
#define CP_COMMIT() asm volatile("cp.async.commit_group;" ::: "memory")
#define CP_WAIT2()  asm volatile("cp.async.wait_group 2;" ::: "memory")

// ---------------- MLP GEMM: fp16 single-pass -------------------------------
#define TC_STAGE 32768u                // A 16KB, B 16KB
#define TC_SMEM  (3 * TC_STAGE)

template <int ACT, int OUT>
__global__ void __launch_bounds__(256, 1)
k_tc(const __half* __restrict__ A_, const __half* __restrict__ Bh_,
     const float* __restrict__ bias,
     float* __restrict__ Cf, __half* __restrict__ Oh, int N, int K) {
    extern __shared__ char smc[];
    const uint32_t sb = s2u(smc);
    const int tid = threadIdx.x, lane = tid & 31, warp = tid >> 5;
    const int wm = warp & 3, wn = warp >> 2;
    const int g = lane >> 2, tig = lane & 3;
    const int bm = blockIdx.y * 128, bn = blockIdx.x * 128;

    float c[2][8][4];
#pragma unroll
    for (int i = 0; i < 2; i++)
#pragma unroll
        for (int j = 0; j < 8; j++)
#pragma unroll
            for (int q = 0; q < 4; q++) c[i][j][q] = 0.f;

    auto load_stage = [&](int s) {
        const uint32_t st = sb + (uint32_t)(s % 3) * TC_STAGE;
        const int k0 = s * 64;
#pragma unroll
        for (int j = 0; j < 4; j++) {
            int cidx = tid + 256 * j;
            int row = cidx >> 3, kc = cidx & 7;
            uint32_t off = (uint32_t)(row * 128 + kc * 16);
            off ^= (off >> 3) & 0x70;
            size_t ga = (size_t)(bm + row) * K + k0 + kc * 8;
            size_t gb = (size_t)(bn + row) * K + k0 + kc * 8;
            cpa16(st + off, A_ + ga);
            cpa16(st + 16384 + off, Bh_ + gb);
        }
    };

    const int nst = K >> 6;
#pragma unroll
    for (int i = 0; i < 3; i++) {
        if (i < nst) load_stage(i);
        CP_COMMIT();
    }

    for (int s = 0; s < nst; s++) {
        CP_WAIT2();
        __syncthreads();
        const uint32_t st = sb + (uint32_t)(s % 3) * TC_STAGE;
#pragma unroll
        for (int kk = 0; kk < 64; kk += 16) {
            uint32_t ah[2][4], bh[8][2];
#pragma unroll
            for (int mt = 0; mt < 2; mt++) {
                int row = wm * 32 + mt * 16 + (lane & 15);
                uint32_t off = (uint32_t)(row * 128) + (uint32_t)(kk * 2) + (uint32_t)(lane & 16);
                off ^= (off >> 3) & 0x70;
                ldsm4(ah[mt], st + off);
            }
#pragma unroll
            for (int bt = 0; bt < 4; bt++) {
                int row = wn * 64 + bt * 16 + ((lane >> 4) << 3) + (lane & 7);
                uint32_t off = (uint32_t)(row * 128) + (uint32_t)(kk * 2) + (uint32_t)((lane & 8) << 1);
                off ^= (off >> 3) & 0x70;
                uint32_t r[4];
                ldsm4(r, st + 16384 + off);
                bh[2 * bt][0] = r[0]; bh[2 * bt][1] = r[1];
                bh[2 * bt + 1][0] = r[2]; bh[2 * bt + 1][1] = r[3];
            }
#pragma unroll
            for (int mt = 0; mt < 2; mt++)
#pragma unroll
                for (int nt = 0; nt < 8; nt++)
                    mma_f16(c[mt][nt], ah[mt], bh[nt]);
        }
        __syncthreads();
        if (s + 3 < nst) load_stage(s + 3);
        CP_COMMIT();
    }

    // epilogue
#pragma unroll
    for (int mt = 0; mt < 2; mt++) {
#pragma unroll
        for (int nt = 0; nt < 8; nt++) {
            int m0 = bm + wm * 32 + mt * 16 + g;
            int n0 = bn + wn * 64 + nt * 8 + 2 * tig;
            float2 v0 = make_float2(c[mt][nt][0], c[mt][nt][1]);
            float2 v1 = make_float2(c[mt][nt][2], c[mt][nt][3]);
            if (bias) {
                float bx = bias[n0], by = bias[n0 + 1];
                v0.x += bx; v0.y += by; v1.x += bx; v1.y += by;
            }
            if (ACT == 1) {
                v0.x = fmaxf(v0.x, 0.f); v0.y = fmaxf(v0.y, 0.f);
                v1.x = fmaxf(v1.x, 0.f); v1.y = fmaxf(v1.y, 0.f);
            } else if (ACT == 2) {
                v0.x = 1.f / (1.f + expf(-v0.x)); v0.y = 1.f / (1.f + expf(-v0.y));
                v1.x = 1.f / (1.f + expf(-v1.x)); v1.y = 1.f / (1.f + expf(-v1.y));
            }
            if (OUT == 0) {
                *reinterpret_cast<float2*>(Cf + (size_t)m0 * N + n0) = v0;
                *reinterpret_cast<float2*>(Cf + (size_t)(m0 + 8) * N + n0) = v1;
            } else {
                *reinterpret_cast<uint32_t*>(Oh + (size_t)m0 * N + n0) = pack_h2(v0.x, v0.y);
                *reinterpret_cast<uint32_t*>(Oh + (size_t)(m0 + 8) * N + n0) = pack_h2(v1.x, v1.y);
            }
        }
    }
}

// ---------------- orchestration ----------------
extern "C" void kernel_launch(void* const* d_in, const int* in_sizes, int n_in,
                              void* d_out, int out_size) {
    const float* hM  = (const float*)d_in[0];
    const float* hD  = (const float*)d_in[1];
    const float* hT  = (const float*)d_in[2];
    const float* W1  = (const float*)d_in[3];
    const float* b1  = (const float*)d_in[4];
    const float* W2  = (const float*)d_in[5];
    const float* b2  = (const float*)d_in[6];
    const float* W3  = (const float*)d_in[7];
    const float* b3  = (const float*)d_in[8];
    const float* Adj = (const float*)d_in[9];
    const float* f1w = (const float*)d_in[10];
    const float* f1b = (const float*)d_in[11];
    const float* f2w = (const float*)d_in[12];
    const float* f2b = (const float*)d_in[13];
    const float* f3w = (const float*)d_in[14];
    const float* f3b = (const float*)d_in[15];
    const float* f4w = (const float*)d_in[16];
    const float* f4b = (const float*)d_in[17];
    const int* edges = (const int*)d_in[18];

    float *p_node, *p_agg, *p_outinv, *p_ininv, *p_xs32;
    __half *p_bth, *p_adjcat, *p_x1h, *p_x2h, *p_x3h, *p_xsh;
    cudaGetSymbolAddress((void**)&p_node, g_node);
    cudaGetSymbolAddress((void**)&p_agg, g_agg);
    cudaGetSymbolAddress((void**)&p_outinv, g_outinv);
    cudaGetSymbolAddress((void**)&p_ininv, g_ininv);
    cudaGetSymbolAddress((void**)&p_xs32, g_xs32);
    cudaGetSymbolAddress((void**)&p_xsh, g_xsh);
    cudaGetSymbolAddress((void**)&p_bth, g_bth);
    cudaGetSymbolAddress((void**)&p_adjcat, g_adjcat);
    cudaGetSymbolAddress((void**)&p_x1h, g_x1h);
    cudaGetSymbolAddress((void**)&p_x2h, g_x2h);
    cudaGetSymbolAddress((void**)&p_x3h, g_x3h);

    float* fe   = (float*)d_out;                       // 4096 x 128
    float* outx = (float*)d_out + (size_t)MROW * OUTD; // 4096 x 8192

    cudaFuncSetAttribute(k_tc<1, 1>, cudaFuncAttributeMaxDynamicSharedMemorySize, TC_SMEM);
    cudaFuncSetAttribute(k_tc<2, 0>, cudaFuncAttributeMaxDynamicSharedMemorySize, TC_SMEM);
    cudaFuncSetAttribute(k_count, cudaFuncAttributeMaxDynamicSharedMemorySize, 2 * NN * 4);

    // operand prep (independent of GNN stages)
    k_cvt<<<(MROW * ITEM / 4) / 256, 256>>>((const float4*)Adj, p_adjcat);
    k_tsp<<<dim3(256 / 32, KCAT / 32), dim3(32, 8)>>>(f1w, p_bth + O1, KCAT, 256);
    k_tsp<<<dim3(512 / 32, 256 / 32),  dim3(32, 8)>>>(f2w, p_bth + O2, 256, 512);
    k_tsp<<<dim3(1024 / 32, 512 / 32), dim3(32, 8)>>>(f3w, p_bth + O3, 512, 1024);
    k_tsp<<<dim3(8192 / 32, 1024 / 32), dim3(32, 8)>>>(f4w, p_bth + O4, 1024, 8192);

    // CSR + degrees
    k_zero_counts<<<(NREL * NN + 255) / 256, 256>>>();
    k_count<<<dim3(CB, NREL), 512, 2 * NN * 4>>>(edges);
    k_scan<<<NREL, 1024>>>();
    k_fill<<<(NREL * NE / 4 + 255) / 256, 256>>>(edges);

    // layer 1: FEAT=256 -> 64 (fp16 xs), gather at 64
    k_conv_b<__half><<<dim3(1, NN / 64, 6), 256>>>(hM, hD, hT, W1, p_outinv, 256, 64,
                                                   p_xsh, (size_t)NN * 64);
    k_agg_v<<<dim3(NN / 16, 3), dim3(16, 16)>>>(b1);

    // layer 2: 64 -> 64 (fp16 xs), gather at 64
    k_conv_b<__half><<<dim3(1, NN / 64, 6), 256>>>(p_node, p_node + (size_t)NN * 128,
                                                   p_node + (size_t)2 * NN * 128, W2,
                                                   p_outinv, 64, 64, p_xsh, (size_t)NN * 64);
    k_agg_v<<<dim3(NN / 16, 3), dim3(16, 16)>>>(b2);

    // layer 3: pre-aggregate fp16 shadow, GEMM 64->128 fp32, combine
    k_aggpre<<<dim3(NN / 16, 6), dim3(16, 16)>>>();
    k_conv_b<float><<<dim3(2, NN / 64, 6), 256>>>(p_agg, nullptr, nullptr, W3, p_ininv,
                                                  64, 128, p_xs32, (size_t)NN * 128);
    k_addb<<<dim3(NN * 128 / 4 / 256, 3), 256>>>(b3);

    // fake_embeding = L1-normalized hM3[0:4096] -> d_out (+ fp16 into adjcat)
    k_l1norm<<<MROW, 128>>>(fe, p_adjcat);

    // MLP decoder (fp16 single-pass)
    k_tc<1, 1><<<dim3(2, 32), 256, TC_SMEM>>>(
        p_adjcat, p_bth + O1, f1b, nullptr, p_x1h, 256, KCAT);
    k_tc<1, 1><<<dim3(4, 32), 256, TC_SMEM>>>(
        p_x1h, p_bth + O2, f2b, nullptr, p_x2h, 512, 256);
    k_tc<1, 1><<<dim3(8, 32), 256, TC_SMEM>>>(
        p_x2h, p_bth + O3, f3b, nullptr, p_x3h, 1024, 512);
    k_tc<2, 0><<<dim3(64, 32), 256, TC_SMEM>>>(
        p_x3h, p_bth + O4, f4b, outx, nullptr, 8192, 1024);
}

// round 10
// speedup vs baseline: 5.7212x; 1.1370x over previous
#include <cuda_runtime.h>
#include <cuda_fp16.h>
#include <stdint.h>
#include <math.h>

#define NN   8192
#define NE   500000
#define NREL 6
#define FEAT 256
#define HIDD 64
#define OUTD 128
#define MROW 4096   // SIZE
#define ITEM 8192
#define CB   8      // count blocks per relation

// ---------------- scratch (device globals: allocation-free) ----------------
__device__ int   g_outcnt[NREL][NN];
__device__ int   g_incnt [NREL][NN];
__device__ float g_outinv[NREL][NN];
__device__ float g_ininv [NREL][NN];
__device__ int   g_rowptr[NREL][NN + 1];
__device__ int   g_fill  [NREL][NN];
__device__ int   g_srcs  [NREL][NE];
__device__ __half g_xsh [NREL][NN * 64];    // layers 1-2 conv outputs (gathered)
__device__ float g_xs32 [NREL][NN * 128];   // layer-3 conv outputs (fp32)
__device__ float g_agg  [NREL][NN * 64];    // layer-3 pre-aggregated inputs
__device__ float g_node [3][NN * 128];      // trunk state fp32
__device__ __half g_nodeh[3][NN * 64];      // fp16 shadow for layer-3 gather

// pre-transposed fp16 weights: Bt[n][k] per matrix, offsets below
#define O1A 0                            // f1w top^T [256][8192]
#define O1B 2097152                      // f1w bot^T [256][128]
#define O2  2129920                      // f2w^T     [512][256]
#define O3  2260992                      // f3w^T     [1024][512]
#define O4  2785280                      // f4w^T     [8192][1024]
#define BT_TOTAL 11173888
__device__ __half g_bth[BT_TOTAL];

// fp16 activations
__device__ __half g_adjh[(size_t)MROW * ITEM];
__device__ __half g_feh[MROW * OUTD];
__device__ float  g_x1f[MROW * 256];        // f1 Adj-partial (fp32)
__device__ __half g_x1h[MROW * 256];
__device__ __half g_x2h[MROW * 512];
__device__ __half g_x3h[MROW * 1024];

// ---------------- fp16 helpers ----------------
__device__ __forceinline__ uint32_t pack_h2(float x, float y) {
    __half2 h = __floats2half2_rn(x, y);
    return *reinterpret_cast<uint32_t*>(&h);
}
__device__ __forceinline__ float4 h4tof4(uint2 u) {
    float2 a = __half22float2(*reinterpret_cast<__half2*>(&u.x));
    float2 b = __half22float2(*reinterpret_cast<__half2*>(&u.y));
    return make_float4(a.x, a.y, b.x, b.y);
}
__device__ __forceinline__ void store4(float* p, float a, float b, float c, float d) {
    *reinterpret_cast<float4*>(p) = make_float4(a, b, c, d);
}
__device__ __forceinline__ void store4(__half* p, float a, float b, float c, float d) {
    *reinterpret_cast<uint2*>(p) = make_uint2(pack_h2(a, b), pack_h2(c, d));
}

// ---------------- CSR build ----------------
__global__ void k_zero_counts() {
    int i = blockIdx.x * blockDim.x + threadIdx.x;
    if (i < NREL * NN) {
        ((int*)g_outcnt)[i] = 0;
        ((int*)g_incnt)[i]  = 0;
    }
}

__global__ void k_count(const int* __restrict__ edges) {
    extern __shared__ int smcnt[];            // [2*NN]
    const int r = blockIdx.y, b = blockIdx.x;
    int* so = smcnt;
    int* si = smcnt + NN;
    for (int i = threadIdx.x; i < 2 * NN; i += blockDim.x) smcnt[i] = 0;
    __syncthreads();
    const int per = NE / CB;
    const int e0 = b * per;
    const int* es = edges + (size_t)r * 2 * NE;
    for (int e = e0 + threadIdx.x * 4; e < e0 + per; e += blockDim.x * 4) {
        int4 s = *reinterpret_cast<const int4*>(es + e);
        int4 d = *reinterpret_cast<const int4*>(es + NE + e);
        atomicAdd(&so[s.x], 1); atomicAdd(&so[s.y], 1);
        atomicAdd(&so[s.z], 1); atomicAdd(&so[s.w], 1);
        atomicAdd(&si[d.x], 1); atomicAdd(&si[d.y], 1);
        atomicAdd(&si[d.z], 1); atomicAdd(&si[d.w], 1);
    }
    __syncthreads();
    for (int i = threadIdx.x; i < NN; i += blockDim.x) {
        int v = so[i];
        if (v) atomicAdd(&g_outcnt[r][i], v);
        v = si[i];
        if (v) atomicAdd(&g_incnt[r][i], v);
    }
}

__global__ void k_scan() {
    int r = blockIdx.x;
    int tid = threadIdx.x;          // 1024 threads
    int base = tid * 8;
    int c[8];
    int s = 0;
#pragma unroll
    for (int i = 0; i < 8; i++) { c[i] = g_incnt[r][base + i]; s += c[i]; }

    int lane = tid & 31, w = tid >> 5;
    int incl = s;
#pragma unroll
    for (int o = 1; o < 32; o <<= 1) {
        int v = __shfl_up_sync(0xffffffffu, incl, o);
        if (lane >= o) incl += v;
    }
    __shared__ int wsum[32];
    if (lane == 31) wsum[w] = incl;
    __syncthreads();
    if (w == 0) {
        int v = wsum[lane];
#pragma unroll
        for (int o = 1; o < 32; o <<= 1) {
            int t = __shfl_up_sync(0xffffffffu, v, o);
            if (lane >= o) v += t;
        }
        wsum[lane] = v;
    }
    __syncthreads();
    int excl = (incl - s) + (w > 0 ? wsum[w - 1] : 0);
    int run = excl;
#pragma unroll
    for (int i = 0; i < 8; i++) {
        g_rowptr[r][base + i] = run;
        g_fill[r][base + i]   = run;
        run += c[i];
        int ic = c[i] > 0 ? c[i] : 1;
        g_ininv[r][base + i] = rsqrtf((float)ic);
        int oc = g_outcnt[r][base + i];
        if (oc < 1) oc = 1;
        g_outinv[r][base + i] = rsqrtf((float)oc);
    }
    if (tid == 1023) g_rowptr[r][NN] = run;
}

__global__ void k_fill(const int* __restrict__ edges) {
    int i = (blockIdx.x * blockDim.x + threadIdx.x) * 4;
    if (i >= NREL * NE) return;
    int r = i / NE, e = i - r * NE;
    int4 src = *reinterpret_cast<const int4*>(edges + (size_t)r * 2 * NE + e);
    int4 dst = *reinterpret_cast<const int4*>(edges + (size_t)r * 2 * NE + NE + e);
    g_srcs[r][atomicAdd(&g_fill[r][dst.x], 1)] = src.x;
    g_srcs[r][atomicAdd(&g_fill[r][dst.y], 1)] = src.y;
    g_srcs[r][atomicAdd(&g_fill[r][dst.z], 1)] = src.z;
    g_srcs[r][atomicAdd(&g_fill[r][dst.w], 1)] = src.w;
}

// ---------------- conv GEMM batched over relations (gridDim.z = 6) --------
template <typename T>
__global__ void k_conv_b(const float* __restrict__ A0, const float* __restrict__ A1,
                         const float* __restrict__ A2, const float* __restrict__ Wb,
                         const float* __restrict__ scaleb, int K, int Nh,
                         T* __restrict__ xsbase, size_t xstride) {
    const int r = blockIdx.z;
    const int smap[6] = {0, 1, 0, 2, 2, 1};
    const float* A;
    if (A1 == nullptr) {
        A = A0 + (size_t)r * NN * K;
    } else {
        int si = smap[r];
        A = (si == 0) ? A0 : (si == 1) ? A1 : A2;
    }
    const float* W = Wb + (size_t)r * K * Nh;
    T* Xs = xsbase + (size_t)r * xstride;
    const float* scale = scaleb + r * NN;

    __shared__ float As[16][64];
    __shared__ float Bs[16][64];
    int tid = threadIdx.x;
    int bx = blockIdx.x, by = blockIdx.y;
    int aRow = tid >> 2, aCol = (tid & 3) * 4;
    int bRow = tid >> 4, bCol = (tid & 15) * 4;
    int tx = tid & 15, ty = tid >> 4;
    float acc[4][4] = {};
    const float* Ap = A + (size_t)(by * 64) * K;
    float scl = scale[by * 64 + aRow];

    for (int k0 = 0; k0 < K; k0 += 16) {
        float4 av = *(const float4*)(Ap + (size_t)aRow * K + k0 + aCol);
        As[aCol + 0][aRow] = av.x * scl;
        As[aCol + 1][aRow] = av.y * scl;
        As[aCol + 2][aRow] = av.z * scl;
        As[aCol + 3][aRow] = av.w * scl;
        float4 bv = *(const float4*)(W + (size_t)(k0 + bRow) * Nh + bx * 64 + bCol);
        *(float4*)&Bs[bRow][bCol] = bv;
        __syncthreads();
#pragma unroll
        for (int kk = 0; kk < 16; kk++) {
            float a[4], b[4];
#pragma unroll
            for (int i = 0; i < 4; i++) a[i] = As[kk][ty * 4 + i];
#pragma unroll
            for (int j = 0; j < 4; j++) b[j] = Bs[kk][tx * 4 + j];
#pragma unroll
            for (int i = 0; i < 4; i++)
#pragma unroll
                for (int j = 0; j < 4; j++) acc[i][j] += a[i] * b[j];
        }
        __syncthreads();
    }
    int row0 = by * 64 + ty * 4, col0 = bx * 64 + tx * 4;
#pragma unroll
    for (int i = 0; i < 4; i++)
        store4(Xs + (size_t)(row0 + i) * Nh + col0,
               acc[i][0], acc[i][1], acc[i][2], acc[i][3]);
}

// ---------------- aggregation helpers ----------------
__device__ __forceinline__ float4 f4add(float4 a, float4 b) {
    a.x += b.x; a.y += b.y; a.z += b.z; a.w += b.w; return a;
}
__device__ __forceinline__ float4 f4fma(float4 a, float s, float4 acc) {
    acc.x += a.x * s; acc.y += a.y * s; acc.z += a.z * s; acc.w += a.w * s; return acc;
}

// post-GEMM agg (layers 1,2): gathers fp16 xs; writes fp32 node + fp16 shadow
__global__ void k_agg_v(const float* __restrict__ bias) {
    const int t = blockIdx.y;
    const int n = blockIdx.x * blockDim.y + threadIdx.y;
    const int lane = threadIdx.x;     // 0..15
    const int RA[3] = {1, 0, 2};
    const int RB[3] = {3, 4, 5};
    int rel[2] = {RA[t], RB[t]};
    float4 acc = f4add(reinterpret_cast<const float4*>(bias + rel[0] * 64)[lane],
                       reinterpret_cast<const float4*>(bias + rel[1] * 64)[lane]);
#pragma unroll
    for (int rr = 0; rr < 2; rr++) {
        int r = rel[rr];
        int e0 = g_rowptr[r][n], e1 = g_rowptr[r][n + 1];
        const __half* xs = g_xsh[r];
        const int* srcs = g_srcs[r];
        float4 s = make_float4(0.f, 0.f, 0.f, 0.f);
        int e = e0;
        for (; e + 7 < e1; e += 8) {
            uint2 u0 = reinterpret_cast<const uint2*>(xs + (size_t)srcs[e] * 64)[lane];
            uint2 u1 = reinterpret_cast<const uint2*>(xs + (size_t)srcs[e + 1] * 64)[lane];
            uint2 u2 = reinterpret_cast<const uint2*>(xs + (size_t)srcs[e + 2] * 64)[lane];
            uint2 u3 = reinterpret_cast<const uint2*>(xs + (size_t)srcs[e + 3] * 64)[lane];
            uint2 u4 = reinterpret_cast<const uint2*>(xs + (size_t)srcs[e + 4] * 64)[lane];
            uint2 u5 = reinterpret_cast<const uint2*>(xs + (size_t)srcs[e + 5] * 64)[lane];
            uint2 u6 = reinterpret_cast<const uint2*>(xs + (size_t)srcs[e + 6] * 64)[lane];
            uint2 u7 = reinterpret_cast<const uint2*>(xs + (size_t)srcs[e + 7] * 64)[lane];
            s = f4add(s, f4add(f4add(h4tof4(u0), h4tof4(u1)),
                               f4add(h4tof4(u2), h4tof4(u3))));
            s = f4add(s, f4add(f4add(h4tof4(u4), h4tof4(u5)),
                               f4add(h4tof4(u6), h4tof4(u7))));
        }
        for (; e < e1; e++) {
            uint2 u = reinterpret_cast<const uint2*>(xs + (size_t)srcs[e] * 64)[lane];
            s = f4add(s, h4tof4(u));
        }
        acc = f4fma(s, g_ininv[r][n], acc);
    }
    reinterpret_cast<float4*>(g_node[t] + (size_t)n * 64)[lane] = acc;
    reinterpret_cast<uint2*>(g_nodeh[t] + (size_t)n * 64)[lane] =
        make_uint2(pack_h2(acc.x, acc.y), pack_h2(acc.z, acc.w));
}

// pre-GEMM agg (layer 3): gathers fp16 node shadow, scaled by outinv[src]
__global__ void k_aggpre() {
    const int r = blockIdx.y;
    const int n = blockIdx.x * blockDim.y + threadIdx.y;
    const int lane = threadIdx.x;     // 0..15
    const int smap[6] = {0, 1, 0, 2, 2, 1};
    const __half* x = g_nodeh[smap[r]];
    const float* oi = g_outinv[r];
    const int* srcs = g_srcs[r];
    int e0 = g_rowptr[r][n], e1 = g_rowptr[r][n + 1];
    float4 acc = make_float4(0.f, 0.f, 0.f, 0.f);
    int e = e0;
    for (; e + 3 < e1; e += 4) {
        int s0 = srcs[e], s1 = srcs[e + 1], s2 = srcs[e + 2], s3 = srcs[e + 3];
        uint2 u0 = reinterpret_cast<const uint2*>(x + (size_t)s0 * 64)[lane];
        uint2 u1 = reinterpret_cast<const uint2*>(x + (size_t)s1 * 64)[lane];
        uint2 u2 = reinterpret_cast<const uint2*>(x + (size_t)s2 * 64)[lane];
        uint2 u3 = reinterpret_cast<const uint2*>(x + (size_t)s3 * 64)[lane];
        acc = f4fma(h4tof4(u0), oi[s0], acc);
        acc = f4fma(h4tof4(u1), oi[s1], acc);
        acc = f4fma(h4tof4(u2), oi[s2], acc);
        acc = f4fma(h4tof4(u3), oi[s3], acc);
    }
    for (; e < e1; e++) {
        int s0 = srcs[e];
        uint2 u0 = reinterpret_cast<const uint2*>(x + (size_t)s0 * 64)[lane];
        acc = f4fma(h4tof4(u0), oi[s0], acc);
    }
    reinterpret_cast<float4*>(g_agg[r] + (size_t)n * 64)[lane] = acc;
}

// layer-3 combine: node[t] = xs32[ra] + xs32[rb] + b[ra] + b[rb]  (stride 128)
__global__ void k_addb(const float* __restrict__ bias) {
    const int t = blockIdx.y;
    const int RA[3] = {1, 0, 2};
    const int RB[3] = {3, 4, 5};
    int ra = RA[t], rb = RB[t];
    int i = blockIdx.x * blockDim.x + threadIdx.x;   // over NN*128/4
    int h = (i & 31);                                 // float4 col index
    float4 a = reinterpret_cast<const float4*>(g_xs32[ra])[i];
    float4 b = reinterpret_cast<const float4*>(g_xs32[rb])[i];
    float4 ba = reinterpret_cast<const float4*>(bias + ra * 128)[h];
    float4 bb = reinterpret_cast<const float4*>(bias + rb * 128)[h];
    float4 o;
    o.x = a.x + b.x + ba.x + bb.x;
    o.y = a.y + b.y + ba.y + bb.y;
    o.z = a.z + b.z + ba.z + bb.z;
    o.w = a.w + b.w + ba.w + bb.w;
    reinterpret_cast<float4*>(g_node[t])[i] = o;
}

// ---------------- row L1-normalize hM3[0:4096] -> fe (f32) + fp16 ----------
__global__ void k_l1norm(float* __restrict__ out, __half* __restrict__ feh) {
    int row = blockIdx.x;
    int h = threadIdx.x;  // 128
    float v = g_node[0][(size_t)row * OUTD + h];
    float a = fabsf(v);
#pragma unroll
    for (int o = 16; o > 0; o >>= 1) a += __shfl_xor_sync(0xffffffffu, a, o);
    __shared__ float sh[4];
    if ((h & 31) == 0) sh[h >> 5] = a;
    __syncthreads();
    float tot = sh[0] + sh[1] + sh[2] + sh[3];
    float r = v / fmaxf(tot, 1e-12f);
    out[(size_t)row * OUTD + h] = r;
    feh[(size_t)row * OUTD + h] = __float2half_rn(r);
}

// ---------------- Adj fp32 -> fp16 -----------------------------------------
__global__ void k_cvt(const float4* __restrict__ src, __half* __restrict__ dst) {
    size_t i = (size_t)blockIdx.x * blockDim.x + threadIdx.x;
    float4 v = src[i];
    uint2 p = make_uint2(pack_h2(v.x, v.y), pack_h2(v.z, v.w));
    *reinterpret_cast<uint2*>(dst + 4 * i) = p;
}

// ---------------- weight transpose fp16: B[K][N] -> Bt[N][K] ---------------
__global__ void k_tsp(const float* __restrict__ B, __half* __restrict__ th,
                      int K, int N) {
    __shared__ float s[32][33];
    int n0 = blockIdx.x * 32, k0 = blockIdx.y * 32;
    int tx = threadIdx.x, ty = threadIdx.y;
#pragma unroll
    for (int i = 0; i < 32; i += 8)
        s[ty + i][tx] = B[(size_t)(k0 + ty + i) * N + n0 + tx];
    __syncthreads();
#pragma unroll
    for (int i = 0; i < 32; i += 8) {
        int n = n0 + ty + i, k = k0 + tx;
        th[(size_t)n * K + k] = __float2half_rn(s[tx][ty + i]);
    }
}

// ---------------- mma.sync + ldmatrix + cp.async plumbing ------------------
__device__ __forceinline__ uint32_t s2u(const void* p) {
    uint32_t a;
    asm("{ .reg .u64 t; cvta.to.shared.u64 t, %1; cvt.u32.u64 %0, t; }" : "=r"(a) : "l"(p));
    return a;
}
__device__ __forceinline__ void mma_f16(float* d, const uint32_t* a, const uint32_t* b) {
    asm volatile(
        "mma.sync.aligned.m16n8k16.row.col.f32.f16.f16.f32 "
        "{%0,%1,%2,%3}, {%4,%5,%6,%7}, {%8,%9}, {%0,%1,%2,%3};"
        : "+f"(d[0]), "+f"(d[1]), "+f"(d[2]), "+f"(d[3])
        : "r"(a[0]), "r"(a[1]), "r"(a[2]), "r"(a[3]), "r"(b[0]), "r"(b[1]));
}
__device__ __forceinline__ void ldsm4(uint32_t* r, uint32_t addr) {
    asm volatile("ldmatrix.sync.aligned.m8n8.x4.shared.b16 {%0,%1,%2,%3}, [%4];"
                 : "=r"(r[0]), "=r"(r[1]), "=r"(r[2]), "=r"(r[3]) : "r"(addr));
}
__device__ __forceinline__ void cpa16(uint32_t s, const void* g) {
    asm volatile("cp.async.cg.shared.global [%0], [%1], 16;" :: "r"(s), "l"(g));
}
#define CP_COMMIT() asm volatile("cp.async.commit_group;" ::: "memory")
#define CP_WAIT2()  asm volatile("cp.async.wait_group 2;" ::: "memory")

// ---------------- MLP GEMM: fp16 single-pass -------------------------------
#define TC_STAGE 32768u                // A 16KB, B 16KB
#define TC_SMEM  (3 * TC_STAGE)

template <int ACT, int OUT, bool HC>
__global__ void __launch_bounds__(256, 1)
k_tc(const __half* __restrict__ A_, const __half* __restrict__ Bh_,
     const float* __restrict__ bias, const float* __restrict__ Cin,
     float* __restrict__ Cf, __half* __restrict__ Oh, int N, int K) {
    extern __shared__ char smc[];
    const uint32_t sb = s2u(smc);
    const int tid = threadIdx.x, lane = tid & 31, warp = tid >> 5;
    const int wm = warp & 3, wn = warp >> 2;
    const int g = lane >> 2, tig = lane & 3;
    const int bm = blockIdx.y * 128, bn = blockIdx.x * 128;

    float c[2][8][4];
#pragma unroll
    for (int i = 0; i < 2; i++)
#pragma unroll
        for (int j = 0; j < 8; j++)
#pragma unroll
            for (int q = 0; q < 4; q++) c[i][j][q] = 0.f;

    auto load_stage = [&](int s) {
        const uint32_t st = sb + (uint32_t)(s % 3) * TC_STAGE;
        const int k0 = s * 64;
#pragma unroll
        for (int j = 0; j < 4; j++) {
            int cidx = tid + 256 * j;
            int row = cidx >> 3, kc = cidx & 7;
            uint32_t off = (uint32_t)(row * 128 + kc * 16);
            off ^= (off >> 3) & 0x70;
            size_t ga = (size_t)(bm + row) * K + k0 + kc * 8;
            size_t gb = (size_t)(bn + row) * K + k0 + kc * 8;
            cpa16(st + off, A_ + ga);
            cpa16(st + 16384 + off, Bh_ + gb);
        }
    };

    const int nst = K >> 6;
#pragma unroll
    for (int i = 0; i < 3; i++) {
        if (i < nst) load_stage(i);
        CP_COMMIT();
    }

    for (int s = 0; s < nst; s++) {
        CP_WAIT2();
        __syncthreads();
        const uint32_t st = sb + (uint32_t)(s % 3) * TC_STAGE;
#pragma unroll
        for (int kk = 0; kk < 64; kk += 16) {
            uint32_t ah[2][4], bh[8][2];
#pragma unroll
            for (int mt = 0; mt < 2; mt++) {
                int row = wm * 32 + mt * 16 + (lane & 15);
                uint32_t off = (uint32_t)(row * 128) + (uint32_t)(kk * 2) + (uint32_t)(lane & 16);
                off ^= (off >> 3) & 0x70;
                ldsm4(ah[mt], st + off);
            }
#pragma unroll
            for (int bt = 0; bt < 4; bt++) {
                int row = wn * 64 + bt * 16 + ((lane >> 4) << 3) + (lane & 7);
                uint32_t off = (uint32_t)(row * 128) + (uint32_t)(kk * 2) + (uint32_t)((lane & 8) << 1);
                off ^= (off >> 3) & 0x70;
                uint32_t r[4];
                ldsm4(r, st + 16384 + off);
                bh[2 * bt][0] = r[0]; bh[2 * bt][1] = r[1];
                bh[2 * bt + 1][0] = r[2]; bh[2 * bt + 1][1] = r[3];
            }
#pragma unroll
            for (int mt = 0; mt < 2; mt++)
#pragma unroll
                for (int nt = 0; nt < 8; nt++)
                    mma_f16(c[mt][nt], ah[mt], bh[nt]);
        }
        __syncthreads();
        if (s + 3 < nst) load_stage(s + 3);
        CP_COMMIT();
    }

    // epilogue
#pragma unroll
    for (int mt = 0; mt < 2; mt++) {
#pragma unroll
        for (int nt = 0; nt < 8; nt++) {
            int m0 = bm + wm * 32 + mt * 16 + g;
            int n0 = bn + wn * 64 + nt * 8 + 2 * tig;
            float2 v0 = make_float2(c[mt][nt][0], c[mt][nt][1]);
            float2 v1 = make_float2(c[mt][nt][2], c[mt][nt][3]);
            if (HC) {
                float2 ci0 = *reinterpret_cast<const float2*>(Cin + (size_t)m0 * N + n0);
                float2 ci1 = *reinterpret_cast<const float2*>(Cin + (size_t)(m0 + 8) * N + n0);
                v0.x += ci0.x; v0.y += ci0.y; v1.x += ci1.x; v1.y += ci1.y;
            }
            if (bias) {
                float bx = bias[n0], by = bias[n0 + 1];
                v0.x += bx; v0.y += by; v1.x += bx; v1.y += by;
            }
            if (ACT == 1) {
                v0.x = fmaxf(v0.x, 0.f); v0.y = fmaxf(v0.y, 0.f);
                v1.x = fmaxf(v1.x, 0.f); v1.y = fmaxf(v1.y, 0.f);
            } else if (ACT == 2) {
                v0.x = 1.f / (1.f + expf(-v0.x)); v0.y = 1.f / (1.f + expf(-v0.y));
                v1.x = 1.f / (1.f + expf(-v1.x)); v1.y = 1.f / (1.f + expf(-v1.y));
            }
            if (OUT == 0) {
                *reinterpret_cast<float2*>(Cf + (size_t)m0 * N + n0) = v0;
                *reinterpret_cast<float2*>(Cf + (size_t)(m0 + 8) * N + n0) = v1;
            } else {
                *reinterpret_cast<uint32_t*>(Oh + (size_t)m0 * N + n0) = pack_h2(v0.x, v0.y);
                *reinterpret_cast<uint32_t*>(Oh + (size_t)(m0 + 8) * N + n0) = pack_h2(v1.x, v1.y);
            }
        }
    }
}

// ---------------- orchestration ----------------
extern "C" void kernel_launch(void* const* d_in, const int* in_sizes, int n_in,
                              void* d_out, int out_size) {
    const float* hM  = (const float*)d_in[0];
    const float* hD  = (const float*)d_in[1];
    const float* hT  = (const float*)d_in[2];
    const float* W1  = (const float*)d_in[3];
    const float* b1  = (const float*)d_in[4];
    const float* W2  = (const float*)d_in[5];
    const float* b2  = (const float*)d_in[6];
    const float* W3  = (const float*)d_in[7];
    const float* b3  = (const float*)d_in[8];
    const float* Adj = (const float*)d_in[9];
    const float* f1w = (const float*)d_in[10];
    const float* f1b = (const float*)d_in[11];
    const float* f2w = (const float*)d_in[12];
    const float* f2b = (const float*)d_in[13];
    const float* f3w = (const float*)d_in[14];
    const float* f3b = (const float*)d_in[15];
    const float* f4w = (const float*)d_in[16];
    const float* f4b = (const float*)d_in[17];
    const int* edges = (const int*)d_in[18];

    float *p_node, *p_agg, *p_outinv, *p_ininv, *p_xs32, *p_x1f;
    __half *p_bth, *p_adjh, *p_feh, *p_x1h, *p_x2h, *p_x3h, *p_xsh;
    cudaGetSymbolAddress((void**)&p_node, g_node);
    cudaGetSymbolAddress((void**)&p_agg, g_agg);
    cudaGetSymbolAddress((void**)&p_outinv, g_outinv);
    cudaGetSymbolAddress((void**)&p_ininv, g_ininv);
    cudaGetSymbolAddress((void**)&p_xs32, g_xs32);
    cudaGetSymbolAddress((void**)&p_xsh, g_xsh);
    cudaGetSymbolAddress((void**)&p_bth, g_bth);
    cudaGetSymbolAddress((void**)&p_adjh, g_adjh);
    cudaGetSymbolAddress((void**)&p_feh, g_feh);
    cudaGetSymbolAddress((void**)&p_x1f, g_x1f);
    cudaGetSymbolAddress((void**)&p_x1h, g_x1h);
    cudaGetSymbolAddress((void**)&p_x2h, g_x2h);
    cudaGetSymbolAddress((void**)&p_x3h, g_x3h);

    float* fe   = (float*)d_out;                       // 4096 x 128
    float* outx = (float*)d_out + (size_t)MROW * OUTD; // 4096 x 8192

    static cudaStream_t s2 = nullptr;
    static cudaEvent_t evFork = nullptr, evJoin = nullptr;
    if (s2 == nullptr) {
        cudaStreamCreateWithFlags(&s2, cudaStreamNonBlocking);
        cudaEventCreateWithFlags(&evFork, cudaEventDisableTiming);
        cudaEventCreateWithFlags(&evJoin, cudaEventDisableTiming);
        cudaFuncSetAttribute(k_tc<0, 0, false>, cudaFuncAttributeMaxDynamicSharedMemorySize, TC_SMEM);
        cudaFuncSetAttribute(k_tc<1, 1, true>,  cudaFuncAttributeMaxDynamicSharedMemorySize, TC_SMEM);
        cudaFuncSetAttribute(k_tc<1, 1, false>, cudaFuncAttributeMaxDynamicSharedMemorySize, TC_SMEM);
        cudaFuncSetAttribute(k_tc<2, 0, false>, cudaFuncAttributeMaxDynamicSharedMemorySize, TC_SMEM);
        cudaFuncSetAttribute(k_count, cudaFuncAttributeMaxDynamicSharedMemorySize, 2 * NN * 4);
    }

    // ---- fork side stream: MLP prep + Adj GEMM (independent of GNN) ----
    cudaEventRecord(evFork, 0);
    cudaStreamWaitEvent(s2, evFork, 0);
    k_cvt<<<(MROW * ITEM / 4) / 256, 256, 0, s2>>>((const float4*)Adj, p_adjh);
    k_tsp<<<dim3(256 / 32, 8192 / 32), dim3(32, 8), 0, s2>>>(f1w, p_bth + O1A, 8192, 256);
    k_tsp<<<dim3(256 / 32, 128 / 32),  dim3(32, 8), 0, s2>>>(f1w + (size_t)ITEM * 256, p_bth + O1B, 128, 256);
    k_tsp<<<dim3(512 / 32, 256 / 32),  dim3(32, 8), 0, s2>>>(f2w, p_bth + O2, 256, 512);
    k_tsp<<<dim3(1024 / 32, 512 / 32), dim3(32, 8), 0, s2>>>(f3w, p_bth + O3, 512, 1024);
    k_tsp<<<dim3(8192 / 32, 1024 / 32), dim3(32, 8), 0, s2>>>(f4w, p_bth + O4, 1024, 8192);
    // f1 Adj-partial (fp32): x1f = Adj @ f1w_top
    k_tc<0, 0, false><<<dim3(2, 32), 256, TC_SMEM, s2>>>(
        p_adjh, p_bth + O1A, nullptr, nullptr, p_x1f, nullptr, 256, 8192);
    cudaEventRecord(evJoin, s2);

    // ---- main stream: CSR + GNN trunk ----
    k_zero_counts<<<(NREL * NN + 255) / 256, 256>>>();
    k_count<<<dim3(CB, NREL), 512, 2 * NN * 4>>>(edges);
    k_scan<<<NREL, 1024>>>();
    k_fill<<<(NREL * NE / 4 + 255) / 256, 256>>>(edges);

    k_conv_b<__half><<<dim3(1, NN / 64, 6), 256>>>(hM, hD, hT, W1, p_outinv, 256, 64,
                                                   p_xsh, (size_t)NN * 64);
    k_agg_v<<<dim3(NN / 16, 3), dim3(16, 16)>>>(b1);

    k_conv_b<__half><<<dim3(1, NN / 64, 6), 256>>>(p_node, p_node + (size_t)NN * 128,
                                                   p_node + (size_t)2 * NN * 128, W2,
                                                   p_outinv, 64, 64, p_xsh, (size_t)NN * 64);
    k_agg_v<<<dim3(NN / 16, 3), dim3(16, 16)>>>(b2);

    k_aggpre<<<dim3(NN / 16, 6), dim3(16, 16)>>>();
    k_conv_b<float><<<dim3(2, NN / 64, 6), 256>>>(p_agg, nullptr, nullptr, W3, p_ininv,
                                                  64, 128, p_xs32, (size_t)NN * 128);
    k_addb<<<dim3(NN * 128 / 4 / 256, 3), 256>>>(b3);

    k_l1norm<<<MROW, 128>>>(fe, p_feh);

    // ---- join: f1b needs x1f + transposed weights from s2 ----
    cudaStreamWaitEvent(0, evJoin, 0);

    // x1 = relu(fe @ f1w_bot + x1f + f1b)
    k_tc<1, 1, true><<<dim3(2, 32), 256, TC_SMEM>>>(
        p_feh, p_bth + O1B, f1b, p_x1f, nullptr, p_x1h, 256, 128);
    k_tc<1, 1, false><<<dim3(4, 32), 256, TC_SMEM>>>(
        p_x1h, p_bth + O2, f2b, nullptr, nullptr, p_x2h, 512, 256);
    k_tc<1, 1, false><<<dim3(8, 32), 256, TC_SMEM>>>(
        p_x2h, p_bth + O3, f3b, nullptr, nullptr, p_x3h, 1024, 512);
    k_tc<2, 0, false><<<dim3(64, 32), 256, TC_SMEM>>>(
        p_x3h, p_bth + O4, f4b, nullptr, outx, nullptr, 8192, 1024);
}

// round 11
// speedup vs baseline: 6.2749x; 1.0968x over previous
#include <cuda_runtime.h>
#include <cuda_fp16.h>
#include <stdint.h>
#include <math.h>

#define NN   8192
#define NE   500000
#define NREL 6
#define FEAT 256
#define HIDD 64
#define OUTD 128
#define MROW 4096   // SIZE
#define ITEM 8192
#define CB   8      // count blocks per relation

// ---------------- scratch (device globals: allocation-free) ----------------
__device__ int   g_outcnt[NREL][NN];
__device__ int   g_incnt [NREL][NN];
__device__ float g_outinv[NREL][NN];
__device__ float g_ininv [NREL][NN];
__device__ int   g_rowptr[NREL][NN + 1];
__device__ int   g_fill  [NREL][NN];
__device__ int   g_srcs  [NREL][NE];
__device__ __half g_xsh [NREL][NN * 64];    // layers 1-2 conv outputs (gathered)
__device__ float g_xs32 [NREL][NN * 128];   // layer-3 conv outputs (fp32)
__device__ float g_agg  [NREL][NN * 64];    // layer-3 pre-aggregated inputs
__device__ float g_node [3][NN * 128];      // trunk state fp32
__device__ __half g_nodeh[3][NN * 64];      // fp16 shadow for layer-3 gather

// pre-transposed fp16 weights: Bt[n][k] per matrix, offsets below
#define O1A 0                            // f1w top^T [256][8192]
#define O1B 2097152                      // f1w bot^T [256][128]
#define O2  2129920                      // f2w^T     [512][256]
#define O3  2260992                      // f3w^T     [1024][512]
#define O4  2785280                      // f4w^T     [8192][1024]
#define BT_TOTAL 11173888
__device__ __half g_bth[BT_TOTAL];

// fp16 activations
__device__ __half g_adjh[(size_t)MROW * ITEM];
__device__ __half g_feh[MROW * OUTD];
__device__ float  g_x1f[MROW * 256];        // f1 Adj-partial (fp32)
__device__ __half g_x1h[MROW * 256];
__device__ __half g_x2h[MROW * 512];
__device__ __half g_x3h[MROW * 1024];

// ---------------- fp16 helpers ----------------
__device__ __forceinline__ uint32_t pack_h2(float x, float y) {
    __half2 h = __floats2half2_rn(x, y);
    return *reinterpret_cast<uint32_t*>(&h);
}
__device__ __forceinline__ float4 h4tof4(uint2 u) {
    float2 a = __half22float2(*reinterpret_cast<__half2*>(&u.x));
    float2 b = __half22float2(*reinterpret_cast<__half2*>(&u.y));
    return make_float4(a.x, a.y, b.x, b.y);
}
__device__ __forceinline__ void store4(float* p, float a, float b, float c, float d) {
    *reinterpret_cast<float4*>(p) = make_float4(a, b, c, d);
}
__device__ __forceinline__ void store4(__half* p, float a, float b, float c, float d) {
    *reinterpret_cast<uint2*>(p) = make_uint2(pack_h2(a, b), pack_h2(c, d));
}

// ---------------- CSR build ----------------
__global__ void k_zero_counts() {
    int i = blockIdx.x * blockDim.x + threadIdx.x;
    if (i < NREL * NN) {
        ((int*)g_outcnt)[i] = 0;
        ((int*)g_incnt)[i]  = 0;
    }
}

__global__ void k_count(const int* __restrict__ edges) {
    extern __shared__ int smcnt[];            // [2*NN]
    const int r = blockIdx.y, b = blockIdx.x;
    int* so = smcnt;
    int* si = smcnt + NN;
    for (int i = threadIdx.x; i < 2 * NN; i += blockDim.x) smcnt[i] = 0;
    __syncthreads();
    const int per = NE / CB;
    const int e0 = b * per;
    const int* es = edges + (size_t)r * 2 * NE;
    for (int e = e0 + threadIdx.x * 4; e < e0 + per; e += blockDim.x * 4) {
        int4 s = *reinterpret_cast<const int4*>(es + e);
        int4 d = *reinterpret_cast<const int4*>(es + NE + e);
        atomicAdd(&so[s.x], 1); atomicAdd(&so[s.y], 1);
        atomicAdd(&so[s.z], 1); atomicAdd(&so[s.w], 1);
        atomicAdd(&si[d.x], 1); atomicAdd(&si[d.y], 1);
        atomicAdd(&si[d.z], 1); atomicAdd(&si[d.w], 1);
    }
    __syncthreads();
    for (int i = threadIdx.x; i < NN; i += blockDim.x) {
        int v = so[i];
        if (v) atomicAdd(&g_outcnt[r][i], v);
        v = si[i];
        if (v) atomicAdd(&g_incnt[r][i], v);
    }
}

__global__ void k_scan() {
    int r = blockIdx.x;
    int tid = threadIdx.x;          // 1024 threads
    int base = tid * 8;
    int c[8];
    int s = 0;
#pragma unroll
    for (int i = 0; i < 8; i++) { c[i] = g_incnt[r][base + i]; s += c[i]; }

    int lane = tid & 31, w = tid >> 5;
    int incl = s;
#pragma unroll
    for (int o = 1; o < 32; o <<= 1) {
        int v = __shfl_up_sync(0xffffffffu, incl, o);
        if (lane >= o) incl += v;
    }
    __shared__ int wsum[32];
    if (lane == 31) wsum[w] = incl;
    __syncthreads();
    if (w == 0) {
        int v = wsum[lane];
#pragma unroll
        for (int o = 1; o < 32; o <<= 1) {
            int t = __shfl_up_sync(0xffffffffu, v, o);
            if (lane >= o) v += t;
        }
        wsum[lane] = v;
    }
    __syncthreads();
    int excl = (incl - s) + (w > 0 ? wsum[w - 1] : 0);
    int run = excl;
#pragma unroll
    for (int i = 0; i < 8; i++) {
        g_rowptr[r][base + i] = run;
        g_fill[r][base + i]   = run;
        run += c[i];
        int ic = c[i] > 0 ? c[i] : 1;
        g_ininv[r][base + i] = rsqrtf((float)ic);
        int oc = g_outcnt[r][base + i];
        if (oc < 1) oc = 1;
        g_outinv[r][base + i] = rsqrtf((float)oc);
    }
    if (tid == 1023) g_rowptr[r][NN] = run;
}

__global__ void k_fill(const int* __restrict__ edges) {
    int i = (blockIdx.x * blockDim.x + threadIdx.x) * 4;
    if (i >= NREL * NE) return;
    int r = i / NE, e = i - r * NE;
    int4 src = *reinterpret_cast<const int4*>(edges + (size_t)r * 2 * NE + e);
    int4 dst = *reinterpret_cast<const int4*>(edges + (size_t)r * 2 * NE + NE + e);
    g_srcs[r][atomicAdd(&g_fill[r][dst.x], 1)] = src.x;
    g_srcs[r][atomicAdd(&g_fill[r][dst.y], 1)] = src.y;
    g_srcs[r][atomicAdd(&g_fill[r][dst.z], 1)] = src.z;
    g_srcs[r][atomicAdd(&g_fill[r][dst.w], 1)] = src.w;
}

// ---------------- conv GEMM batched over relations --------------------------
// relation r = (rpat >> 4*blockIdx.z) & 0xF (liveness-pruned relation sets)
template <typename T>
__global__ void k_conv_b(const float* __restrict__ A0, const float* __restrict__ A1,
                         const float* __restrict__ A2, const float* __restrict__ Wb,
                         const float* __restrict__ scaleb, int K, int Nh,
                         T* __restrict__ xsbase, size_t xstride, uint32_t rpat) {
    const int r = (rpat >> (4 * blockIdx.z)) & 0xF;
    const int smap[6] = {0, 1, 0, 2, 2, 1};
    const float* A;
    if (A1 == nullptr) {
        A = A0 + (size_t)r * NN * K;
    } else {
        int si = smap[r];
        A = (si == 0) ? A0 : (si == 1) ? A1 : A2;
    }
    const float* W = Wb + (size_t)r * K * Nh;
    T* Xs = xsbase + (size_t)r * xstride;
    const float* scale = scaleb + r * NN;

    __shared__ float As[16][64];
    __shared__ float Bs[16][64];
    int tid = threadIdx.x;
    int bx = blockIdx.x, by = blockIdx.y;
    int aRow = tid >> 2, aCol = (tid & 3) * 4;
    int bRow = tid >> 4, bCol = (tid & 15) * 4;
    int tx = tid & 15, ty = tid >> 4;
    float acc[4][4] = {};
    const float* Ap = A + (size_t)(by * 64) * K;
    float scl = scale[by * 64 + aRow];

    for (int k0 = 0; k0 < K; k0 += 16) {
        float4 av = *(const float4*)(Ap + (size_t)aRow * K + k0 + aCol);
        As[aCol + 0][aRow] = av.x * scl;
        As[aCol + 1][aRow] = av.y * scl;
        As[aCol + 2][aRow] = av.z * scl;
        As[aCol + 3][aRow] = av.w * scl;
        float4 bv = *(const float4*)(W + (size_t)(k0 + bRow) * Nh + bx * 64 + bCol);
        *(float4*)&Bs[bRow][bCol] = bv;
        __syncthreads();
#pragma unroll
        for (int kk = 0; kk < 16; kk++) {
            float a[4], b[4];
#pragma unroll
            for (int i = 0; i < 4; i++) a[i] = As[kk][ty * 4 + i];
#pragma unroll
            for (int j = 0; j < 4; j++) b[j] = Bs[kk][tx * 4 + j];
#pragma unroll
            for (int i = 0; i < 4; i++)
#pragma unroll
                for (int j = 0; j < 4; j++) acc[i][j] += a[i] * b[j];
        }
        __syncthreads();
    }
    int row0 = by * 64 + ty * 4, col0 = bx * 64 + tx * 4;
#pragma unroll
    for (int i = 0; i < 4; i++)
        store4(Xs + (size_t)(row0 + i) * Nh + col0,
               acc[i][0], acc[i][1], acc[i][2], acc[i][3]);
}

// ---------------- aggregation helpers ----------------
__device__ __forceinline__ float4 f4add(float4 a, float4 b) {
    a.x += b.x; a.y += b.y; a.z += b.z; a.w += b.w; return a;
}
__device__ __forceinline__ float4 f4fma(float4 a, float s, float4 acc) {
    acc.x += a.x * s; acc.y += a.y * s; acc.z += a.z * s; acc.w += a.w * s; return acc;
}

// post-GEMM agg: t = tbase + blockIdx.y (layer 1: all 3; layer 2: D,T only)
__global__ void k_agg_v(const float* __restrict__ bias, int tbase) {
    const int t = tbase + blockIdx.y;
    const int n = blockIdx.x * blockDim.y + threadIdx.y;
    const int lane = threadIdx.x;     // 0..15
    const int RA[3] = {1, 0, 2};
    const int RB[3] = {3, 4, 5};
    int rel[2] = {RA[t], RB[t]};
    float4 acc = f4add(reinterpret_cast<const float4*>(bias + rel[0] * 64)[lane],
                       reinterpret_cast<const float4*>(bias + rel[1] * 64)[lane]);
#pragma unroll
    for (int rr = 0; rr < 2; rr++) {
        int r = rel[rr];
        int e0 = g_rowptr[r][n], e1 = g_rowptr[r][n + 1];
        const __half* xs = g_xsh[r];
        const int* srcs = g_srcs[r];
        float4 s = make_float4(0.f, 0.f, 0.f, 0.f);
        int e = e0;
        for (; e + 7 < e1; e += 8) {
            uint2 u0 = reinterpret_cast<const uint2*>(xs + (size_t)srcs[e] * 64)[lane];
            uint2 u1 = reinterpret_cast<const uint2*>(xs + (size_t)srcs[e + 1] * 64)[lane];
            uint2 u2 = reinterpret_cast<const uint2*>(xs + (size_t)srcs[e + 2] * 64)[lane];
            uint2 u3 = reinterpret_cast<const uint2*>(xs + (size_t)srcs[e + 3] * 64)[lane];
            uint2 u4 = reinterpret_cast<const uint2*>(xs + (size_t)srcs[e + 4] * 64)[lane];
            uint2 u5 = reinterpret_cast<const uint2*>(xs + (size_t)srcs[e + 5] * 64)[lane];
            uint2 u6 = reinterpret_cast<const uint2*>(xs + (size_t)srcs[e + 6] * 64)[lane];
            uint2 u7 = reinterpret_cast<const uint2*>(xs + (size_t)srcs[e + 7] * 64)[lane];
            s = f4add(s, f4add(f4add(h4tof4(u0), h4tof4(u1)),
                               f4add(h4tof4(u2), h4tof4(u3))));
            s = f4add(s, f4add(f4add(h4tof4(u4), h4tof4(u5)),
                               f4add(h4tof4(u6), h4tof4(u7))));
        }
        for (; e < e1; e++) {
            uint2 u = reinterpret_cast<const uint2*>(xs + (size_t)srcs[e] * 64)[lane];
            s = f4add(s, h4tof4(u));
        }
        acc = f4fma(s, g_ininv[r][n], acc);
    }
    reinterpret_cast<float4*>(g_node[t] + (size_t)n * 64)[lane] = acc;
    reinterpret_cast<uint2*>(g_nodeh[t] + (size_t)n * 64)[lane] =
        make_uint2(pack_h2(acc.x, acc.y), pack_h2(acc.z, acc.w));
}

// pre-GEMM agg (layer 3): only relations {1,3} feed hM3 (others dead)
__global__ void k_aggpre() {
    const int r = 1 + 2 * blockIdx.y;           // 1, 3
    const int n = blockIdx.x * blockDim.y + threadIdx.y;
    const int lane = threadIdx.x;     // 0..15
    const int smap[6] = {0, 1, 0, 2, 2, 1};
    const __half* x = g_nodeh[smap[r]];
    const float* oi = g_outinv[r];
    const int* srcs = g_srcs[r];
    int e0 = g_rowptr[r][n], e1 = g_rowptr[r][n + 1];
    float4 acc = make_float4(0.f, 0.f, 0.f, 0.f);
    int e = e0;
    for (; e + 3 < e1; e += 4) {
        int s0 = srcs[e], s1 = srcs[e + 1], s2 = srcs[e + 2], s3 = srcs[e + 3];
        uint2 u0 = reinterpret_cast<const uint2*>(x + (size_t)s0 * 64)[lane];
        uint2 u1 = reinterpret_cast<const uint2*>(x + (size_t)s1 * 64)[lane];
        uint2 u2 = reinterpret_cast<const uint2*>(x + (size_t)s2 * 64)[lane];
        uint2 u3 = reinterpret_cast<const uint2*>(x + (size_t)s3 * 64)[lane];
        acc = f4fma(h4tof4(u0), oi[s0], acc);
        acc = f4fma(h4tof4(u1), oi[s1], acc);
        acc = f4fma(h4tof4(u2), oi[s2], acc);
        acc = f4fma(h4tof4(u3), oi[s3], acc);
    }
    for (; e < e1; e++) {
        int s0 = srcs[e];
        uint2 u0 = reinterpret_cast<const uint2*>(x + (size_t)s0 * 64)[lane];
        acc = f4fma(h4tof4(u0), oi[s0], acc);
    }
    reinterpret_cast<float4*>(g_agg[r] + (size_t)n * 64)[lane] = acc;
}

// layer-3 combine (only hM3 live): node[0] = xs32[1] + xs32[3] + b[1] + b[3]
__global__ void k_addb(const float* __restrict__ bias) {
    int i = blockIdx.x * blockDim.x + threadIdx.x;   // over NN*128/4
    int h = (i & 31);                                 // float4 col index
    float4 a = reinterpret_cast<const float4*>(g_xs32[1])[i];
    float4 b = reinterpret_cast<const float4*>(g_xs32[3])[i];
    float4 ba = reinterpret_cast<const float4*>(bias + 1 * 128)[h];
    float4 bb = reinterpret_cast<const float4*>(bias + 3 * 128)[h];
    float4 o;
    o.x = a.x + b.x + ba.x + bb.x;
    o.y = a.y + b.y + ba.y + bb.y;
    o.z = a.z + b.z + ba.z + bb.z;
    o.w = a.w + b.w + ba.w + bb.w;
    reinterpret_cast<float4*>(g_node[0])[i] = o;
}

// ---------------- row L1-normalize hM3[0:4096] -> fe (f32) + fp16 ----------
__global__ void k_l1norm(float* __restrict__ out, __half* __restrict__ feh) {
    int row = blockIdx.x;
    int h = threadIdx.x;  // 128
    float v = g_node[0][(size_t)row * OUTD + h];
    float a = fabsf(v);
#pragma unroll
    for (int o = 16; o > 0; o >>= 1) a += __shfl_xor_sync(0xffffffffu, a, o);
    __shared__ float sh[4];
    if ((h & 31) == 0) sh[h >> 5] = a;
    __syncthreads();
    float tot = sh[0] + sh[1] + sh[2] + sh[3];
    float r = v / fmaxf(tot, 1e-12f);
    out[(size_t)row * OUTD + h] = r;
    feh[(size_t)row * OUTD + h] = __float2half_rn(r);
}

// ---------------- Adj fp32 -> fp16 -----------------------------------------
__global__ void k_cvt(const float4* __restrict__ src, __half* __restrict__ dst) {
    size_t i = (size_t)blockIdx.x * blockDim.x + threadIdx.x;
    float4 v = src[i];
    uint2 p = make_uint2(pack_h2(v.x, v.y), pack_h2(v.z, v.w));
    *reinterpret_cast<uint2*>(dst + 4 * i) = p;
}

// ---------------- weight transpose fp16: B[K][N] -> Bt[N][K] ---------------
__global__ void k_tsp(const float* __restrict__ B, __half* __restrict__ th,
                      int K, int N) {
    __shared__ float s[32][33];
    int n0 = blockIdx.x * 32, k0 = blockIdx.y * 32;
    int tx = threadIdx.x, ty = threadIdx.y;
#pragma unroll
    for (int i = 0; i < 32; i += 8)
        s[ty + i][tx] = B[(size_t)(k0 + ty + i) * N + n0 + tx];
    __syncthreads();
#pragma unroll
    for (int i = 0; i < 32; i += 8) {
        int n = n0 + ty + i, k = k0 + tx;
        th[(size_t)n * K + k] = __float2half_rn(s[tx][ty + i]);
    }
}

// ---------------- mma.sync + ldmatrix + cp.async plumbing ------------------
__device__ __forceinline__ uint32_t s2u(const void* p) {
    uint32_t a;
    asm("{ .reg .u64 t; cvta.to.shared.u64 t, %1; cvt.u32.u64 %0, t; }" : "=r"(a) : "l"(p));
    return a;
}
__device__ __forceinline__ void mma_f16(float* d, const uint32_t* a, const uint32_t* b) {
    asm volatile(
        "mma.sync.aligned.m16n8k16.row.col.f32.f16.f16.f32 "
        "{%0,%1,%2,%3}, {%4,%5,%6,%7}, {%8,%9}, {%0,%1,%2,%3};"
        : "+f"(d[0]), "+f"(d[1]), "+f"(d[2]), "+f"(d[3])
        : "r"(a[0]), "r"(a[1]), "r"(a[2]), "r"(a[3]), "r"(b[0]), "r"(b[1]));
}
__device__ __forceinline__ void ldsm4(uint32_t* r, uint32_t addr) {
    asm volatile("ldmatrix.sync.aligned.m8n8.x4.shared.b16 {%0,%1,%2,%3}, [%4];"
                 : "=r"(r[0]), "=r"(r[1]), "=r"(r[2]), "=r"(r[3]) : "r"(addr));
}
__device__ __forceinline__ void cpa16(uint32_t s, const void* g) {
    asm volatile("cp.async.cg.shared.global [%0], [%1], 16;" :: "r"(s), "l"(g));
}
#define CP_COMMIT() asm volatile("cp.async.commit_group;" ::: "memory")
#define CP_WAIT2()  asm volatile("cp.async.wait_group 2;" ::: "memory")

// ---------------- MLP GEMM: fp16 single-pass -------------------------------
#define TC_STAGE 32768u                // A 16KB, B 16KB
#define TC_SMEM  (3 * TC_STAGE)

template <int ACT, int OUT, bool HC>
__global__ void __launch_bounds__(256, 1)
k_tc(const __half* __restrict__ A_, const __half* __restrict__ Bh_,
     const float* __restrict__ bias, const float* __restrict__ Cin,
     float* __restrict__ Cf, __half* __restrict__ Oh, int N, int K) {
    extern __shared__ char smc[];
    const uint32_t sb = s2u(smc);
    const int tid = threadIdx.x, lane = tid & 31, warp = tid >> 5;
    const int wm = warp & 3, wn = warp >> 2;
    const int g = lane >> 2, tig = lane & 3;
    const int bm = blockIdx.y * 128, bn = blockIdx.x * 128;

    float c[2][8][4];
#pragma unroll
    for (int i = 0; i < 2; i++)
#pragma unroll
        for (int j = 0; j < 8; j++)
#pragma unroll
            for (int q = 0; q < 4; q++) c[i][j][q] = 0.f;

    auto load_stage = [&](int s) {
        const uint32_t st = sb + (uint32_t)(s % 3) * TC_STAGE;
        const int k0 = s * 64;
#pragma unroll
        for (int j = 0; j < 4; j++) {
            int cidx = tid + 256 * j;
            int row = cidx >> 3, kc = cidx & 7;
            uint32_t off = (uint32_t)(row * 128 + kc * 16);
            off ^= (off >> 3) & 0x70;
            size_t ga = (size_t)(bm + row) * K + k0 + kc * 8;
            size_t gb = (size_t)(bn + row) * K + k0 + kc * 8;
            cpa16(st + off, A_ + ga);
            cpa16(st + 16384 + off, Bh_ + gb);
        }
    };

    const int nst = K >> 6;
#pragma unroll
    for (int i = 0; i < 3; i++) {
        if (i < nst) load_stage(i);
        CP_COMMIT();
    }

    for (int s = 0; s < nst; s++) {
        CP_WAIT2();
        __syncthreads();
        const uint32_t st = sb + (uint32_t)(s % 3) * TC_STAGE;
#pragma unroll
        for (int kk = 0; kk < 64; kk += 16) {
            uint32_t ah[2][4], bh[8][2];
#pragma unroll
            for (int mt = 0; mt < 2; mt++) {
                int row = wm * 32 + mt * 16 + (lane & 15);
                uint32_t off = (uint32_t)(row * 128) + (uint32_t)(kk * 2) + (uint32_t)(lane & 16);
                off ^= (off >> 3) & 0x70;
                ldsm4(ah[mt], st + off);
            }
#pragma unroll
            for (int bt = 0; bt < 4; bt++) {
                int row = wn * 64 + bt * 16 + ((lane >> 4) << 3) + (lane & 7);
                uint32_t off = (uint32_t)(row * 128) + (uint32_t)(kk * 2) + (uint32_t)((lane & 8) << 1);
                off ^= (off >> 3) & 0x70;
                uint32_t r[4];
                ldsm4(r, st + 16384 + off);
                bh[2 * bt][0] = r[0]; bh[2 * bt][1] = r[1];
                bh[2 * bt + 1][0] = r[2]; bh[2 * bt + 1][1] = r[3];
            }
#pragma unroll
            for (int mt = 0; mt < 2; mt++)
#pragma unroll
                for (int nt = 0; nt < 8; nt++)
                    mma_f16(c[mt][nt], ah[mt], bh[nt]);
        }
        __syncthreads();
        if (s + 3 < nst) load_stage(s + 3);
        CP_COMMIT();
    }

    // epilogue
#pragma unroll
    for (int mt = 0; mt < 2; mt++) {
#pragma unroll
        for (int nt = 0; nt < 8; nt++) {
            int m0 = bm + wm * 32 + mt * 16 + g;
            int n0 = bn + wn * 64 + nt * 8 + 2 * tig;
            float2 v0 = make_float2(c[mt][nt][0], c[mt][nt][1]);
            float2 v1 = make_float2(c[mt][nt][2], c[mt][nt][3]);
            if (HC) {
                float2 ci0 = *reinterpret_cast<const float2*>(Cin + (size_t)m0 * N + n0);
                float2 ci1 = *reinterpret_cast<const float2*>(Cin + (size_t)(m0 + 8) * N + n0);
                v0.x += ci0.x; v0.y += ci0.y; v1.x += ci1.x; v1.y += ci1.y;
            }
            if (bias) {
                float bx = bias[n0], by = bias[n0 + 1];
                v0.x += bx; v0.y += by; v1.x += bx; v1.y += by;
            }
            if (ACT == 1) {
                v0.x = fmaxf(v0.x, 0.f); v0.y = fmaxf(v0.y, 0.f);
                v1.x = fmaxf(v1.x, 0.f); v1.y = fmaxf(v1.y, 0.f);
            } else if (ACT == 2) {
                v0.x = 1.f / (1.f + expf(-v0.x)); v0.y = 1.f / (1.f + expf(-v0.y));
                v1.x = 1.f / (1.f + expf(-v1.x)); v1.y = 1.f / (1.f + expf(-v1.y));
            }
            if (OUT == 0) {
                *reinterpret_cast<float2*>(Cf + (size_t)m0 * N + n0) = v0;
                *reinterpret_cast<float2*>(Cf + (size_t)(m0 + 8) * N + n0) = v1;
            } else {
                *reinterpret_cast<uint32_t*>(Oh + (size_t)m0 * N + n0) = pack_h2(v0.x, v0.y);
                *reinterpret_cast<uint32_t*>(Oh + (size_t)(m0 + 8) * N + n0) = pack_h2(v1.x, v1.y);
            }
        }
    }
}

// ---------------- orchestration ----------------
extern "C" void kernel_launch(void* const* d_in, const int* in_sizes, int n_in,
                              void* d_out, int out_size) {
    const float* hM  = (const float*)d_in[0];
    const float* hD  = (const float*)d_in[1];
    const float* hT  = (const float*)d_in[2];
    const float* W1  = (const float*)d_in[3];
    const float* b1  = (const float*)d_in[4];
    const float* W2  = (const float*)d_in[5];
    const float* b2  = (const float*)d_in[6];
    const float* W3  = (const float*)d_in[7];
    const float* b3  = (const float*)d_in[8];
    const float* Adj = (const float*)d_in[9];
    const float* f1w = (const float*)d_in[10];
    const float* f1b = (const float*)d_in[11];
    const float* f2w = (const float*)d_in[12];
    const float* f2b = (const float*)d_in[13];
    const float* f3w = (const float*)d_in[14];
    const float* f3b = (const float*)d_in[15];
    const float* f4w = (const float*)d_in[16];
    const float* f4b = (const float*)d_in[17];
    const int* edges = (const int*)d_in[18];

    float *p_node, *p_agg, *p_outinv, *p_ininv, *p_xs32, *p_x1f;
    __half *p_bth, *p_adjh, *p_feh, *p_x1h, *p_x2h, *p_x3h, *p_xsh;
    cudaGetSymbolAddress((void**)&p_node, g_node);
    cudaGetSymbolAddress((void**)&p_agg, g_agg);
    cudaGetSymbolAddress((void**)&p_outinv, g_outinv);
    cudaGetSymbolAddress((void**)&p_ininv, g_ininv);
    cudaGetSymbolAddress((void**)&p_xs32, g_xs32);
    cudaGetSymbolAddress((void**)&p_xsh, g_xsh);
    cudaGetSymbolAddress((void**)&p_bth, g_bth);
    cudaGetSymbolAddress((void**)&p_adjh, g_adjh);
    cudaGetSymbolAddress((void**)&p_feh, g_feh);
    cudaGetSymbolAddress((void**)&p_x1f, g_x1f);
    cudaGetSymbolAddress((void**)&p_x1h, g_x1h);
    cudaGetSymbolAddress((void**)&p_x2h, g_x2h);
    cudaGetSymbolAddress((void**)&p_x3h, g_x3h);

    float* fe   = (float*)d_out;                       // 4096 x 128
    float* outx = (float*)d_out + (size_t)MROW * OUTD; // 4096 x 8192

    static cudaStream_t s2 = nullptr, s3 = nullptr;
    static cudaEvent_t evFork = nullptr, evJoin = nullptr, evScan = nullptr, evFill = nullptr;
    if (s2 == nullptr) {
        cudaStreamCreateWithFlags(&s2, cudaStreamNonBlocking);
        cudaStreamCreateWithFlags(&s3, cudaStreamNonBlocking);
        cudaEventCreateWithFlags(&evFork, cudaEventDisableTiming);
        cudaEventCreateWithFlags(&evJoin, cudaEventDisableTiming);
        cudaEventCreateWithFlags(&evScan, cudaEventDisableTiming);
        cudaEventCreateWithFlags(&evFill, cudaEventDisableTiming);
        cudaFuncSetAttribute(k_tc<0, 0, false>, cudaFuncAttributeMaxDynamicSharedMemorySize, TC_SMEM);
        cudaFuncSetAttribute(k_tc<1, 1, true>,  cudaFuncAttributeMaxDynamicSharedMemorySize, TC_SMEM);
        cudaFuncSetAttribute(k_tc<1, 1, false>, cudaFuncAttributeMaxDynamicSharedMemorySize, TC_SMEM);
        cudaFuncSetAttribute(k_tc<2, 0, false>, cudaFuncAttributeMaxDynamicSharedMemorySize, TC_SMEM);
        cudaFuncSetAttribute(k_count, cudaFuncAttributeMaxDynamicSharedMemorySize, 2 * NN * 4);
    }

    // ---- fork s2: MLP prep + Adj GEMM (independent of GNN) ----
    cudaEventRecord(evFork, 0);
    cudaStreamWaitEvent(s2, evFork, 0);
    k_cvt<<<(MROW * ITEM / 4) / 256, 256, 0, s2>>>((const float4*)Adj, p_adjh);
    k_tsp<<<dim3(256 / 32, 8192 / 32), dim3(32, 8), 0, s2>>>(f1w, p_bth + O1A, 8192, 256);
    k_tsp<<<dim3(256 / 32, 128 / 32),  dim3(32, 8), 0, s2>>>(f1w + (size_t)ITEM * 256, p_bth + O1B, 128, 256);
    k_tsp<<<dim3(512 / 32, 256 / 32),  dim3(32, 8), 0, s2>>>(f2w, p_bth + O2, 256, 512);
    k_tsp<<<dim3(1024 / 32, 512 / 32), dim3(32, 8), 0, s2>>>(f3w, p_bth + O3, 512, 1024);
    k_tsp<<<dim3(8192 / 32, 1024 / 32), dim3(32, 8), 0, s2>>>(f4w, p_bth + O4, 1024, 8192);
    k_tc<0, 0, false><<<dim3(2, 32), 256, TC_SMEM, s2>>>(
        p_adjh, p_bth + O1A, nullptr, nullptr, p_x1f, nullptr, 256, 8192);
    cudaEventRecord(evJoin, s2);

    // ---- main stream: CSR counts + scan ----
    k_zero_counts<<<(NREL * NN + 255) / 256, 256>>>();
    k_count<<<dim3(CB, NREL), 512, 2 * NN * 4>>>(edges);
    k_scan<<<NREL, 1024>>>();
    cudaEventRecord(evScan, 0);

    // ---- fork s3: CSR fill (needed only by gathers) ----
    cudaStreamWaitEvent(s3, evScan, 0);
    k_fill<<<(NREL * NE / 4 + 255) / 256, 256, 0, s3>>>(edges);
    cudaEventRecord(evFill, s3);

    // ---- main: layer-1 conv overlaps fill ----
    k_conv_b<__half><<<dim3(1, NN / 64, 6), 256>>>(hM, hD, hT, W1, p_outinv, 256, 64,
                                                   p_xsh, (size_t)NN * 64, 0x543210u);
    cudaStreamWaitEvent(0, evFill, 0);
    k_agg_v<<<dim3(NN / 16, 3), dim3(16, 16)>>>(b1, 0);

    // layer 2: only relations {0,2,4,5}, targets {D,T} (hM2 dead)
    k_conv_b<__half><<<dim3(1, NN / 64, 4), 256>>>(p_node, p_node + (size_t)NN * 128,
                                                   p_node + (size_t)2 * NN * 128, W2,
                                                   p_outinv, 64, 64, p_xsh, (size_t)NN * 64,
                                                   0x5420u);
    k_agg_v<<<dim3(NN / 16, 2), dim3(16, 16)>>>(b2, 1);

    // layer 3: only relations {1,3} (hM3 is the only live output)
    k_aggpre<<<dim3(NN / 16, 2), dim3(16, 16)>>>();
    k_conv_b<float><<<dim3(2, NN / 64, 2), 256>>>(p_agg, nullptr, nullptr, W3, p_ininv,
                                                  64, 128, p_xs32, (size_t)NN * 128, 0x31u);
    k_addb<<<NN * 128 / 4 / 256, 256>>>(b3);

    k_l1norm<<<MROW, 128>>>(fe, p_feh);

    // ---- join: f1b needs x1f + transposed weights from s2 ----
    cudaStreamWaitEvent(0, evJoin, 0);

    k_tc<1, 1, true><<<dim3(2, 32), 256, TC_SMEM>>>(
        p_feh, p_bth + O1B, f1b, p_x1f, nullptr, p_x1h, 256, 128);
    k_tc<1, 1, false><<<dim3(4, 32), 256, TC_SMEM>>>(
        p_x1h, p_bth + O2, f2b, nullptr, nullptr, p_x2h, 512, 256);
    k_tc<1, 1, false><<<dim3(8, 32), 256, TC_SMEM>>>(
        p_x2h, p_bth + O3, f3b, nullptr, nullptr, p_x3h, 1024, 512);
    k_tc<2, 0, false><<<dim3(64, 32), 256, TC_SMEM>>>(
        p_x3h, p_bth + O4, f4b, nullptr, outx, nullptr, 8192, 1024);
}

// round 12
// speedup vs baseline: 6.3913x; 1.0185x over previous
#include <cuda_runtime.h>
#include <cuda_fp16.h>
#include <stdint.h>
#include <math.h>

#define NN   8192
#define NE   500000
#define NREL 6
#define FEAT 256
#define HIDD 64
#define OUTD 128
#define MROW 4096   // SIZE
#define ITEM 8192
#define CB   8      // count blocks per relation

// ---------------- scratch (device globals: allocation-free) ----------------
__device__ int   g_outcnt[NREL][NN];
__device__ int   g_incnt [NREL][NN];
__device__ float g_outinv[NREL][NN];
__device__ float g_ininv [NREL][NN];
__device__ int   g_rowptr[NREL][NN + 1];
__device__ int   g_fill  [NREL][NN];
__device__ int   g_srcs  [NREL][NE];
__device__ __half g_xsh [NREL][NN * 64];    // layers 1-2 conv outputs (gathered)
__device__ float g_xs32 [NREL][NN * 128];   // layer-3 conv outputs (fp32)
__device__ float g_agg  [NREL][NN * 64];    // layer-3 pre-aggregated inputs
__device__ float g_node [3][NN * 128];      // trunk state fp32
__device__ __half g_nodeh[3][NN * 64];      // fp16 shadow for layer-3 gather

// pre-transposed fp16 weights: Bt[n][k] per matrix, offsets below
#define O1A 0                            // f1w top^T [256][8192]
#define O1B 2097152                      // f1w bot^T [256][128]
#define O2  2129920                      // f2w^T     [512][256]
#define O3  2260992                      // f3w^T     [1024][512]
#define O4  2785280                      // f4w^T     [8192][1024]
#define BT_TOTAL 11173888
__device__ __half g_bth[BT_TOTAL];

// fp16 activations
__device__ __half g_adjh[(size_t)MROW * ITEM];
__device__ __half g_feh[MROW * OUTD];
__device__ float  g_x1f[MROW * 256];        // f1 Adj-partial (fp32)
__device__ __half g_x1h[MROW * 256];
__device__ __half g_x2h[MROW * 512];
__device__ __half g_x3h[MROW * 1024];

// ---------------- fp16 helpers ----------------
__device__ __forceinline__ uint32_t pack_h2(float x, float y) {
    __half2 h = __floats2half2_rn(x, y);
    return *reinterpret_cast<uint32_t*>(&h);
}
__device__ __forceinline__ float4 h4tof4(uint2 u) {
    float2 a = __half22float2(*reinterpret_cast<__half2*>(&u.x));
    float2 b = __half22float2(*reinterpret_cast<__half2*>(&u.y));
    return make_float4(a.x, a.y, b.x, b.y);
}
__device__ __forceinline__ uint2 h2add(uint2 a, uint2 b) {
    __half2* A = reinterpret_cast<__half2*>(&a);
    __half2* B = reinterpret_cast<__half2*>(&b);
    uint2 r;
    reinterpret_cast<__half2*>(&r)[0] = __hadd2(A[0], B[0]);
    reinterpret_cast<__half2*>(&r)[1] = __hadd2(A[1], B[1]);
    return r;
}
__device__ __forceinline__ void store4(float* p, float a, float b, float c, float d) {
    *reinterpret_cast<float4*>(p) = make_float4(a, b, c, d);
}
__device__ __forceinline__ void store4(__half* p, float a, float b, float c, float d) {
    *reinterpret_cast<uint2*>(p) = make_uint2(pack_h2(a, b), pack_h2(c, d));
}

// ---------------- CSR build ----------------
__global__ void k_zero_counts() {
    int i = blockIdx.x * blockDim.x + threadIdx.x;
    if (i < NREL * NN) {
        ((int*)g_outcnt)[i] = 0;
        ((int*)g_incnt)[i]  = 0;
    }
}

__global__ void k_count(const int* __restrict__ edges) {
    extern __shared__ int smcnt[];            // [2*NN]
    const int r = blockIdx.y, b = blockIdx.x;
    int* so = smcnt;
    int* si = smcnt + NN;
    for (int i = threadIdx.x; i < 2 * NN; i += blockDim.x) smcnt[i] = 0;
    __syncthreads();
    const int per = NE / CB;
    const int e0 = b * per;
    const int* es = edges + (size_t)r * 2 * NE;
    for (int e = e0 + threadIdx.x * 4; e < e0 + per; e += blockDim.x * 4) {
        int4 s = *reinterpret_cast<const int4*>(es + e);
        int4 d = *reinterpret_cast<const int4*>(es + NE + e);
        atomicAdd(&so[s.x], 1); atomicAdd(&so[s.y], 1);
        atomicAdd(&so[s.z], 1); atomicAdd(&so[s.w], 1);
        atomicAdd(&si[d.x], 1); atomicAdd(&si[d.y], 1);
        atomicAdd(&si[d.z], 1); atomicAdd(&si[d.w], 1);
    }
    __syncthreads();
    for (int i = threadIdx.x; i < NN; i += blockDim.x) {
        int v = so[i];
        if (v) atomicAdd(&g_outcnt[r][i], v);
        v = si[i];
        if (v) atomicAdd(&g_incnt[r][i], v);
    }
}

__global__ void k_scan() {
    int r = blockIdx.x;
    int tid = threadIdx.x;          // 1024 threads
    int base = tid * 8;
    int c[8];
    int s = 0;
#pragma unroll
    for (int i = 0; i < 8; i++) { c[i] = g_incnt[r][base + i]; s += c[i]; }

    int lane = tid & 31, w = tid >> 5;
    int incl = s;
#pragma unroll
    for (int o = 1; o < 32; o <<= 1) {
        int v = __shfl_up_sync(0xffffffffu, incl, o);
        if (lane >= o) incl += v;
    }
    __shared__ int wsum[32];
    if (lane == 31) wsum[w] = incl;
    __syncthreads();
    if (w == 0) {
        int v = wsum[lane];
#pragma unroll
        for (int o = 1; o < 32; o <<= 1) {
            int t = __shfl_up_sync(0xffffffffu, v, o);
            if (lane >= o) v += t;
        }
        wsum[lane] = v;
    }
    __syncthreads();
    int excl = (incl - s) + (w > 0 ? wsum[w - 1] : 0);
    int run = excl;
#pragma unroll
    for (int i = 0; i < 8; i++) {
        g_rowptr[r][base + i] = run;
        g_fill[r][base + i]   = run;
        run += c[i];
        int ic = c[i] > 0 ? c[i] : 1;
        g_ininv[r][base + i] = rsqrtf((float)ic);
        int oc = g_outcnt[r][base + i];
        if (oc < 1) oc = 1;
        g_outinv[r][base + i] = rsqrtf((float)oc);
    }
    if (tid == 1023) g_rowptr[r][NN] = run;
}

__global__ void k_fill(const int* __restrict__ edges) {
    int i = (blockIdx.x * blockDim.x + threadIdx.x) * 4;
    if (i >= NREL * NE) return;
    int r = i / NE, e = i - r * NE;
    int4 src = *reinterpret_cast<const int4*>(edges + (size_t)r * 2 * NE + e);
    int4 dst = *reinterpret_cast<const int4*>(edges + (size_t)r * 2 * NE + NE + e);
    g_srcs[r][atomicAdd(&g_fill[r][dst.x], 1)] = src.x;
    g_srcs[r][atomicAdd(&g_fill[r][dst.y], 1)] = src.y;
    g_srcs[r][atomicAdd(&g_fill[r][dst.z], 1)] = src.z;
    g_srcs[r][atomicAdd(&g_fill[r][dst.w], 1)] = src.w;
}

// ---------------- conv GEMM batched over relations --------------------------
template <typename T>
__global__ void k_conv_b(const float* __restrict__ A0, const float* __restrict__ A1,
                         const float* __restrict__ A2, const float* __restrict__ Wb,
                         const float* __restrict__ scaleb, int K, int Nh,
                         T* __restrict__ xsbase, size_t xstride, uint32_t rpat) {
    const int r = (rpat >> (4 * blockIdx.z)) & 0xF;
    const int smap[6] = {0, 1, 0, 2, 2, 1};
    const float* A;
    if (A1 == nullptr) {
        A = A0 + (size_t)r * NN * K;
    } else {
        int si = smap[r];
        A = (si == 0) ? A0 : (si == 1) ? A1 : A2;
    }
    const float* W = Wb + (size_t)r * K * Nh;
    T* Xs = xsbase + (size_t)r * xstride;
    const float* scale = scaleb + r * NN;

    __shared__ float As[16][64];
    __shared__ float Bs[16][64];
    int tid = threadIdx.x;
    int bx = blockIdx.x, by = blockIdx.y;
    int aRow = tid >> 2, aCol = (tid & 3) * 4;
    int bRow = tid >> 4, bCol = (tid & 15) * 4;
    int tx = tid & 15, ty = tid >> 4;
    float acc[4][4] = {};
    const float* Ap = A + (size_t)(by * 64) * K;
    float scl = scale[by * 64 + aRow];

    for (int k0 = 0; k0 < K; k0 += 16) {
        float4 av = *(const float4*)(Ap + (size_t)aRow * K + k0 + aCol);
        As[aCol + 0][aRow] = av.x * scl;
        As[aCol + 1][aRow] = av.y * scl;
        As[aCol + 2][aRow] = av.z * scl;
        As[aCol + 3][aRow] = av.w * scl;
        float4 bv = *(const float4*)(W + (size_t)(k0 + bRow) * Nh + bx * 64 + bCol);
        *(float4*)&Bs[bRow][bCol] = bv;
        __syncthreads();
#pragma unroll
        for (int kk = 0; kk < 16; kk++) {
            float a[4], b[4];
#pragma unroll
            for (int i = 0; i < 4; i++) a[i] = As[kk][ty * 4 + i];
#pragma unroll
            for (int j = 0; j < 4; j++) b[j] = Bs[kk][tx * 4 + j];
#pragma unroll
            for (int i = 0; i < 4; i++)
#pragma unroll
                for (int j = 0; j < 4; j++) acc[i][j] += a[i] * b[j];
        }
        __syncthreads();
    }
    int row0 = by * 64 + ty * 4, col0 = bx * 64 + tx * 4;
#pragma unroll
    for (int i = 0; i < 4; i++)
        store4(Xs + (size_t)(row0 + i) * Nh + col0,
               acc[i][0], acc[i][1], acc[i][2], acc[i][3]);
}

// ---------------- aggregation helpers ----------------
__device__ __forceinline__ float4 f4add(float4 a, float4 b) {
    a.x += b.x; a.y += b.y; a.z += b.z; a.w += b.w; return a;
}
__device__ __forceinline__ float4 f4fma(float4 a, float s, float4 acc) {
    acc.x += a.x * s; acc.y += a.y * s; acc.z += a.z * s; acc.w += a.w * s; return acc;
}

// post-GEMM agg: t = tbase + blockIdx.y; pairwise fp16 adds, fp32 accumulate
__global__ void k_agg_v(const float* __restrict__ bias, int tbase) {
    const int t = tbase + blockIdx.y;
    const int n = blockIdx.x * blockDim.y + threadIdx.y;
    const int lane = threadIdx.x;     // 0..15
    const int RA[3] = {1, 0, 2};
    const int RB[3] = {3, 4, 5};
    int rel[2] = {RA[t], RB[t]};
    float4 acc = f4add(reinterpret_cast<const float4*>(bias + rel[0] * 64)[lane],
                       reinterpret_cast<const float4*>(bias + rel[1] * 64)[lane]);
#pragma unroll
    for (int rr = 0; rr < 2; rr++) {
        int r = rel[rr];
        int e0 = g_rowptr[r][n], e1 = g_rowptr[r][n + 1];
        const __half* xs = g_xsh[r];
        const int* srcs = g_srcs[r];
        float4 s = make_float4(0.f, 0.f, 0.f, 0.f);
        int e = e0;
        for (; e + 7 < e1; e += 8) {
            uint2 u0 = reinterpret_cast<const uint2*>(xs + (size_t)srcs[e] * 64)[lane];
            uint2 u1 = reinterpret_cast<const uint2*>(xs + (size_t)srcs[e + 1] * 64)[lane];
            uint2 u2 = reinterpret_cast<const uint2*>(xs + (size_t)srcs[e + 2] * 64)[lane];
            uint2 u3 = reinterpret_cast<const uint2*>(xs + (size_t)srcs[e + 3] * 64)[lane];
            uint2 u4 = reinterpret_cast<const uint2*>(xs + (size_t)srcs[e + 4] * 64)[lane];
            uint2 u5 = reinterpret_cast<const uint2*>(xs + (size_t)srcs[e + 5] * 64)[lane];
            uint2 u6 = reinterpret_cast<const uint2*>(xs + (size_t)srcs[e + 6] * 64)[lane];
            uint2 u7 = reinterpret_cast<const uint2*>(xs + (size_t)srcs[e + 7] * 64)[lane];
            // pairwise fp16 adds (half the conversions + fp32 adds)
            float4 p0 = h4tof4(h2add(u0, u1));
            float4 p1 = h4tof4(h2add(u2, u3));
            float4 p2 = h4tof4(h2add(u4, u5));
            float4 p3 = h4tof4(h2add(u6, u7));
            s = f4add(s, f4add(f4add(p0, p1), f4add(p2, p3)));
        }
        for (; e < e1; e++) {
            uint2 u = reinterpret_cast<const uint2*>(xs + (size_t)srcs[e] * 64)[lane];
            s = f4add(s, h4tof4(u));
        }
        acc = f4fma(s, g_ininv[r][n], acc);
    }
    reinterpret_cast<float4*>(g_node[t] + (size_t)n * 64)[lane] = acc;
    reinterpret_cast<uint2*>(g_nodeh[t] + (size_t)n * 64)[lane] =
        make_uint2(pack_h2(acc.x, acc.y), pack_h2(acc.z, acc.w));
}

// pre-GEMM agg (layer 3): only relations {1,3} feed hM3
__global__ void k_aggpre() {
    const int r = 1 + 2 * blockIdx.y;           // 1, 3
    const int n = blockIdx.x * blockDim.y + threadIdx.y;
    const int lane = threadIdx.x;     // 0..15
    const int smap[6] = {0, 1, 0, 2, 2, 1};
    const __half* x = g_nodeh[smap[r]];
    const float* oi = g_outinv[r];
    const int* srcs = g_srcs[r];
    int e0 = g_rowptr[r][n], e1 = g_rowptr[r][n + 1];
    float4 acc = make_float4(0.f, 0.f, 0.f, 0.f);
    int e = e0;
    for (; e + 3 < e1; e += 4) {
        int s0 = srcs[e], s1 = srcs[e + 1], s2 = srcs[e + 2], s3 = srcs[e + 3];
        uint2 u0 = reinterpret_cast<const uint2*>(x + (size_t)s0 * 64)[lane];
        uint2 u1 = reinterpret_cast<const uint2*>(x + (size_t)s1 * 64)[lane];
        uint2 u2 = reinterpret_cast<const uint2*>(x + (size_t)s2 * 64)[lane];
        uint2 u3 = reinterpret_cast<const uint2*>(x + (size_t)s3 * 64)[lane];
        acc = f4fma(h4tof4(u0), oi[s0], acc);
        acc = f4fma(h4tof4(u1), oi[s1], acc);
        acc = f4fma(h4tof4(u2), oi[s2], acc);
        acc = f4fma(h4tof4(u3), oi[s3], acc);
    }
    for (; e < e1; e++) {
        int s0 = srcs[e];
        uint2 u0 = reinterpret_cast<const uint2*>(x + (size_t)s0 * 64)[lane];
        acc = f4fma(h4tof4(u0), oi[s0], acc);
    }
    reinterpret_cast<float4*>(g_agg[r] + (size_t)n * 64)[lane] = acc;
}

// layer-3 combine (only hM3 live)
__global__ void k_addb(const float* __restrict__ bias) {
    int i = blockIdx.x * blockDim.x + threadIdx.x;
    int h = (i & 31);
    float4 a = reinterpret_cast<const float4*>(g_xs32[1])[i];
    float4 b = reinterpret_cast<const float4*>(g_xs32[3])[i];
    float4 ba = reinterpret_cast<const float4*>(bias + 1 * 128)[h];
    float4 bb = reinterpret_cast<const float4*>(bias + 3 * 128)[h];
    float4 o;
    o.x = a.x + b.x + ba.x + bb.x;
    o.y = a.y + b.y + ba.y + bb.y;
    o.z = a.z + b.z + ba.z + bb.z;
    o.w = a.w + b.w + ba.w + bb.w;
    reinterpret_cast<float4*>(g_node[0])[i] = o;
}

// ---------------- row L1-normalize hM3[0:4096] -> fe (f32) + fp16 ----------
__global__ void k_l1norm(float* __restrict__ out, __half* __restrict__ feh) {
    int row = blockIdx.x;
    int h = threadIdx.x;  // 128
    float v = g_node[0][(size_t)row * OUTD + h];
    float a = fabsf(v);
#pragma unroll
    for (int o = 16; o > 0; o >>= 1) a += __shfl_xor_sync(0xffffffffu, a, o);
    __shared__ float sh[4];
    if ((h & 31) == 0) sh[h >> 5] = a;
    __syncthreads();
    float tot = sh[0] + sh[1] + sh[2] + sh[3];
    float r = v / fmaxf(tot, 1e-12f);
    out[(size_t)row * OUTD + h] = r;
    feh[(size_t)row * OUTD + h] = __float2half_rn(r);
}

// ---------------- Adj fp32 -> fp16 -----------------------------------------
__global__ void k_cvt(const float4* __restrict__ src, __half* __restrict__ dst) {
    size_t i = (size_t)blockIdx.x * blockDim.x + threadIdx.x;
    float4 v = src[i];
    uint2 p = make_uint2(pack_h2(v.x, v.y), pack_h2(v.z, v.w));
    *reinterpret_cast<uint2*>(dst + 4 * i) = p;
}

// ---------------- weight transpose fp16: B[K][N] -> Bt[N][K] ---------------
__global__ void k_tsp(const float* __restrict__ B, __half* __restrict__ th,
                      int K, int N) {
    __shared__ float s[32][33];
    int n0 = blockIdx.x * 32, k0 = blockIdx.y * 32;
    int tx = threadIdx.x, ty = threadIdx.y;
#pragma unroll
    for (int i = 0; i < 32; i += 8)
        s[ty + i][tx] = B[(size_t)(k0 + ty + i) * N + n0 + tx];
    __syncthreads();
#pragma unroll
    for (int i = 0; i < 32; i += 8) {
        int n = n0 + ty + i, k = k0 + tx;
        th[(size_t)n * K + k] = __float2half_rn(s[tx][ty + i]);
    }
}

// ---------------- mma.sync + ldmatrix + cp.async plumbing ------------------
__device__ __forceinline__ uint32_t s2u(const void* p) {
    uint32_t a;
    asm("{ .reg .u64 t; cvta.to.shared.u64 t, %1; cvt.u32.u64 %0, t; }" : "=r"(a) : "l"(p));
    return a;
}
__device__ __forceinline__ void mma_f16(float* d, const uint32_t* a, const uint32_t* b) {
    asm volatile(
        "mma.sync.aligned.m16n8k16.row.col.f32.f16.f16.f32 "
        "{%0,%1,%2,%3}, {%4,%5,%6,%7}, {%8,%9}, {%0,%1,%2,%3};"
        : "+f"(d[0]), "+f"(d[1]), "+f"(d[2]), "+f"(d[3])
        : "r"(a[0]), "r"(a[1]), "r"(a[2]), "r"(a[3]), "r"(b[0]), "r"(b[1]));
}
__device__ __forceinline__ void ldsm4(uint32_t* r, uint32_t addr) {
    asm volatile("ldmatrix.sync.aligned.m8n8.x4.shared.b16 {%0,%1,%2,%3}, [%4];"
                 : "=r"(r[0]), "=r"(r[1]), "=r"(r[2]), "=r"(r[3]) : "r"(addr));
}
__device__ __forceinline__ void cpa16(uint32_t s, const void* g) {
    asm volatile("cp.async.cg.shared.global [%0], [%1], 16;" :: "r"(s), "l"(g));
}
#define CP_COMMIT() asm volatile("cp.async.commit_group;" ::: "memory")
#define CP_WAIT2()  asm volatile("cp.async.wait_group 2;" ::: "memory")

// ---------------- MLP GEMM: fp16 single-pass, templated BN -----------------
// NT = n-subtiles per warp (8 -> BN=128, 16 -> BN=256). BM=128, BK=64.
template <int ACT, int OUT, bool HC, int NT>
__global__ void __launch_bounds__(256, 1)
k_tc(const __half* __restrict__ A_, const __half* __restrict__ Bh_,
     const float* __restrict__ bias, const float* __restrict__ Cin,
     float* __restrict__ Cf, __half* __restrict__ Oh, int N, int K) {
    constexpr int BN = NT * 16;
    constexpr uint32_t ASZ = 16384u;
    constexpr uint32_t STG = ASZ + (uint32_t)BN * 128u;
    extern __shared__ char smc[];
    const uint32_t sb = s2u(smc);
    const int tid = threadIdx.x, lane = tid & 31, warp = tid >> 5;
    const int wm = warp & 3, wn = warp >> 2;
    const int g = lane >> 2, tig = lane & 3;
    const int bm = blockIdx.y * 128, bn = blockIdx.x * BN;

    float c[2][NT][4];
#pragma unroll
    for (int i = 0; i < 2; i++)
#pragma unroll
        for (int j = 0; j < NT; j++)
#pragma unroll
            for (int q = 0; q < 4; q++) c[i][j][q] = 0.f;

    auto load_stage = [&](int s) {
        const uint32_t st = sb + (uint32_t)(s % 3) * STG;
        const int k0 = s * 64;
#pragma unroll
        for (int j = 0; j < (128 + BN) / 32; j++) {
            int cidx = tid + 256 * j;
            int row = cidx >> 3, kc = cidx & 7;
            if (row < 128) {
                uint32_t off = (uint32_t)(row * 128 + kc * 16);
                off ^= (off >> 3) & 0x70;
                cpa16(st + off, A_ + (size_t)(bm + row) * K + k0 + kc * 8);
            } else {
                int br = row - 128;
                uint32_t off = (uint32_t)(br * 128 + kc * 16);
                off ^= (off >> 3) & 0x70;
                cpa16(st + ASZ + off, Bh_ + (size_t)(bn + br) * K + k0 + kc * 8);
            }
        }
    };

    const int nst = K >> 6;
#pragma unroll
    for (int i = 0; i < 3; i++) {
        if (i < nst) load_stage(i);
        CP_COMMIT();
    }

    for (int s = 0; s < nst; s++) {
        CP_WAIT2();
        __syncthreads();
        const uint32_t st = sb + (uint32_t)(s % 3) * STG;
#pragma unroll
        for (int kk = 0; kk < 64; kk += 16) {
            uint32_t ah[2][4], bh[NT][2];
#pragma unroll
            for (int mt = 0; mt < 2; mt++) {
                int row = wm * 32 + mt * 16 + (lane & 15);
                uint32_t off = (uint32_t)(row * 128) + (uint32_t)(kk * 2) + (uint32_t)(lane & 16);
                off ^= (off >> 3) & 0x70;
                ldsm4(ah[mt], st + off);
            }
#pragma unroll
            for (int bt = 0; bt < NT / 2; bt++) {
                int row = wn * (8 * NT) + bt * 16 + ((lane >> 4) << 3) + (lane & 7);
                uint32_t off = (uint32_t)(row * 128) + (uint32_t)(kk * 2) + (uint32_t)((lane & 8) << 1);
                off ^= (off >> 3) & 0x70;
                uint32_t r[4];
                ldsm4(r, st + ASZ + off);
                bh[2 * bt][0] = r[0]; bh[2 * bt][1] = r[1];
                bh[2 * bt + 1][0] = r[2]; bh[2 * bt + 1][1] = r[3];
            }
#pragma unroll
            for (int mt = 0; mt < 2; mt++)
#pragma unroll
                for (int nt = 0; nt < NT; nt++)
                    mma_f16(c[mt][nt], ah[mt], bh[nt]);
        }
        __syncthreads();
        if (s + 3 < nst) load_stage(s + 3);
        CP_COMMIT();
    }

    // epilogue
#pragma unroll
    for (int mt = 0; mt < 2; mt++) {
#pragma unroll
        for (int nt = 0; nt < NT; nt++) {
            int m0 = bm + wm * 32 + mt * 16 + g;
            int n0 = bn + wn * (8 * NT) + nt * 8 + 2 * tig;
            float2 v0 = make_float2(c[mt][nt][0], c[mt][nt][1]);
            float2 v1 = make_float2(c[mt][nt][2], c[mt][nt][3]);
            if (HC) {
                float2 ci0 = *reinterpret_cast<const float2*>(Cin + (size_t)m0 * N + n0);
                float2 ci1 = *reinterpret_cast<const float2*>(Cin + (size_t)(m0 + 8) * N + n0);
                v0.x += ci0.x; v0.y += ci0.y; v1.x += ci1.x; v1.y += ci1.y;
            }
            if (bias) {
                float bx = bias[n0], by = bias[n0 + 1];
                v0.x += bx; v0.y += by; v1.x += bx; v1.y += by;
            }
            if (ACT == 1) {
                v0.x = fmaxf(v0.x, 0.f); v0.y = fmaxf(v0.y, 0.f);
                v1.x = fmaxf(v1.x, 0.f); v1.y = fmaxf(v1.y, 0.f);
            } else if (ACT == 2) {
                v0.x = 1.f / (1.f + expf(-v0.x)); v0.y = 1.f / (1.f + expf(-v0.y));
                v1.x = 1.f / (1.f + expf(-v1.x)); v1.y = 1.f / (1.f + expf(-v1.y));
            }
            if (OUT == 0) {
                *reinterpret_cast<float2*>(Cf + (size_t)m0 * N + n0) = v0;
                *reinterpret_cast<float2*>(Cf + (size_t)(m0 + 8) * N + n0) = v1;
            } else {
                *reinterpret_cast<uint32_t*>(Oh + (size_t)m0 * N + n0) = pack_h2(v0.x, v0.y);
                *reinterpret_cast<uint32_t*>(Oh + (size_t)(m0 + 8) * N + n0) = pack_h2(v1.x, v1.y);
            }
        }
    }
}

#define SM8  (3 * (16384 + 128 * 128))   // 96 KB  (NT=8)
#define SM16 (3 * (16384 + 256 * 128))   // 144 KB (NT=16)

// ---------------- orchestration ----------------
extern "C" void kernel_launch(void* const* d_in, const int* in_sizes, int n_in,
                              void* d_out, int out_size) {
    const float* hM  = (const float*)d_in[0];
    const float* hD  = (const float*)d_in[1];
    const float* hT  = (const float*)d_in[2];
    const float* W1  = (const float*)d_in[3];
    const float* b1  = (const float*)d_in[4];
    const float* W2  = (const float*)d_in[5];
    const float* b2  = (const float*)d_in[6];
    const float* W3  = (const float*)d_in[7];
    const float* b3  = (const float*)d_in[8];
    const float* Adj = (const float*)d_in[9];
    const float* f1w = (const float*)d_in[10];
    const float* f1b = (const float*)d_in[11];
    const float* f2w = (const float*)d_in[12];
    const float* f2b = (const float*)d_in[13];
    const float* f3w = (const float*)d_in[14];
    const float* f3b = (const float*)d_in[15];
    const float* f4w = (const float*)d_in[16];
    const float* f4b = (const float*)d_in[17];
    const int* edges = (const int*)d_in[18];

    float *p_node, *p_agg, *p_outinv, *p_ininv, *p_xs32, *p_x1f;
    __half *p_bth, *p_adjh, *p_feh, *p_x1h, *p_x2h, *p_x3h, *p_xsh;
    cudaGetSymbolAddress((void**)&p_node, g_node);
    cudaGetSymbolAddress((void**)&p_agg, g_agg);
    cudaGetSymbolAddress((void**)&p_outinv, g_outinv);
    cudaGetSymbolAddress((void**)&p_ininv, g_ininv);
    cudaGetSymbolAddress((void**)&p_xs32, g_xs32);
    cudaGetSymbolAddress((void**)&p_xsh, g_xsh);
    cudaGetSymbolAddress((void**)&p_bth, g_bth);
    cudaGetSymbolAddress((void**)&p_adjh, g_adjh);
    cudaGetSymbolAddress((void**)&p_feh, g_feh);
    cudaGetSymbolAddress((void**)&p_x1f, g_x1f);
    cudaGetSymbolAddress((void**)&p_x1h, g_x1h);
    cudaGetSymbolAddress((void**)&p_x2h, g_x2h);
    cudaGetSymbolAddress((void**)&p_x3h, g_x3h);

    float* fe   = (float*)d_out;                       // 4096 x 128
    float* outx = (float*)d_out + (size_t)MROW * OUTD; // 4096 x 8192

    static cudaStream_t s2 = nullptr, s3 = nullptr;
    static cudaEvent_t evFork = nullptr, evJoin = nullptr, evScan = nullptr, evFill = nullptr;
    if (s2 == nullptr) {
        cudaStreamCreateWithFlags(&s2, cudaStreamNonBlocking);
        cudaStreamCreateWithFlags(&s3, cudaStreamNonBlocking);
        cudaEventCreateWithFlags(&evFork, cudaEventDisableTiming);
        cudaEventCreateWithFlags(&evJoin, cudaEventDisableTiming);
        cudaEventCreateWithFlags(&evScan, cudaEventDisableTiming);
        cudaEventCreateWithFlags(&evFill, cudaEventDisableTiming);
        cudaFuncSetAttribute(k_tc<0, 0, false, 8>, cudaFuncAttributeMaxDynamicSharedMemorySize, SM8);
        cudaFuncSetAttribute(k_tc<1, 1, true, 8>,  cudaFuncAttributeMaxDynamicSharedMemorySize, SM8);
        cudaFuncSetAttribute(k_tc<1, 1, false, 8>, cudaFuncAttributeMaxDynamicSharedMemorySize, SM8);
        cudaFuncSetAttribute(k_tc<2, 0, false, 16>, cudaFuncAttributeMaxDynamicSharedMemorySize, SM16);
        cudaFuncSetAttribute(k_count, cudaFuncAttributeMaxDynamicSharedMemorySize, 2 * NN * 4);
    }

    // ---- fork s2: MLP prep + Adj GEMM (independent of GNN) ----
    cudaEventRecord(evFork, 0);
    cudaStreamWaitEvent(s2, evFork, 0);
    k_cvt<<<(MROW * ITEM / 4) / 256, 256, 0, s2>>>((const float4*)Adj, p_adjh);
    k_tsp<<<dim3(256 / 32, 8192 / 32), dim3(32, 8), 0, s2>>>(f1w, p_bth + O1A, 8192, 256);
    k_tsp<<<dim3(256 / 32, 128 / 32),  dim3(32, 8), 0, s2>>>(f1w + (size_t)ITEM * 256, p_bth + O1B, 128, 256);
    k_tsp<<<dim3(512 / 32, 256 / 32),  dim3(32, 8), 0, s2>>>(f2w, p_bth + O2, 256, 512);
    k_tsp<<<dim3(1024 / 32, 512 / 32), dim3(32, 8), 0, s2>>>(f3w, p_bth + O3, 512, 1024);
    k_tsp<<<dim3(8192 / 32, 1024 / 32), dim3(32, 8), 0, s2>>>(f4w, p_bth + O4, 1024, 8192);
    k_tc<0, 0, false, 8><<<dim3(2, 32), 256, SM8, s2>>>(
        p_adjh, p_bth + O1A, nullptr, nullptr, p_x1f, nullptr, 256, 8192);
    cudaEventRecord(evJoin, s2);

    // ---- main stream: CSR counts + scan ----
    k_zero_counts<<<(NREL * NN + 255) / 256, 256>>>();
    k_count<<<dim3(CB, NREL), 512, 2 * NN * 4>>>(edges);
    k_scan<<<NREL, 1024>>>();
    cudaEventRecord(evScan, 0);

    // ---- fork s3: CSR fill ----
    cudaStreamWaitEvent(s3, evScan, 0);
    k_fill<<<(NREL * NE / 4 + 255) / 256, 256, 0, s3>>>(edges);
    cudaEventRecord(evFill, s3);

    // ---- main: layer-1 conv overlaps fill ----
    k_conv_b<__half><<<dim3(1, NN / 64, 6), 256>>>(hM, hD, hT, W1, p_outinv, 256, 64,
                                                   p_xsh, (size_t)NN * 64, 0x543210u);
    cudaStreamWaitEvent(0, evFill, 0);
    k_agg_v<<<dim3(NN / 16, 3), dim3(16, 16)>>>(b1, 0);

    // layer 2: relations {0,2,4,5}, targets {D,T}
    k_conv_b<__half><<<dim3(1, NN / 64, 4), 256>>>(p_node, p_node + (size_t)NN * 128,
                                                   p_node + (size_t)2 * NN * 128, W2,
                                                   p_outinv, 64, 64, p_xsh, (size_t)NN * 64,
                                                   0x5420u);
    k_agg_v<<<dim3(NN / 16, 2), dim3(16, 16)>>>(b2, 1);

    // layer 3: relations {1,3}
    k_aggpre<<<dim3(NN / 16, 2), dim3(16, 16)>>>();
    k_conv_b<float><<<dim3(2, NN / 64, 2), 256>>>(p_agg, nullptr, nullptr, W3, p_ininv,
                                                  64, 128, p_xs32, (size_t)NN * 128, 0x31u);
    k_addb<<<NN * 128 / 4 / 256, 256>>>(b3);

    k_l1norm<<<MROW, 128>>>(fe, p_feh);

    // ---- join + MLP tail ----
    cudaStreamWaitEvent(0, evJoin, 0);

    k_tc<1, 1, true, 8><<<dim3(2, 32), 256, SM8>>>(
        p_feh, p_bth + O1B, f1b, p_x1f, nullptr, p_x1h, 256, 128);
    k_tc<1, 1, false, 8><<<dim3(4, 32), 256, SM8>>>(
        p_x1h, p_bth + O2, f2b, nullptr, nullptr, p_x2h, 512, 256);
    k_tc<1, 1, false, 8><<<dim3(8, 32), 256, SM8>>>(
        p_x2h, p_bth + O3, f3b, nullptr, nullptr, p_x3h, 1024, 512);
    k_tc<2, 0, false, 16><<<dim3(32, 32), 256, SM16>>>(
        p_x3h, p_bth + O4, f4b, nullptr, outx, nullptr, 8192, 1024);
}

// round 13
// speedup vs baseline: 6.6755x; 1.0445x over previous
#include <cuda_runtime.h>
#include <cuda_fp16.h>
#include <stdint.h>
#include <math.h>

#define NN   8192
#define NE   500000
#define NREL 6
#define FEAT 256
#define HIDD 64
#define OUTD 128
#define MROW 4096   // SIZE
#define ITEM 8192
#define CB   8      // count blocks per relation

// ---------------- scratch (device globals: allocation-free) ----------------
__device__ int   g_outcnt[NREL][NN];
__device__ int   g_incnt [NREL][NN];
__device__ float g_outinv[NREL][NN];
__device__ float g_ininv [NREL][NN];
__device__ int   g_rowptr[NREL][NN + 1];
__device__ int   g_fill  [NREL][NN];
__device__ int   g_srcs  [NREL][NE];
__device__ __half g_xsh [NREL][NN * 64];    // layers 1-2 conv outputs (gathered)
__device__ float g_xs32 [NREL][NN * 128];   // layer-3 conv outputs (fp32, rows<4096)
__device__ float g_agg  [NREL][NN * 64];    // layer-3 pre-aggregated inputs
__device__ float g_node [3][NN * 128];      // trunk state fp32
__device__ __half g_nodeh[3][NN * 64];      // fp16 shadow for layer-3 gather

// pre-transposed fp16 weights
#define O1A 0                            // f1w top^T [256][8192]
#define O1B 2097152                      // f1w bot^T [256][128]
#define O2  2129920                      // f2w^T     [512][256]
#define O3  2260992                      // f3w^T     [1024][512]
#define O4  2785280                      // f4w^T     [8192][1024]
#define BT_TOTAL 11173888
__device__ __half g_bth[BT_TOTAL];

// fp16 activations
__device__ __half g_adjh[(size_t)MROW * ITEM];
__device__ __half g_feh[MROW * OUTD];
__device__ float  g_x1f[MROW * 256];        // f1 Adj-partial (fp32)
__device__ __half g_x1h[MROW * 256];
__device__ __half g_x2h[MROW * 512];
__device__ __half g_x3h[MROW * 1024];

// ---------------- fp16 helpers ----------------
__device__ __forceinline__ uint32_t pack_h2(float x, float y) {
    __half2 h = __floats2half2_rn(x, y);
    return *reinterpret_cast<uint32_t*>(&h);
}
__device__ __forceinline__ float4 h4tof4(uint2 u) {
    float2 a = __half22float2(*reinterpret_cast<__half2*>(&u.x));
    float2 b = __half22float2(*reinterpret_cast<__half2*>(&u.y));
    return make_float4(a.x, a.y, b.x, b.y);
}
__device__ __forceinline__ uint2 h2add(uint2 a, uint2 b) {
    __half2* A = reinterpret_cast<__half2*>(&a);
    __half2* B = reinterpret_cast<__half2*>(&b);
    uint2 r;
    reinterpret_cast<__half2*>(&r)[0] = __hadd2(A[0], B[0]);
    reinterpret_cast<__half2*>(&r)[1] = __hadd2(A[1], B[1]);
    return r;
}
__device__ __forceinline__ void store4(float* p, float a, float b, float c, float d) {
    *reinterpret_cast<float4*>(p) = make_float4(a, b, c, d);
}
__device__ __forceinline__ void store4(__half* p, float a, float b, float c, float d) {
    *reinterpret_cast<uint2*>(p) = make_uint2(pack_h2(a, b), pack_h2(c, d));
}

// ---------------- CSR build ----------------
__global__ void k_zero_counts() {
    int i = blockIdx.x * blockDim.x + threadIdx.x;
    if (i < NREL * NN) {
        ((int*)g_outcnt)[i] = 0;
        ((int*)g_incnt)[i]  = 0;
    }
}

__global__ void k_count(const int* __restrict__ edges) {
    extern __shared__ int smcnt[];            // [2*NN]
    const int r = blockIdx.y, b = blockIdx.x;
    int* so = smcnt;
    int* si = smcnt + NN;
    for (int i = threadIdx.x; i < 2 * NN; i += blockDim.x) smcnt[i] = 0;
    __syncthreads();
    const int per = NE / CB;
    const int e0 = b * per;
    const int* es = edges + (size_t)r * 2 * NE;
    for (int e = e0 + threadIdx.x * 4; e < e0 + per; e += blockDim.x * 4) {
        int4 s = *reinterpret_cast<const int4*>(es + e);
        int4 d = *reinterpret_cast<const int4*>(es + NE + e);
        atomicAdd(&so[s.x], 1); atomicAdd(&so[s.y], 1);
        atomicAdd(&so[s.z], 1); atomicAdd(&so[s.w], 1);
        atomicAdd(&si[d.x], 1); atomicAdd(&si[d.y], 1);
        atomicAdd(&si[d.z], 1); atomicAdd(&si[d.w], 1);
    }
    __syncthreads();
    for (int i = threadIdx.x; i < NN; i += blockDim.x) {
        int v = so[i];
        if (v) atomicAdd(&g_outcnt[r][i], v);
        v = si[i];
        if (v) atomicAdd(&g_incnt[r][i], v);
    }
}

__global__ void k_scan() {
    int r = blockIdx.x;
    int tid = threadIdx.x;          // 1024 threads
    int base = tid * 8;
    int c[8];
    int s = 0;
#pragma unroll
    for (int i = 0; i < 8; i++) { c[i] = g_incnt[r][base + i]; s += c[i]; }

    int lane = tid & 31, w = tid >> 5;
    int incl = s;
#pragma unroll
    for (int o = 1; o < 32; o <<= 1) {
        int v = __shfl_up_sync(0xffffffffu, incl, o);
        if (lane >= o) incl += v;
    }
    __shared__ int wsum[32];
    if (lane == 31) wsum[w] = incl;
    __syncthreads();
    if (w == 0) {
        int v = wsum[lane];
#pragma unroll
        for (int o = 1; o < 32; o <<= 1) {
            int t = __shfl_up_sync(0xffffffffu, v, o);
            if (lane >= o) v += t;
        }
        wsum[lane] = v;
    }
    __syncthreads();
    int excl = (incl - s) + (w > 0 ? wsum[w - 1] : 0);
    int run = excl;
#pragma unroll
    for (int i = 0; i < 8; i++) {
        g_rowptr[r][base + i] = run;
        g_fill[r][base + i]   = run;
        run += c[i];
        int ic = c[i] > 0 ? c[i] : 1;
        g_ininv[r][base + i] = rsqrtf((float)ic);
        int oc = g_outcnt[r][base + i];
        if (oc < 1) oc = 1;
        g_outinv[r][base + i] = rsqrtf((float)oc);
    }
    if (tid == 1023) g_rowptr[r][NN] = run;
}

__global__ void k_fill(const int* __restrict__ edges) {
    int i = (blockIdx.x * blockDim.x + threadIdx.x) * 4;
    if (i >= NREL * NE) return;
    int r = i / NE, e = i - r * NE;
    int4 src = *reinterpret_cast<const int4*>(edges + (size_t)r * 2 * NE + e);
    int4 dst = *reinterpret_cast<const int4*>(edges + (size_t)r * 2 * NE + NE + e);
    g_srcs[r][atomicAdd(&g_fill[r][dst.x], 1)] = src.x;
    g_srcs[r][atomicAdd(&g_fill[r][dst.y], 1)] = src.y;
    g_srcs[r][atomicAdd(&g_fill[r][dst.z], 1)] = src.z;
    g_srcs[r][atomicAdd(&g_fill[r][dst.w], 1)] = src.w;
}

// ---------------- conv GEMM batched over relations --------------------------
template <typename T>
__global__ void k_conv_b(const float* __restrict__ A0, const float* __restrict__ A1,
                         const float* __restrict__ A2, const float* __restrict__ Wb,
                         const float* __restrict__ scaleb, int K, int Nh,
                         T* __restrict__ xsbase, size_t xstride, uint32_t rpat) {
    const int r = (rpat >> (4 * blockIdx.z)) & 0xF;
    const int smap[6] = {0, 1, 0, 2, 2, 1};
    const float* A;
    if (A1 == nullptr) {
        A = A0 + (size_t)r * NN * K;
    } else {
        int si = smap[r];
        A = (si == 0) ? A0 : (si == 1) ? A1 : A2;
    }
    const float* W = Wb + (size_t)r * K * Nh;
    T* Xs = xsbase + (size_t)r * xstride;
    const float* scale = scaleb + r * NN;

    __shared__ float As[16][64];
    __shared__ float Bs[16][64];
    int tid = threadIdx.x;
    int bx = blockIdx.x, by = blockIdx.y;
    int aRow = tid >> 2, aCol = (tid & 3) * 4;
    int bRow = tid >> 4, bCol = (tid & 15) * 4;
    int tx = tid & 15, ty = tid >> 4;
    float acc[4][4] = {};
    const float* Ap = A + (size_t)(by * 64) * K;
    float scl = scale[by * 64 + aRow];

    for (int k0 = 0; k0 < K; k0 += 16) {
        float4 av = *(const float4*)(Ap + (size_t)aRow * K + k0 + aCol);
        As[aCol + 0][aRow] = av.x * scl;
        As[aCol + 1][aRow] = av.y * scl;
        As[aCol + 2][aRow] = av.z * scl;
        As[aCol + 3][aRow] = av.w * scl;
        float4 bv = *(const float4*)(W + (size_t)(k0 + bRow) * Nh + bx * 64 + bCol);
        *(float4*)&Bs[bRow][bCol] = bv;
        __syncthreads();
#pragma unroll
        for (int kk = 0; kk < 16; kk++) {
            float a[4], b[4];
#pragma unroll
            for (int i = 0; i < 4; i++) a[i] = As[kk][ty * 4 + i];
#pragma unroll
            for (int j = 0; j < 4; j++) b[j] = Bs[kk][tx * 4 + j];
#pragma unroll
            for (int i = 0; i < 4; i++)
#pragma unroll
                for (int j = 0; j < 4; j++) acc[i][j] += a[i] * b[j];
        }
        __syncthreads();
    }
    int row0 = by * 64 + ty * 4, col0 = bx * 64 + tx * 4;
#pragma unroll
    for (int i = 0; i < 4; i++)
        store4(Xs + (size_t)(row0 + i) * Nh + col0,
               acc[i][0], acc[i][1], acc[i][2], acc[i][3]);
}

// ---------------- aggregation helpers ----------------
__device__ __forceinline__ float4 f4add(float4 a, float4 b) {
    a.x += b.x; a.y += b.y; a.z += b.z; a.w += b.w; return a;
}
__device__ __forceinline__ float4 f4fma(float4 a, float s, float4 acc) {
    acc.x += a.x * s; acc.y += a.y * s; acc.z += a.z * s; acc.w += a.w * s; return acc;
}

// post-GEMM agg: both relations interleaved (16 loads in flight per thread)
__global__ void k_agg_v(const float* __restrict__ bias, int tbase) {
    const int t = tbase + blockIdx.y;
    const int n = blockIdx.x * blockDim.y + threadIdx.y;
    const int lane = threadIdx.x;     // 0..15
    const int RA[3] = {1, 0, 2};
    const int RB[3] = {3, 4, 5};
    const int r0 = RA[t], r1 = RB[t];
    const __half* xa = g_xsh[r0];
    const __half* xb = g_xsh[r1];
    const int* sa_ = g_srcs[r0];
    const int* sb_ = g_srcs[r1];
    int ea = g_rowptr[r0][n], ea1 = g_rowptr[r0][n + 1];
    int eb = g_rowptr[r1][n], eb1 = g_rowptr[r1][n + 1];
    float4 sA = make_float4(0.f, 0.f, 0.f, 0.f);
    float4 sB = make_float4(0.f, 0.f, 0.f, 0.f);

    // interleaved main loop: 8+8 gathers in flight
    while (ea + 7 < ea1 && eb + 7 < eb1) {
        uint2 a0 = reinterpret_cast<const uint2*>(xa + (size_t)sa_[ea] * 64)[lane];
        uint2 a1 = reinterpret_cast<const uint2*>(xa + (size_t)sa_[ea + 1] * 64)[lane];
        uint2 a2 = reinterpret_cast<const uint2*>(xa + (size_t)sa_[ea + 2] * 64)[lane];
        uint2 a3 = reinterpret_cast<const uint2*>(xa + (size_t)sa_[ea + 3] * 64)[lane];
        uint2 a4 = reinterpret_cast<const uint2*>(xa + (size_t)sa_[ea + 4] * 64)[lane];
        uint2 a5 = reinterpret_cast<const uint2*>(xa + (size_t)sa_[ea + 5] * 64)[lane];
        uint2 a6 = reinterpret_cast<const uint2*>(xa + (size_t)sa_[ea + 6] * 64)[lane];
        uint2 a7 = reinterpret_cast<const uint2*>(xa + (size_t)sa_[ea + 7] * 64)[lane];
        uint2 b0 = reinterpret_cast<const uint2*>(xb + (size_t)sb_[eb] * 64)[lane];
        uint2 b1 = reinterpret_cast<const uint2*>(xb + (size_t)sb_[eb + 1] * 64)[lane];
        uint2 b2 = reinterpret_cast<const uint2*>(xb + (size_t)sb_[eb + 2] * 64)[lane];
        uint2 b3 = reinterpret_cast<const uint2*>(xb + (size_t)sb_[eb + 3] * 64)[lane];
        uint2 b4 = reinterpret_cast<const uint2*>(xb + (size_t)sb_[eb + 4] * 64)[lane];
        uint2 b5 = reinterpret_cast<const uint2*>(xb + (size_t)sb_[eb + 5] * 64)[lane];
        uint2 b6 = reinterpret_cast<const uint2*>(xb + (size_t)sb_[eb + 6] * 64)[lane];
        uint2 b7 = reinterpret_cast<const uint2*>(xb + (size_t)sb_[eb + 7] * 64)[lane];
        float4 pa0 = h4tof4(h2add(a0, a1));
        float4 pa1 = h4tof4(h2add(a2, a3));
        float4 pa2 = h4tof4(h2add(a4, a5));
        float4 pa3 = h4tof4(h2add(a6, a7));
        float4 pb0 = h4tof4(h2add(b0, b1));
        float4 pb1 = h4tof4(h2add(b2, b3));
        float4 pb2 = h4tof4(h2add(b4, b5));
        float4 pb3 = h4tof4(h2add(b6, b7));
        sA = f4add(sA, f4add(f4add(pa0, pa1), f4add(pa2, pa3)));
        sB = f4add(sB, f4add(f4add(pb0, pb1), f4add(pb2, pb3)));
        ea += 8; eb += 8;
    }
    // tails
    for (; ea + 7 < ea1; ea += 8) {
        uint2 a0 = reinterpret_cast<const uint2*>(xa + (size_t)sa_[ea] * 64)[lane];
        uint2 a1 = reinterpret_cast<const uint2*>(xa + (size_t)sa_[ea + 1] * 64)[lane];
        uint2 a2 = reinterpret_cast<const uint2*>(xa + (size_t)sa_[ea + 2] * 64)[lane];
        uint2 a3 = reinterpret_cast<const uint2*>(xa + (size_t)sa_[ea + 3] * 64)[lane];
        uint2 a4 = reinterpret_cast<const uint2*>(xa + (size_t)sa_[ea + 4] * 64)[lane];
        uint2 a5 = reinterpret_cast<const uint2*>(xa + (size_t)sa_[ea + 5] * 64)[lane];
        uint2 a6 = reinterpret_cast<const uint2*>(xa + (size_t)sa_[ea + 6] * 64)[lane];
        uint2 a7 = reinterpret_cast<const uint2*>(xa + (size_t)sa_[ea + 7] * 64)[lane];
        float4 p0 = h4tof4(h2add(a0, a1));
        float4 p1 = h4tof4(h2add(a2, a3));
        float4 p2 = h4tof4(h2add(a4, a5));
        float4 p3 = h4tof4(h2add(a6, a7));
        sA = f4add(sA, f4add(f4add(p0, p1), f4add(p2, p3)));
    }
    for (; ea < ea1; ea++)
        sA = f4add(sA, h4tof4(reinterpret_cast<const uint2*>(xa + (size_t)sa_[ea] * 64)[lane]));
    for (; eb + 7 < eb1; eb += 8) {
        uint2 b0 = reinterpret_cast<const uint2*>(xb + (size_t)sb_[eb] * 64)[lane];
        uint2 b1 = reinterpret_cast<const uint2*>(xb + (size_t)sb_[eb + 1] * 64)[lane];
        uint2 b2 = reinterpret_cast<const uint2*>(xb + (size_t)sb_[eb + 2] * 64)[lane];
        uint2 b3 = reinterpret_cast<const uint2*>(xb + (size_t)sb_[eb + 3] * 64)[lane];
        uint2 b4 = reinterpret_cast<const uint2*>(xb + (size_t)sb_[eb + 4] * 64)[lane];
        uint2 b5 = reinterpret_cast<const uint2*>(xb + (size_t)sb_[eb + 5] * 64)[lane];
        uint2 b6 = reinterpret_cast<const uint2*>(xb + (size_t)sb_[eb + 6] * 64)[lane];
        uint2 b7 = reinterpret_cast<const uint2*>(xb + (size_t)sb_[eb + 7] * 64)[lane];
        float4 p0 = h4tof4(h2add(b0, b1));
        float4 p1 = h4tof4(h2add(b2, b3));
        float4 p2 = h4tof4(h2add(b4, b5));
        float4 p3 = h4tof4(h2add(b6, b7));
        sB = f4add(sB, f4add(f4add(p0, p1), f4add(p2, p3)));
    }
    for (; eb < eb1; eb++)
        sB = f4add(sB, h4tof4(reinterpret_cast<const uint2*>(xb + (size_t)sb_[eb] * 64)[lane]));

    float4 acc = f4add(reinterpret_cast<const float4*>(bias + r0 * 64)[lane],
                       reinterpret_cast<const float4*>(bias + r1 * 64)[lane]);
    acc = f4fma(sA, g_ininv[r0][n], acc);
    acc = f4fma(sB, g_ininv[r1][n], acc);
    reinterpret_cast<float4*>(g_node[t] + (size_t)n * 64)[lane] = acc;
    reinterpret_cast<uint2*>(g_nodeh[t] + (size_t)n * 64)[lane] =
        make_uint2(pack_h2(acc.x, acc.y), pack_h2(acc.z, acc.w));
}

// pre-GEMM agg (layer 3): relations {1,3}, dst rows [0,4096) only, 8-unroll
__global__ void k_aggpre() {
    const int r = 1 + 2 * blockIdx.y;           // 1, 3
    const int n = blockIdx.x * blockDim.y + threadIdx.y;   // < 4096
    const int lane = threadIdx.x;     // 0..15
    const int smap[6] = {0, 1, 0, 2, 2, 1};
    const __half* x = g_nodeh[smap[r]];
    const float* oi = g_outinv[r];
    const int* srcs = g_srcs[r];
    int e0 = g_rowptr[r][n], e1 = g_rowptr[r][n + 1];
    float4 acc = make_float4(0.f, 0.f, 0.f, 0.f);
    int e = e0;
    for (; e + 7 < e1; e += 8) {
        int s0 = srcs[e], s1 = srcs[e + 1], s2 = srcs[e + 2], s3 = srcs[e + 3];
        int s4 = srcs[e + 4], s5 = srcs[e + 5], s6 = srcs[e + 6], s7 = srcs[e + 7];
        uint2 u0 = reinterpret_cast<const uint2*>(x + (size_t)s0 * 64)[lane];
        uint2 u1 = reinterpret_cast<const uint2*>(x + (size_t)s1 * 64)[lane];
        uint2 u2 = reinterpret_cast<const uint2*>(x + (size_t)s2 * 64)[lane];
        uint2 u3 = reinterpret_cast<const uint2*>(x + (size_t)s3 * 64)[lane];
        uint2 u4 = reinterpret_cast<const uint2*>(x + (size_t)s4 * 64)[lane];
        uint2 u5 = reinterpret_cast<const uint2*>(x + (size_t)s5 * 64)[lane];
        uint2 u6 = reinterpret_cast<const uint2*>(x + (size_t)s6 * 64)[lane];
        uint2 u7 = reinterpret_cast<const uint2*>(x + (size_t)s7 * 64)[lane];
        acc = f4fma(h4tof4(u0), oi[s0], acc);
        acc = f4fma(h4tof4(u1), oi[s1], acc);
        acc = f4fma(h4tof4(u2), oi[s2], acc);
        acc = f4fma(h4tof4(u3), oi[s3], acc);
        acc = f4fma(h4tof4(u4), oi[s4], acc);
        acc = f4fma(h4tof4(u5), oi[s5], acc);
        acc = f4fma(h4tof4(u6), oi[s6], acc);
        acc = f4fma(h4tof4(u7), oi[s7], acc);
    }
    for (; e < e1; e++) {
        int s0 = srcs[e];
        uint2 u0 = reinterpret_cast<const uint2*>(x + (size_t)s0 * 64)[lane];
        acc = f4fma(h4tof4(u0), oi[s0], acc);
    }
    reinterpret_cast<float4*>(g_agg[r] + (size_t)n * 64)[lane] = acc;
}

// ---------------- fused combine + L1-normalize (rows [0,4096)) -------------
// hM3[row] = xs32[1][row] + xs32[3][row] + b3[1] + b3[3]; then L1 norm.
__global__ void k_l1norm(const float* __restrict__ b3,
                         float* __restrict__ out, __half* __restrict__ feh) {
    int row = blockIdx.x;
    int h = threadIdx.x;  // 128
    float v = g_xs32[1][(size_t)row * OUTD + h] + g_xs32[3][(size_t)row * OUTD + h]
            + b3[128 + h] + b3[384 + h];
    float a = fabsf(v);
#pragma unroll
    for (int o = 16; o > 0; o >>= 1) a += __shfl_xor_sync(0xffffffffu, a, o);
    __shared__ float sh[4];
    if ((h & 31) == 0) sh[h >> 5] = a;
    __syncthreads();
    float tot = sh[0] + sh[1] + sh[2] + sh[3];
    float r = v / fmaxf(tot, 1e-12f);
    out[(size_t)row * OUTD + h] = r;
    feh[(size_t)row * OUTD + h] = __float2half_rn(r);
}

// ---------------- Adj fp32 -> fp16 -----------------------------------------
__global__ void k_cvt(const float4* __restrict__ src, __half* __restrict__ dst) {
    size_t i = (size_t)blockIdx.x * blockDim.x + threadIdx.x;
    float4 v = src[i];
    uint2 p = make_uint2(pack_h2(v.x, v.y), pack_h2(v.z, v.w));
    *reinterpret_cast<uint2*>(dst + 4 * i) = p;
}

// ---------------- weight transpose fp16: B[K][N] -> Bt[N][K] ---------------
__global__ void k_tsp(const float* __restrict__ B, __half* __restrict__ th,
                      int K, int N) {
    __shared__ float s[32][33];
    int n0 = blockIdx.x * 32, k0 = blockIdx.y * 32;
    int tx = threadIdx.x, ty = threadIdx.y;
#pragma unroll
    for (int i = 0; i < 32; i += 8)
        s[ty + i][tx] = B[(size_t)(k0 + ty + i) * N + n0 + tx];
    __syncthreads();
#pragma unroll
    for (int i = 0; i < 32; i += 8) {
        int n = n0 + ty + i, k = k0 + tx;
        th[(size_t)n * K + k] = __float2half_rn(s[tx][ty + i]);
    }
}

// ---------------- mma.sync + ldmatrix + cp.async plumbing ------------------
__device__ __forceinline__ uint32_t s2u(const void* p) {
    uint32_t a;
    asm("{ .reg .u64 t; cvta.to.shared.u64 t, %1; cvt.u32.u64 %0, t; }" : "=r"(a) : "l"(p));
    return a;
}
__device__ __forceinline__ void mma_f16(float* d, const uint32_t* a, const uint32_t* b) {
    asm volatile(
        "mma.sync.aligned.m16n8k16.row.col.f32.f16.f16.f32 "
        "{%0,%1,%2,%3}, {%4,%5,%6,%7}, {%8,%9}, {%0,%1,%2,%3};"
        : "+f"(d[0]), "+f"(d[1]), "+f"(d[2]), "+f"(d[3])
        : "r"(a[0]), "r"(a[1]), "r"(a[2]), "r"(a[3]), "r"(b[0]), "r"(b[1]));
}
__device__ __forceinline__ void ldsm4(uint32_t* r, uint32_t addr) {
    asm volatile("ldmatrix.sync.aligned.m8n8.x4.shared.b16 {%0,%1,%2,%3}, [%4];"
                 : "=r"(r[0]), "=r"(r[1]), "=r"(r[2]), "=r"(r[3]) : "r"(addr));
}
__device__ __forceinline__ void cpa16(uint32_t s, const void* g) {
    asm volatile("cp.async.cg.shared.global [%0], [%1], 16;" :: "r"(s), "l"(g));
}
#define CP_COMMIT() asm volatile("cp.async.commit_group;" ::: "memory")
#define CP_WAIT2()  asm volatile("cp.async.wait_group 2;" ::: "memory")

// ---------------- MLP GEMM: fp16 single-pass, templated BN -----------------
template <int ACT, int OUT, bool HC, int NT>
__global__ void __launch_bounds__(256, 1)
k_tc(const __half* __restrict__ A_, const __half* __restrict__ Bh_,
     const float* __restrict__ bias, const float* __restrict__ Cin,
     float* __restrict__ Cf, __half* __restrict__ Oh, int N, int K) {
    constexpr int BN = NT * 16;
    constexpr uint32_t ASZ = 16384u;
    constexpr uint32_t STG = ASZ + (uint32_t)BN * 128u;
    extern __shared__ char smc[];
    const uint32_t sb = s2u(smc);
    const int tid = threadIdx.x, lane = tid & 31, warp = tid >> 5;
    const int wm = warp & 3, wn = warp >> 2;
    const int g = lane >> 2, tig = lane & 3;
    const int bm = blockIdx.y * 128, bn = blockIdx.x * BN;

    float c[2][NT][4];
#pragma unroll
    for (int i = 0; i < 2; i++)
#pragma unroll
        for (int j = 0; j < NT; j++)
#pragma unroll
            for (int q = 0; q < 4; q++) c[i][j][q] = 0.f;

    auto load_stage = [&](int s) {
        const uint32_t st = sb + (uint32_t)(s % 3) * STG;
        const int k0 = s * 64;
#pragma unroll
        for (int j = 0; j < (128 + BN) / 32; j++) {
            int cidx = tid + 256 * j;
            int row = cidx >> 3, kc = cidx & 7;
            if (row < 128) {
                uint32_t off = (uint32_t)(row * 128 + kc * 16);
                off ^= (off >> 3) & 0x70;
                cpa16(st + off, A_ + (size_t)(bm + row) * K + k0 + kc * 8);
            } else {
                int br = row - 128;
                uint32_t off = (uint32_t)(br * 128 + kc * 16);
                off ^= (off >> 3) & 0x70;
                cpa16(st + ASZ + off, Bh_ + (size_t)(bn + br) * K + k0 + kc * 8);
            }
        }
    };

    const int nst = K >> 6;
#pragma unroll
    for (int i = 0; i < 3; i++) {
        if (i < nst) load_stage(i);
        CP_COMMIT();
    }

    for (int s = 0; s < nst; s++) {
        CP_WAIT2();
        __syncthreads();
        const uint32_t st = sb + (uint32_t)(s % 3) * STG;
#pragma unroll
        for (int kk = 0; kk < 64; kk += 16) {
            uint32_t ah[2][4], bh[NT][2];
#pragma unroll
            for (int mt = 0; mt < 2; mt++) {
                int row = wm * 32 + mt * 16 + (lane & 15);
                uint32_t off = (uint32_t)(row * 128) + (uint32_t)(kk * 2) + (uint32_t)(lane & 16);
                off ^= (off >> 3) & 0x70;
                ldsm4(ah[mt], st + off);
            }
#pragma unroll
            for (int bt = 0; bt < NT / 2; bt++) {
                int row = wn * (8 * NT) + bt * 16 + ((lane >> 4) << 3) + (lane & 7);
                uint32_t off = (uint32_t)(row * 128) + (uint32_t)(kk * 2) + (uint32_t)((lane & 8) << 1);
                off ^= (off >> 3) & 0x70;
                uint32_t r[4];
                ldsm4(r, st + ASZ + off);
                bh[2 * bt][0] = r[0]; bh[2 * bt][1] = r[1];
                bh[2 * bt + 1][0] = r[2]; bh[2 * bt + 1][1] = r[3];
            }
#pragma unroll
            for (int mt = 0; mt < 2; mt++)
#pragma unroll
                for (int nt = 0; nt < NT; nt++)
                    mma_f16(c[mt][nt], ah[mt], bh[nt]);
        }
        __syncthreads();
        if (s + 3 < nst) load_stage(s + 3);
        CP_COMMIT();
    }

    // epilogue
#pragma unroll
    for (int mt = 0; mt < 2; mt++) {
#pragma unroll
        for (int nt = 0; nt < NT; nt++) {
            int m0 = bm + wm * 32 + mt * 16 + g;
            int n0 = bn + wn * (8 * NT) + nt * 8 + 2 * tig;
            float2 v0 = make_float2(c[mt][nt][0], c[mt][nt][1]);
            float2 v1 = make_float2(c[mt][nt][2], c[mt][nt][3]);
            if (HC) {
                float2 ci0 = *reinterpret_cast<const float2*>(Cin + (size_t)m0 * N + n0);
                float2 ci1 = *reinterpret_cast<const float2*>(Cin + (size_t)(m0 + 8) * N + n0);
                v0.x += ci0.x; v0.y += ci0.y; v1.x += ci1.x; v1.y += ci1.y;
            }
            if (bias) {
                float bx = bias[n0], by = bias[n0 + 1];
                v0.x += bx; v0.y += by; v1.x += bx; v1.y += by;
            }
            if (ACT == 1) {
                v0.x = fmaxf(v0.x, 0.f); v0.y = fmaxf(v0.y, 0.f);
                v1.x = fmaxf(v1.x, 0.f); v1.y = fmaxf(v1.y, 0.f);
            } else if (ACT == 2) {
                v0.x = 1.f / (1.f + expf(-v0.x)); v0.y = 1.f / (1.f + expf(-v0.y));
                v1.x = 1.f / (1.f + expf(-v1.x)); v1.y = 1.f / (1.f + expf(-v1.y));
            }
            if (OUT == 0) {
                *reinterpret_cast<float2*>(Cf + (size_t)m0 * N + n0) = v0;
                *reinterpret_cast<float2*>(Cf + (size_t)(m0 + 8) * N + n0) = v1;
            } else {
                *reinterpret_cast<uint32_t*>(Oh + (size_t)m0 * N + n0) = pack_h2(v0.x, v0.y);
                *reinterpret_cast<uint32_t*>(Oh + (size_t)(m0 + 8) * N + n0) = pack_h2(v1.x, v1.y);
            }
        }
    }
}

#define SM8  (3 * (16384 + 128 * 128))   // 96 KB  (NT=8)
#define SM16 (3 * (16384 + 256 * 128))   // 144 KB (NT=16)

// ---------------- orchestration ----------------
extern "C" void kernel_launch(void* const* d_in, const int* in_sizes, int n_in,
                              void* d_out, int out_size) {
    const float* hM  = (const float*)d_in[0];
    const float* hD  = (const float*)d_in[1];
    const float* hT  = (const float*)d_in[2];
    const float* W1  = (const float*)d_in[3];
    const float* b1  = (const float*)d_in[4];
    const float* W2  = (const float*)d_in[5];
    const float* b2  = (const float*)d_in[6];
    const float* W3  = (const float*)d_in[7];
    const float* b3  = (const float*)d_in[8];
    const float* Adj = (const float*)d_in[9];
    const float* f1w = (const float*)d_in[10];
    const float* f1b = (const float*)d_in[11];
    const float* f2w = (const float*)d_in[12];
    const float* f2b = (const float*)d_in[13];
    const float* f3w = (const float*)d_in[14];
    const float* f3b = (const float*)d_in[15];
    const float* f4w = (const float*)d_in[16];
    const float* f4b = (const float*)d_in[17];
    const int* edges = (const int*)d_in[18];

    float *p_node, *p_agg, *p_outinv, *p_ininv, *p_xs32, *p_x1f;
    __half *p_bth, *p_adjh, *p_feh, *p_x1h, *p_x2h, *p_x3h, *p_xsh;
    cudaGetSymbolAddress((void**)&p_node, g_node);
    cudaGetSymbolAddress((void**)&p_agg, g_agg);
    cudaGetSymbolAddress((void**)&p_outinv, g_outinv);
    cudaGetSymbolAddress((void**)&p_ininv, g_ininv);
    cudaGetSymbolAddress((void**)&p_xs32, g_xs32);
    cudaGetSymbolAddress((void**)&p_xsh, g_xsh);
    cudaGetSymbolAddress((void**)&p_bth, g_bth);
    cudaGetSymbolAddress((void**)&p_adjh, g_adjh);
    cudaGetSymbolAddress((void**)&p_feh, g_feh);
    cudaGetSymbolAddress((void**)&p_x1f, g_x1f);
    cudaGetSymbolAddress((void**)&p_x1h, g_x1h);
    cudaGetSymbolAddress((void**)&p_x2h, g_x2h);
    cudaGetSymbolAddress((void**)&p_x3h, g_x3h);

    float* fe   = (float*)d_out;                       // 4096 x 128
    float* outx = (float*)d_out + (size_t)MROW * OUTD; // 4096 x 8192

    static cudaStream_t s2 = nullptr, s3 = nullptr;
    static cudaEvent_t evFork = nullptr, evJoin = nullptr, evScan = nullptr, evFill = nullptr;
    if (s2 == nullptr) {
        cudaStreamCreateWithFlags(&s2, cudaStreamNonBlocking);
        cudaStreamCreateWithFlags(&s3, cudaStreamNonBlocking);
        cudaEventCreateWithFlags(&evFork, cudaEventDisableTiming);
        cudaEventCreateWithFlags(&evJoin, cudaEventDisableTiming);
        cudaEventCreateWithFlags(&evScan, cudaEventDisableTiming);
        cudaEventCreateWithFlags(&evFill, cudaEventDisableTiming);
        cudaFuncSetAttribute(k_tc<0, 0, false, 8>, cudaFuncAttributeMaxDynamicSharedMemorySize, SM8);
        cudaFuncSetAttribute(k_tc<1, 1, true, 8>,  cudaFuncAttributeMaxDynamicSharedMemorySize, SM8);
        cudaFuncSetAttribute(k_tc<1, 1, false, 8>, cudaFuncAttributeMaxDynamicSharedMemorySize, SM8);
        cudaFuncSetAttribute(k_tc<2, 0, false, 16>, cudaFuncAttributeMaxDynamicSharedMemorySize, SM16);
        cudaFuncSetAttribute(k_count, cudaFuncAttributeMaxDynamicSharedMemorySize, 2 * NN * 4);
    }

    // ---- fork s2: MLP prep + Adj GEMM (independent of GNN) ----
    cudaEventRecord(evFork, 0);
    cudaStreamWaitEvent(s2, evFork, 0);
    k_cvt<<<(MROW * ITEM / 4) / 256, 256, 0, s2>>>((const float4*)Adj, p_adjh);
    k_tsp<<<dim3(256 / 32, 8192 / 32), dim3(32, 8), 0, s2>>>(f1w, p_bth + O1A, 8192, 256);
    k_tsp<<<dim3(256 / 32, 128 / 32),  dim3(32, 8), 0, s2>>>(f1w + (size_t)ITEM * 256, p_bth + O1B, 128, 256);
    k_tsp<<<dim3(512 / 32, 256 / 32),  dim3(32, 8), 0, s2>>>(f2w, p_bth + O2, 256, 512);
    k_tsp<<<dim3(1024 / 32, 512 / 32), dim3(32, 8), 0, s2>>>(f3w, p_bth + O3, 512, 1024);
    k_tsp<<<dim3(8192 / 32, 1024 / 32), dim3(32, 8), 0, s2>>>(f4w, p_bth + O4, 1024, 8192);
    k_tc<0, 0, false, 8><<<dim3(2, 32), 256, SM8, s2>>>(
        p_adjh, p_bth + O1A, nullptr, nullptr, p_x1f, nullptr, 256, 8192);
    cudaEventRecord(evJoin, s2);

    // ---- main stream: CSR counts + scan ----
    k_zero_counts<<<(NREL * NN + 255) / 256, 256>>>();
    k_count<<<dim3(CB, NREL), 512, 2 * NN * 4>>>(edges);
    k_scan<<<NREL, 1024>>>();
    cudaEventRecord(evScan, 0);

    // ---- fork s3: CSR fill ----
    cudaStreamWaitEvent(s3, evScan, 0);
    k_fill<<<(NREL * NE / 4 + 255) / 256, 256, 0, s3>>>(edges);
    cudaEventRecord(evFill, s3);

    // ---- main: layer-1 conv overlaps fill ----
    k_conv_b<__half><<<dim3(1, NN / 64, 6), 256>>>(hM, hD, hT, W1, p_outinv, 256, 64,
                                                   p_xsh, (size_t)NN * 64, 0x543210u);
    cudaStreamWaitEvent(0, evFill, 0);
    k_agg_v<<<dim3(NN / 16, 3), dim3(16, 16)>>>(b1, 0);

    // layer 2: relations {0,2,4,5}, targets {D,T}
    k_conv_b<__half><<<dim3(1, NN / 64, 4), 256>>>(p_node, p_node + (size_t)NN * 128,
                                                   p_node + (size_t)2 * NN * 128, W2,
                                                   p_outinv, 64, 64, p_xsh, (size_t)NN * 64,
                                                   0x5420u);
    k_agg_v<<<dim3(NN / 16, 2), dim3(16, 16)>>>(b2, 1);

    // layer 3: relations {1,3}, dst rows [0,4096) only
    k_aggpre<<<dim3(MROW / 16, 2), dim3(16, 16)>>>();
    k_conv_b<float><<<dim3(2, MROW / 64, 2), 256>>>(p_agg, nullptr, nullptr, W3, p_ininv,
                                                    64, 128, p_xs32, (size_t)NN * 128, 0x31u);
    // combine + L1-normalize fused
    k_l1norm<<<MROW, 128>>>(b3, fe, p_feh);

    // ---- join + MLP tail ----
    cudaStreamWaitEvent(0, evJoin, 0);

    k_tc<1, 1, true, 8><<<dim3(2, 32), 256, SM8>>>(
        p_feh, p_bth + O1B, f1b, p_x1f, nullptr, p_x1h, 256, 128);
    k_tc<1, 1, false, 8><<<dim3(4, 32), 256, SM8>>>(
        p_x1h, p_bth + O2, f2b, nullptr, nullptr, p_x2h, 512, 256);
    k_tc<1, 1, false, 8><<<dim3(8, 32), 256, SM8>>>(
        p_x2h, p_bth + O3, f3b, nullptr, nullptr, p_x3h, 1024, 512);
    k_tc<2, 0, false, 16><<<dim3(32, 32), 256, SM16>>>(
        p_x3h, p_bth + O4, f4b, nullptr, outx, nullptr, 8192, 1024);
}